// round 2
// baseline (speedup 1.0000x reference)
#include <cuda_runtime.h>
#include <math.h>

#define T_TOK 2048
#define HIDN  2048
#define NH    32
#define NKV   4
#define HD    128
#define QKV_N ((NH + 2*NKV)*HD)   /* 5120 */
#define ON    (NH*HD)             /* 4096 */

// Scratch (static device globals: allocation-free)
__device__ float g_qkv[(size_t)T_TOK * QKV_N];   // ~40 MiB
__device__ float g_o  [(size_t)T_TOK * ON];      // ~32 MiB

// ---------------------------------------------------------------------------
// SGEMM (NT): C[M,N] = sum_k A[m*K+k] * B[n*K+k].  A:[M,K] row-major,
// B:[N,K] row-major (both K-contiguous). 128x128x16 tile, 256 threads, 8x8/thr.
// ---------------------------------------------------------------------------
__global__ __launch_bounds__(256, 2) void sgemm_nt(
    const float* __restrict__ A, const float* __restrict__ B,
    float* __restrict__ C, int M, int N, int K)
{
  __shared__ float As[16][132];   // [k][m], padded (132*4B divisible by 16)
  __shared__ float Bs[16][132];   // [k][n]
  const int tid  = threadIdx.x;
  const int tcol = tid & 15;
  const int trow = tid >> 4;
  const float* Ab = A + (size_t)blockIdx.y * 128 * K;
  const float* Bb = B + (size_t)blockIdx.x * 128 * K;
  const int lr = tid >> 2;          // 0..63
  const int lc = (tid & 3) << 2;    // k offset 0,4,8,12

  float acc[8][8];
  #pragma unroll
  for (int i = 0; i < 8; i++)
    #pragma unroll
    for (int j = 0; j < 8; j++) acc[i][j] = 0.f;

  for (int k0 = 0; k0 < K; k0 += 16) {
    #pragma unroll
    for (int r = 0; r < 2; r++) {
      const int row = lr + r * 64;
      float4 va = *(const float4*)(Ab + (size_t)row * K + k0 + lc);
      As[lc+0][row] = va.x; As[lc+1][row] = va.y;
      As[lc+2][row] = va.z; As[lc+3][row] = va.w;
      float4 vb = *(const float4*)(Bb + (size_t)row * K + k0 + lc);
      Bs[lc+0][row] = vb.x; Bs[lc+1][row] = vb.y;
      Bs[lc+2][row] = vb.z; Bs[lc+3][row] = vb.w;
    }
    __syncthreads();
    #pragma unroll
    for (int k = 0; k < 16; k++) {
      float4 a0 = *(const float4*)&As[k][trow*8];
      float4 a1 = *(const float4*)&As[k][trow*8+4];
      float4 b0 = *(const float4*)&Bs[k][tcol*8];
      float4 b1 = *(const float4*)&Bs[k][tcol*8+4];
      float a[8] = {a0.x,a0.y,a0.z,a0.w,a1.x,a1.y,a1.z,a1.w};
      float b[8] = {b0.x,b0.y,b0.z,b0.w,b1.x,b1.y,b1.z,b1.w};
      #pragma unroll
      for (int i = 0; i < 8; i++)
        #pragma unroll
        for (int j = 0; j < 8; j++) acc[i][j] = fmaf(a[i], b[j], acc[i][j]);
    }
    __syncthreads();
  }

  float* Cb = C + (size_t)(blockIdx.y*128 + trow*8) * N + blockIdx.x*128 + tcol*8;
  #pragma unroll
  for (int i = 0; i < 8; i++) {
    float4 c0 = make_float4(acc[i][0], acc[i][1], acc[i][2], acc[i][3]);
    float4 c1 = make_float4(acc[i][4], acc[i][5], acc[i][6], acc[i][7]);
    *(float4*)(Cb + (size_t)i * N)     = c0;
    *(float4*)(Cb + (size_t)i * N + 4) = c1;
  }
}

// ---------------------------------------------------------------------------
// Per-head RMSNorm + NeoX RoPE, in place on the Q and K slices of g_qkv.
// grid: (T, NH+NKV), block: 128 threads (one per head-dim element).
// ---------------------------------------------------------------------------
__global__ __launch_bounds__(128) void norm_rope(
    float* __restrict__ qkv, const int* __restrict__ positions,
    const float* __restrict__ qw, const float* __restrict__ kw)
{
  const int t  = blockIdx.x;
  const int hh = blockIdx.y;      // 0..NH-1 = q heads, NH..NH+NKV-1 = k heads
  const int d  = threadIdx.x;     // 0..127
  float* base = qkv + (size_t)t * QKV_N +
                (hh < NH ? hh * HD : NH * HD + (hh - NH) * HD);
  const float* w = (hh < NH) ? qw : kw;

  float x  = base[d];
  float ss = x * x;
  #pragma unroll
  for (int off = 16; off > 0; off >>= 1)
    ss += __shfl_xor_sync(0xffffffffu, ss, off);
  __shared__ float red[4];
  __shared__ float ybuf[HD];
  if ((d & 31) == 0) red[d >> 5] = ss;
  __syncthreads();
  float tot = red[0] + red[1] + red[2] + red[3];
  float y = x * rsqrtf(tot * (1.0f / HD) + 1e-6f) * w[d];
  ybuf[d] = y;
  __syncthreads();

  const float pos = (float)positions[t];
  const int   i   = d & 63;
  // theta^{-i/64} = 2^{-i * log2(1e6)/64}
  const float inv = exp2f(-(float)i * (19.931568569324174f / 64.0f));
  float s, c;
  sincosf(pos * inv, &s, &c);
  float out;
  if (d < 64) out = y * c - ybuf[d + 64] * s;
  else        out = ybuf[d - 64] * s + y * c;
  base[d] = out;
}

// ---------------------------------------------------------------------------
// Flash attention (fp32, causal, GQA). 64x64 tiles, 256 threads.
// Q,K stored d-major (transposed, stride 65) in smem for conflict-light dot;
// V natural [n][128]; P [m][65].
// Thread (tx,ty): tx=tid&15 (4 S-cols / 8 O-dcols), ty=tid>>4 (4 rows).
// ---------------------------------------------------------------------------
#define FBM 64
#define FBN 64
#define TQS 65

__global__ __launch_bounds__(256) void flash_fwd(
    const float* __restrict__ qkv, float* __restrict__ o)
{
  extern __shared__ float sm[];
  float* Qt = sm;                  // [HD][TQS]
  float* Kt = Qt + HD * TQS;       // [HD][TQS]
  float* Vs = Kt + HD * TQS;       // [FBN][HD]
  float* Ps = Vs + FBN * HD;       // [FBM][TQS]

  const int tid = threadIdx.x;
  const int tx  = tid & 15;
  const int ty  = tid >> 4;
  const int q0  = blockIdx.x * FBM;
  const int h   = blockIdx.y;
  const int kvh = h >> 3;          // NH/NKV = 8
  const float scale = 0.08838834764831845f;  // 1/sqrt(128)

  // Load Q tile, transposed + pre-scaled
  for (int i = tid; i < FBM * HD / 4; i += 256) {
    int r = i >> 5;
    int c = (i & 31) << 2;
    float4 v = *(const float4*)(qkv + (size_t)(q0 + r) * QKV_N + h * HD + c);
    Qt[(c+0)*TQS + r] = v.x * scale;
    Qt[(c+1)*TQS + r] = v.y * scale;
    Qt[(c+2)*TQS + r] = v.z * scale;
    Qt[(c+3)*TQS + r] = v.w * scale;
  }

  float m_i[4], l_i[4], oa[4][8];
  #pragma unroll
  for (int i = 0; i < 4; i++) {
    m_i[i] = -1e30f; l_i[i] = 0.f;
    #pragma unroll
    for (int c = 0; c < 8; c++) oa[i][c] = 0.f;
  }

  const int ktmax = q0 / FBN;
  for (int kt = 0; kt <= ktmax; kt++) {
    const int k0 = kt * FBN;
    __syncthreads();   // prev PV done with Vs/Ps; Q load done (iter 0)
    for (int i = tid; i < FBN * HD / 4; i += 256) {
      int r = i >> 5;
      int c = (i & 31) << 2;
      float4 kv = *(const float4*)(qkv + (size_t)(k0 + r) * QKV_N + NH*HD + kvh*HD + c);
      Kt[(c+0)*TQS + r] = kv.x;
      Kt[(c+1)*TQS + r] = kv.y;
      Kt[(c+2)*TQS + r] = kv.z;
      Kt[(c+3)*TQS + r] = kv.w;
      *(float4*)&Vs[r * HD + c] =
        *(const float4*)(qkv + (size_t)(k0 + r) * QKV_N + (NH+NKV)*HD + kvh*HD + c);
    }
    __syncthreads();

    // S = (Q*scale) @ K^T   (4x4 per thread)
    float s[4][4];
    #pragma unroll
    for (int i = 0; i < 4; i++)
      #pragma unroll
      for (int j = 0; j < 4; j++) s[i][j] = 0.f;

    #pragma unroll 8
    for (int d = 0; d < HD; d++) {
      const float* qrow = &Qt[d * TQS + ty * 4];
      const float* krow = &Kt[d * TQS + tx * 4];
      float a0 = qrow[0], a1 = qrow[1], a2 = qrow[2], a3 = qrow[3];
      float b0 = krow[0], b1 = krow[1], b2 = krow[2], b3 = krow[3];
      s[0][0] = fmaf(a0,b0,s[0][0]); s[0][1] = fmaf(a0,b1,s[0][1]);
      s[0][2] = fmaf(a0,b2,s[0][2]); s[0][3] = fmaf(a0,b3,s[0][3]);
      s[1][0] = fmaf(a1,b0,s[1][0]); s[1][1] = fmaf(a1,b1,s[1][1]);
      s[1][2] = fmaf(a1,b2,s[1][2]); s[1][3] = fmaf(a1,b3,s[1][3]);
      s[2][0] = fmaf(a2,b0,s[2][0]); s[2][1] = fmaf(a2,b1,s[2][1]);
      s[2][2] = fmaf(a2,b2,s[2][2]); s[2][3] = fmaf(a2,b3,s[2][3]);
      s[3][0] = fmaf(a3,b0,s[3][0]); s[3][1] = fmaf(a3,b1,s[3][1]);
      s[3][2] = fmaf(a3,b2,s[3][2]); s[3][3] = fmaf(a3,b3,s[3][3]);
    }

    if (kt == ktmax) {  // diagonal tile (k0 == q0): causal mask
      #pragma unroll
      for (int i = 0; i < 4; i++)
        #pragma unroll
        for (int j = 0; j < 4; j++)
          if (tx * 4 + j > ty * 4 + i) s[i][j] = -1e30f;
    }

    // Online softmax update per row (row group = 16 lanes, half-warp)
    #pragma unroll
    for (int i = 0; i < 4; i++) {
      float mx = fmaxf(fmaxf(s[i][0], s[i][1]), fmaxf(s[i][2], s[i][3]));
      #pragma unroll
      for (int off = 8; off > 0; off >>= 1)
        mx = fmaxf(mx, __shfl_xor_sync(0xffffffffu, mx, off));
      float mnew = fmaxf(m_i[i], mx);
      float p0 = __expf(s[i][0] - mnew);
      float p1 = __expf(s[i][1] - mnew);
      float p2 = __expf(s[i][2] - mnew);
      float p3 = __expf(s[i][3] - mnew);
      float rs = p0 + p1 + p2 + p3;
      #pragma unroll
      for (int off = 8; off > 0; off >>= 1)
        rs += __shfl_xor_sync(0xffffffffu, rs, off);
      float corr = __expf(m_i[i] - mnew);
      l_i[i] = l_i[i] * corr + rs;
      m_i[i] = mnew;
      #pragma unroll
      for (int c = 0; c < 8; c++) oa[i][c] *= corr;
      float* prow = &Ps[(ty * 4 + i) * TQS + tx * 4];
      prow[0] = p0; prow[1] = p1; prow[2] = p2; prow[3] = p3;
    }
    __syncthreads();

    // O += P @ V   (each thread: 4 rows x 8 d-cols)
    #pragma unroll 4
    for (int n = 0; n < FBN; n++) {
      float p0 = Ps[(ty*4+0)*TQS + n];
      float p1 = Ps[(ty*4+1)*TQS + n];
      float p2 = Ps[(ty*4+2)*TQS + n];
      float p3 = Ps[(ty*4+3)*TQS + n];
      float4 v0 = *(const float4*)&Vs[n * HD + tx * 8];
      float4 v1 = *(const float4*)&Vs[n * HD + tx * 8 + 4];
      float v[8] = {v0.x,v0.y,v0.z,v0.w,v1.x,v1.y,v1.z,v1.w};
      #pragma unroll
      for (int c = 0; c < 8; c++) {
        oa[0][c] = fmaf(p0, v[c], oa[0][c]);
        oa[1][c] = fmaf(p1, v[c], oa[1][c]);
        oa[2][c] = fmaf(p2, v[c], oa[2][c]);
        oa[3][c] = fmaf(p3, v[c], oa[3][c]);
      }
    }
  }

  // Epilogue: normalize and write O
  #pragma unroll
  for (int i = 0; i < 4; i++) {
    float inv = 1.0f / l_i[i];
    float4 c0 = make_float4(oa[i][0]*inv, oa[i][1]*inv, oa[i][2]*inv, oa[i][3]*inv);
    float4 c1 = make_float4(oa[i][4]*inv, oa[i][5]*inv, oa[i][6]*inv, oa[i][7]*inv);
    float* op = o + (size_t)(q0 + ty * 4 + i) * ON + h * HD + tx * 8;
    *(float4*)op       = c0;
    *(float4*)(op + 4) = c1;
  }
}

// ---------------------------------------------------------------------------
extern "C" void kernel_launch(void* const* d_in, const int* in_sizes, int n_in,
                              void* d_out, int out_size)
{
  (void)in_sizes; (void)n_in; (void)out_size;
  const int*   positions = (const int*)  d_in[0];
  const float* hidden    = (const float*)d_in[1];
  const float* w_qkv     = (const float*)d_in[2];
  const float* w_o       = (const float*)d_in[3];
  const float* qw        = (const float*)d_in[4];
  const float* kw        = (const float*)d_in[5];
  float* out = (float*)d_out;

  float *qkv, *obuf;
  cudaGetSymbolAddress((void**)&qkv,  g_qkv);
  cudaGetSymbolAddress((void**)&obuf, g_o);

  // 1) QKV projection: [2048,2048] @ [5120,2048]^T
  sgemm_nt<<<dim3(QKV_N/128, T_TOK/128), 256>>>(hidden, w_qkv, qkv,
                                                T_TOK, QKV_N, HIDN);
  // 2) RMSNorm + RoPE in place on Q/K head slices
  norm_rope<<<dim3(T_TOK, NH + NKV), 128>>>(qkv, positions, qw, kw);

  // 3) Causal GQA flash attention
  const size_t smem = (size_t)(HD*TQS*2 + FBN*HD + FBM*TQS) * sizeof(float);
  cudaFuncSetAttribute(flash_fwd, cudaFuncAttributeMaxDynamicSharedMemorySize,
                       (int)smem);
  flash_fwd<<<dim3(T_TOK/FBM, NH), 256, smem>>>(qkv, obuf);

  // 4) Output projection: [2048,4096] @ [2048,4096]^T
  sgemm_nt<<<dim3(HIDN/128, T_TOK/128), 256>>>(obuf, w_o, out,
                                               T_TOK, HIDN, ON);
}

// round 6
// speedup vs baseline: 1.3691x; 1.3691x over previous
#include <cuda_runtime.h>
#include <cuda_bf16.h>
#include <math.h>
#include <stdint.h>

#define T_TOK 2048
#define HIDN  2048
#define NH    32
#define NKV   4
#define HD    128
#define QKV_N ((NH + 2*NKV)*HD)   /* 5120 */
#define ON    (NH*HD)             /* 4096 */

// Scratch (static device globals: allocation-free)
__device__ float g_qkv[(size_t)T_TOK * QKV_N];   // ~40 MiB
__device__ float g_o  [(size_t)T_TOK * ON];      // ~32 MiB

// ===========================================================================
// Helpers
// ===========================================================================
__device__ __forceinline__ uint32_t smem_u32(const void* p) {
  uint32_t a;
  asm("{ .reg .u64 t; cvta.to.shared.u64 t, %1; cvt.u32.u64 %0, t; }"
      : "=r"(a) : "l"(p));
  return a;
}

// fp32 -> (hi, lo) bf16 split, 4 elements -> two 8B words
__device__ __forceinline__ void cvt_split(float4 v, uint2& hi, uint2& lo) {
  float f[4] = {v.x, v.y, v.z, v.w};
  uint32_t hs[4], ls[4];
  #pragma unroll
  for (int i = 0; i < 4; i++) {
    __nv_bfloat16 h = __float2bfloat16_rn(f[i]);
    float r = f[i] - __bfloat162float(h);
    __nv_bfloat16 l = __float2bfloat16_rn(r);
    hs[i] = (uint32_t)__bfloat16_as_ushort(h);
    ls[i] = (uint32_t)__bfloat16_as_ushort(l);
  }
  hi.x = hs[0] | (hs[1] << 16); hi.y = hs[2] | (hs[3] << 16);
  lo.x = ls[0] | (ls[1] << 16); lo.y = ls[2] | (ls[3] << 16);
}

#define LDSM4(r, a)                                                          \
  asm volatile("ldmatrix.sync.aligned.m8n8.x4.shared.b16 {%0,%1,%2,%3}, [%4];" \
    : "=r"((r)[0]), "=r"((r)[1]), "=r"((r)[2]), "=r"((r)[3]) : "r"(a))

#define MMA_BF16(c, a, b)                                                    \
  asm volatile("mma.sync.aligned.m16n8k16.row.col.f32.bf16.bf16.f32 "        \
    "{%0,%1,%2,%3}, {%4,%5,%6,%7}, {%8,%9}, {%0,%1,%2,%3};"                  \
    : "+f"((c)[0]), "+f"((c)[1]), "+f"((c)[2]), "+f"((c)[3])                 \
    : "r"((a)[0]), "r"((a)[1]), "r"((a)[2]), "r"((a)[3]),                    \
      "r"((b)[0]), "r"((b)[1]))

// ===========================================================================
// bf16-split HMMA GEMM (NT): C[M,N] = A[M,K] @ B[N,K]^T, fp32 in/out.
// CTA tile 128x128, 8 warps (4x2), warp tile 32x64, K chunk 32,
// double-buffered smem stages (Ah/Al/Bh/Bl, padded stride 40 bf16).
// ===========================================================================
#define KC 32
#define KP 40                      /* padded bf16 row stride */
#define TILE_E (128 * KP)          /* 5120 elems per tile */
#define STAGE_E (4 * TILE_E)       /* 20480 elems per stage */
#define GEMM_SMEM (2 * STAGE_E * 2)/* 81920 bytes */

__global__ __launch_bounds__(256) void gemm_mma(
    const float* __restrict__ A, const float* __restrict__ B,
    float* __restrict__ C, int M, int N, int K)
{
  extern __shared__ __nv_bfloat16 sm[];
  const int tid  = threadIdx.x;
  const int lane = tid & 31;
  const int w    = tid >> 5;
  const int wm   = w & 3;          // 0..3 (M)
  const int wn   = w >> 2;         // 0..1 (N)
  const int bm   = blockIdx.y, bn = blockIdx.x;

  const float* Ab = A + (size_t)bm * 128 * K;
  const float* Bb = B + (size_t)bn * 128 * K;

  // loader mapping: 1024 float4 per tile / 256 thr = 4 iters
  const int lr = tid >> 3;          // row 0..31 (+32/iter)
  const int lc = (tid & 7) << 2;    // k offset 0,4,...,28

  // ldmatrix per-thread source rows
  const int mi  = lane >> 3, li = lane & 7;
  const int a_r = ((mi & 1) << 3) + li;   // A: m offset
  const int a_k = (mi >> 1) << 3;         // A: k offset
  const int b_r = ((mi >> 1) << 3) + li;  // B: n offset
  const int b_k = (mi & 1) << 3;          // B: k offset

  float acc[2][8][4];
  #pragma unroll
  for (int mt = 0; mt < 2; ++mt)
    #pragma unroll
    for (int nt = 0; nt < 8; ++nt)
      #pragma unroll
      for (int q = 0; q < 4; ++q) acc[mt][nt][q] = 0.f;

  float4 ar[4], br[4];

  auto LDG = [&](int ch) {
    const size_t kb = (size_t)ch * KC;
    #pragma unroll
    for (int it = 0; it < 4; ++it) {
      const int r = lr + it * 32;
      ar[it] = *(const float4*)(Ab + (size_t)r * K + kb + lc);
      br[it] = *(const float4*)(Bb + (size_t)r * K + kb + lc);
    }
  };

  auto STS = [&](int s) {
    __nv_bfloat16* st = sm + s * STAGE_E;
    #pragma unroll
    for (int it = 0; it < 4; ++it) {
      const int r   = lr + it * 32;
      const int off = r * KP + lc;
      uint2 hi, lo;
      cvt_split(ar[it], hi, lo);
      *(uint2*)(st + off)              = hi;   // Ah
      *(uint2*)(st + TILE_E + off)     = lo;   // Al
      cvt_split(br[it], hi, lo);
      *(uint2*)(st + 2 * TILE_E + off) = hi;   // Bh
      *(uint2*)(st + 3 * TILE_E + off) = lo;   // Bl
    }
  };

  auto COMP = [&](int s) {
    const uint32_t base = smem_u32(sm + s * STAGE_E);
    #pragma unroll
    for (int ks = 0; ks < 2; ++ks) {
      uint32_t ah[2][4], al[2][4], bh[4][4], bl[4][4];
      #pragma unroll
      for (int mt = 0; mt < 2; ++mt) {
        uint32_t ad = base + (uint32_t)(((wm * 32 + mt * 16 + a_r) * KP +
                                         ks * 16 + a_k) << 1);
        LDSM4(ah[mt], ad);
        LDSM4(al[mt], ad + TILE_E * 2);
      }
      #pragma unroll
      for (int np = 0; np < 4; ++np) {
        uint32_t bd = base + 2 * TILE_E * 2 +
                      (uint32_t)(((wn * 64 + np * 16 + b_r) * KP +
                                  ks * 16 + b_k) << 1);
        LDSM4(bh[np], bd);
        LDSM4(bl[np], bd + TILE_E * 2);
      }
      #pragma unroll
      for (int mt = 0; mt < 2; ++mt)
        #pragma unroll
        for (int nt = 0; nt < 8; ++nt) {
          uint32_t* bhp = &bh[nt >> 1][(nt & 1) * 2];
          uint32_t* blp = &bl[nt >> 1][(nt & 1) * 2];
          MMA_BF16(acc[mt][nt], ah[mt], bhp);
          MMA_BF16(acc[mt][nt], ah[mt], blp);
          MMA_BF16(acc[mt][nt], al[mt], bhp);
        }
    }
  };

  const int NC = K / KC;
  LDG(0); STS(0);
  __syncthreads();
  for (int ch = 0; ch < NC; ++ch) {
    if (ch + 1 < NC) LDG(ch + 1);      // LDG latency hides behind COMP
    COMP(ch & 1);
    if (ch + 1 < NC) STS((ch + 1) & 1);
    __syncthreads();
  }

  // epilogue: fragment -> gmem (float2 stores)
  #pragma unroll
  for (int mt = 0; mt < 2; ++mt) {
    const int r0 = bm * 128 + wm * 32 + mt * 16 + (lane >> 2);
    #pragma unroll
    for (int nt = 0; nt < 8; ++nt) {
      const int c0 = bn * 128 + wn * 64 + nt * 8 + ((lane & 3) << 1);
      *(float2*)&C[(size_t)r0 * N + c0] =
          make_float2(acc[mt][nt][0], acc[mt][nt][1]);
      *(float2*)&C[(size_t)(r0 + 8) * N + c0] =
          make_float2(acc[mt][nt][2], acc[mt][nt][3]);
    }
  }
}

// ---------------------------------------------------------------------------
// Per-head RMSNorm + NeoX RoPE, in place on the Q and K slices of g_qkv.
// ---------------------------------------------------------------------------
__global__ __launch_bounds__(128) void norm_rope(
    float* __restrict__ qkv, const int* __restrict__ positions,
    const float* __restrict__ qw, const float* __restrict__ kw)
{
  const int t  = blockIdx.x;
  const int hh = blockIdx.y;
  const int d  = threadIdx.x;
  float* base = qkv + (size_t)t * QKV_N +
                (hh < NH ? hh * HD : NH * HD + (hh - NH) * HD);
  const float* w = (hh < NH) ? qw : kw;

  float x  = base[d];
  float ss = x * x;
  #pragma unroll
  for (int off = 16; off > 0; off >>= 1)
    ss += __shfl_xor_sync(0xffffffffu, ss, off);
  __shared__ float red[4];
  __shared__ float ybuf[HD];
  if ((d & 31) == 0) red[d >> 5] = ss;
  __syncthreads();
  float tot = red[0] + red[1] + red[2] + red[3];
  float y = x * rsqrtf(tot * (1.0f / HD) + 1e-6f) * w[d];
  ybuf[d] = y;
  __syncthreads();

  const float pos = (float)positions[t];
  const int   i   = d & 63;
  const float inv = exp2f(-(float)i * (19.931568569324174f / 64.0f));
  float s, c;
  sincosf(pos * inv, &s, &c);
  float out;
  if (d < 64) out = y * c - ybuf[d + 64] * s;
  else        out = ybuf[d - 64] * s + y * c;
  base[d] = out;
}

// ---------------------------------------------------------------------------
// Flash attention (fp32, causal, GQA). 64x64 tiles, 256 threads.
// (unchanged from the passing R2 version)
// ---------------------------------------------------------------------------
#define FBM 64
#define FBN 64
#define TQS 65

__global__ __launch_bounds__(256) void flash_fwd(
    const float* __restrict__ qkv, float* __restrict__ o)
{
  extern __shared__ float smf[];
  float* Qt = smf;
  float* Kt = Qt + HD * TQS;
  float* Vs = Kt + HD * TQS;
  float* Ps = Vs + FBN * HD;

  const int tid = threadIdx.x;
  const int tx  = tid & 15;
  const int ty  = tid >> 4;
  const int q0  = blockIdx.x * FBM;
  const int h   = blockIdx.y;
  const int kvh = h >> 3;
  const float scale = 0.08838834764831845f;

  for (int i = tid; i < FBM * HD / 4; i += 256) {
    int r = i >> 5;
    int c = (i & 31) << 2;
    float4 v = *(const float4*)(qkv + (size_t)(q0 + r) * QKV_N + h * HD + c);
    Qt[(c+0)*TQS + r] = v.x * scale;
    Qt[(c+1)*TQS + r] = v.y * scale;
    Qt[(c+2)*TQS + r] = v.z * scale;
    Qt[(c+3)*TQS + r] = v.w * scale;
  }

  float m_i[4], l_i[4], oa[4][8];
  #pragma unroll
  for (int i = 0; i < 4; i++) {
    m_i[i] = -1e30f; l_i[i] = 0.f;
    #pragma unroll
    for (int c = 0; c < 8; c++) oa[i][c] = 0.f;
  }

  const int ktmax = q0 / FBN;
  for (int kt = 0; kt <= ktmax; kt++) {
    const int k0 = kt * FBN;
    __syncthreads();
    for (int i = tid; i < FBN * HD / 4; i += 256) {
      int r = i >> 5;
      int c = (i & 31) << 2;
      float4 kv = *(const float4*)(qkv + (size_t)(k0 + r) * QKV_N + NH*HD + kvh*HD + c);
      Kt[(c+0)*TQS + r] = kv.x;
      Kt[(c+1)*TQS + r] = kv.y;
      Kt[(c+2)*TQS + r] = kv.z;
      Kt[(c+3)*TQS + r] = kv.w;
      *(float4*)&Vs[r * HD + c] =
        *(const float4*)(qkv + (size_t)(k0 + r) * QKV_N + (NH+NKV)*HD + kvh*HD + c);
    }
    __syncthreads();

    float s[4][4];
    #pragma unroll
    for (int i = 0; i < 4; i++)
      #pragma unroll
      for (int j = 0; j < 4; j++) s[i][j] = 0.f;

    #pragma unroll 8
    for (int d = 0; d < HD; d++) {
      const float* qrow = &Qt[d * TQS + ty * 4];
      const float* krow = &Kt[d * TQS + tx * 4];
      float a0 = qrow[0], a1 = qrow[1], a2 = qrow[2], a3 = qrow[3];
      float b0 = krow[0], b1 = krow[1], b2 = krow[2], b3 = krow[3];
      s[0][0] = fmaf(a0,b0,s[0][0]); s[0][1] = fmaf(a0,b1,s[0][1]);
      s[0][2] = fmaf(a0,b2,s[0][2]); s[0][3] = fmaf(a0,b3,s[0][3]);
      s[1][0] = fmaf(a1,b0,s[1][0]); s[1][1] = fmaf(a1,b1,s[1][1]);
      s[1][2] = fmaf(a1,b2,s[1][2]); s[1][3] = fmaf(a1,b3,s[1][3]);
      s[2][0] = fmaf(a2,b0,s[2][0]); s[2][1] = fmaf(a2,b1,s[2][1]);
      s[2][2] = fmaf(a2,b2,s[2][2]); s[2][3] = fmaf(a2,b3,s[2][3]);
      s[3][0] = fmaf(a3,b0,s[3][0]); s[3][1] = fmaf(a3,b1,s[3][1]);
      s[3][2] = fmaf(a3,b2,s[3][2]); s[3][3] = fmaf(a3,b3,s[3][3]);
    }

    if (kt == ktmax) {
      #pragma unroll
      for (int i = 0; i < 4; i++)
        #pragma unroll
        for (int j = 0; j < 4; j++)
          if (tx * 4 + j > ty * 4 + i) s[i][j] = -1e30f;
    }

    #pragma unroll
    for (int i = 0; i < 4; i++) {
      float mx = fmaxf(fmaxf(s[i][0], s[i][1]), fmaxf(s[i][2], s[i][3]));
      #pragma unroll
      for (int off = 8; off > 0; off >>= 1)
        mx = fmaxf(mx, __shfl_xor_sync(0xffffffffu, mx, off));
      float mnew = fmaxf(m_i[i], mx);
      float p0 = __expf(s[i][0] - mnew);
      float p1 = __expf(s[i][1] - mnew);
      float p2 = __expf(s[i][2] - mnew);
      float p3 = __expf(s[i][3] - mnew);
      float rs = p0 + p1 + p2 + p3;
      #pragma unroll
      for (int off = 8; off > 0; off >>= 1)
        rs += __shfl_xor_sync(0xffffffffu, rs, off);
      float corr = __expf(m_i[i] - mnew);
      l_i[i] = l_i[i] * corr + rs;
      m_i[i] = mnew;
      #pragma unroll
      for (int c = 0; c < 8; c++) oa[i][c] *= corr;
      float* prow = &Ps[(ty * 4 + i) * TQS + tx * 4];
      prow[0] = p0; prow[1] = p1; prow[2] = p2; prow[3] = p3;
    }
    __syncthreads();

    #pragma unroll 4
    for (int n = 0; n < FBN; n++) {
      float p0 = Ps[(ty*4+0)*TQS + n];
      float p1 = Ps[(ty*4+1)*TQS + n];
      float p2 = Ps[(ty*4+2)*TQS + n];
      float p3 = Ps[(ty*4+3)*TQS + n];
      float4 v0 = *(const float4*)&Vs[n * HD + tx * 8];
      float4 v1 = *(const float4*)&Vs[n * HD + tx * 8 + 4];
      float v[8] = {v0.x,v0.y,v0.z,v0.w,v1.x,v1.y,v1.z,v1.w};
      #pragma unroll
      for (int c = 0; c < 8; c++) {
        oa[0][c] = fmaf(p0, v[c], oa[0][c]);
        oa[1][c] = fmaf(p1, v[c], oa[1][c]);
        oa[2][c] = fmaf(p2, v[c], oa[2][c]);
        oa[3][c] = fmaf(p3, v[c], oa[3][c]);
      }
    }
  }

  #pragma unroll
  for (int i = 0; i < 4; i++) {
    float inv = 1.0f / l_i[i];
    float4 c0 = make_float4(oa[i][0]*inv, oa[i][1]*inv, oa[i][2]*inv, oa[i][3]*inv);
    float4 c1 = make_float4(oa[i][4]*inv, oa[i][5]*inv, oa[i][6]*inv, oa[i][7]*inv);
    float* op = o + (size_t)(q0 + ty * 4 + i) * ON + h * HD + tx * 8;
    *(float4*)op       = c0;
    *(float4*)(op + 4) = c1;
  }
}

// ---------------------------------------------------------------------------
extern "C" void kernel_launch(void* const* d_in, const int* in_sizes, int n_in,
                              void* d_out, int out_size)
{
  (void)in_sizes; (void)n_in; (void)out_size;
  const int*   positions = (const int*)  d_in[0];
  const float* hidden    = (const float*)d_in[1];
  const float* w_qkv     = (const float*)d_in[2];
  const float* w_o       = (const float*)d_in[3];
  const float* qw        = (const float*)d_in[4];
  const float* kw        = (const float*)d_in[5];
  float* out = (float*)d_out;

  float *qkv, *obuf;
  cudaGetSymbolAddress((void**)&qkv,  g_qkv);
  cudaGetSymbolAddress((void**)&obuf, g_o);

  cudaFuncSetAttribute(gemm_mma, cudaFuncAttributeMaxDynamicSharedMemorySize,
                       GEMM_SMEM);

  // 1) QKV projection: [2048,2048] @ [5120,2048]^T  (bf16-split HMMA)
  gemm_mma<<<dim3(QKV_N/128, T_TOK/128), 256, GEMM_SMEM>>>(
      hidden, w_qkv, qkv, T_TOK, QKV_N, HIDN);

  // 2) RMSNorm + RoPE in place on Q/K head slices
  norm_rope<<<dim3(T_TOK, NH + NKV), 128>>>(qkv, positions, qw, kw);

  // 3) Causal GQA flash attention (fp32, unchanged)
  const size_t smem = (size_t)(HD*TQS*2 + FBN*HD + FBM*TQS) * sizeof(float);
  cudaFuncSetAttribute(flash_fwd, cudaFuncAttributeMaxDynamicSharedMemorySize,
                       (int)smem);
  flash_fwd<<<dim3(T_TOK/FBM, NH), 256, smem>>>(qkv, obuf);

  // 4) Output projection: [2048,4096] @ [2048,4096]^T  (bf16-split HMMA)
  gemm_mma<<<dim3(HIDN/128, T_TOK/128), 256, GEMM_SMEM>>>(
      obuf, w_o, out, T_TOK, HIDN, ON);
}

// round 7
// speedup vs baseline: 2.5300x; 1.8479x over previous
#include <cuda_runtime.h>
#include <cuda_bf16.h>
#include <math.h>
#include <stdint.h>

#define T_TOK 2048
#define HIDN  2048
#define NH    32
#define NKV   4
#define HD    128
#define QKV_N ((NH + 2*NKV)*HD)   /* 5120 */
#define ON    (NH*HD)             /* 4096 */

// Scratch (static device globals: allocation-free)
__device__ float g_qkv[(size_t)T_TOK * QKV_N];   // ~40 MiB
__device__ float g_o  [(size_t)T_TOK * ON];      // ~32 MiB

// ===========================================================================
// Helpers
// ===========================================================================
__device__ __forceinline__ uint32_t smem_u32(const void* p) {
  uint32_t a;
  asm("{ .reg .u64 t; cvta.to.shared.u64 t, %1; cvt.u32.u64 %0, t; }"
      : "=r"(a) : "l"(p));
  return a;
}

// fp32 -> (hi, lo) bf16 split, 4 elements -> two 8B words
__device__ __forceinline__ void cvt_split(float4 v, uint2& hi, uint2& lo) {
  float f[4] = {v.x, v.y, v.z, v.w};
  uint32_t hs[4], ls[4];
  #pragma unroll
  for (int i = 0; i < 4; i++) {
    __nv_bfloat16 h = __float2bfloat16_rn(f[i]);
    float r = f[i] - __bfloat162float(h);
    __nv_bfloat16 l = __float2bfloat16_rn(r);
    hs[i] = (uint32_t)__bfloat16_as_ushort(h);
    ls[i] = (uint32_t)__bfloat16_as_ushort(l);
  }
  hi.x = hs[0] | (hs[1] << 16); hi.y = hs[2] | (hs[3] << 16);
  lo.x = ls[0] | (ls[1] << 16); lo.y = ls[2] | (ls[3] << 16);
}

// two fp32 -> packed bf16x2 hi + residual lo (low 16 bits = first arg)
__device__ __forceinline__ void split2(float a, float b,
                                       uint32_t& hi, uint32_t& lo) {
  __nv_bfloat162 h = __floats2bfloat162_rn(a, b);
  float ra = a - __bfloat162float(h.x);
  float rb = b - __bfloat162float(h.y);
  __nv_bfloat162 l = __floats2bfloat162_rn(ra, rb);
  hi = *reinterpret_cast<uint32_t*>(&h);
  lo = *reinterpret_cast<uint32_t*>(&l);
}

#define LDSM4(r, a)                                                          \
  asm volatile("ldmatrix.sync.aligned.m8n8.x4.shared.b16 {%0,%1,%2,%3}, [%4];" \
    : "=r"((r)[0]), "=r"((r)[1]), "=r"((r)[2]), "=r"((r)[3]) : "r"(a))

#define MMA_BF16(c, a, b)                                                    \
  asm volatile("mma.sync.aligned.m16n8k16.row.col.f32.bf16.bf16.f32 "        \
    "{%0,%1,%2,%3}, {%4,%5,%6,%7}, {%8,%9}, {%0,%1,%2,%3};"                  \
    : "+f"((c)[0]), "+f"((c)[1]), "+f"((c)[2]), "+f"((c)[3])                 \
    : "r"((a)[0]), "r"((a)[1]), "r"((a)[2]), "r"((a)[3]),                    \
      "r"((b)[0]), "r"((b)[1]))

// ===========================================================================
// bf16-split HMMA GEMM (NT): C[M,N] = A[M,K] @ B[N,K]^T, fp32 in/out.
// (unchanged from R6 passing version)
// ===========================================================================
#define KC 32
#define KP 40
#define TILE_E (128 * KP)
#define STAGE_E (4 * TILE_E)
#define GEMM_SMEM (2 * STAGE_E * 2)

__global__ __launch_bounds__(256) void gemm_mma(
    const float* __restrict__ A, const float* __restrict__ B,
    float* __restrict__ C, int M, int N, int K)
{
  extern __shared__ __nv_bfloat16 sm[];
  const int tid  = threadIdx.x;
  const int lane = tid & 31;
  const int w    = tid >> 5;
  const int wm   = w & 3;
  const int wn   = w >> 2;
  const int bm   = blockIdx.y, bn = blockIdx.x;

  const float* Ab = A + (size_t)bm * 128 * K;
  const float* Bb = B + (size_t)bn * 128 * K;

  const int lr = tid >> 3;
  const int lc = (tid & 7) << 2;

  const int mi  = lane >> 3, li = lane & 7;
  const int a_r = ((mi & 1) << 3) + li;
  const int a_k = (mi >> 1) << 3;
  const int b_r = ((mi >> 1) << 3) + li;
  const int b_k = (mi & 1) << 3;

  float acc[2][8][4];
  #pragma unroll
  for (int mt = 0; mt < 2; ++mt)
    #pragma unroll
    for (int nt = 0; nt < 8; ++nt)
      #pragma unroll
      for (int q = 0; q < 4; ++q) acc[mt][nt][q] = 0.f;

  float4 ar[4], br[4];

  auto LDG = [&](int ch) {
    const size_t kb = (size_t)ch * KC;
    #pragma unroll
    for (int it = 0; it < 4; ++it) {
      const int r = lr + it * 32;
      ar[it] = *(const float4*)(Ab + (size_t)r * K + kb + lc);
      br[it] = *(const float4*)(Bb + (size_t)r * K + kb + lc);
    }
  };

  auto STS = [&](int s) {
    __nv_bfloat16* st = sm + s * STAGE_E;
    #pragma unroll
    for (int it = 0; it < 4; ++it) {
      const int r   = lr + it * 32;
      const int off = r * KP + lc;
      uint2 hi, lo;
      cvt_split(ar[it], hi, lo);
      *(uint2*)(st + off)              = hi;
      *(uint2*)(st + TILE_E + off)     = lo;
      cvt_split(br[it], hi, lo);
      *(uint2*)(st + 2 * TILE_E + off) = hi;
      *(uint2*)(st + 3 * TILE_E + off) = lo;
    }
  };

  auto COMP = [&](int s) {
    const uint32_t base = smem_u32(sm + s * STAGE_E);
    #pragma unroll
    for (int ks = 0; ks < 2; ++ks) {
      uint32_t ah[2][4], al[2][4], bh[4][4], bl[4][4];
      #pragma unroll
      for (int mt = 0; mt < 2; ++mt) {
        uint32_t ad = base + (uint32_t)(((wm * 32 + mt * 16 + a_r) * KP +
                                         ks * 16 + a_k) << 1);
        LDSM4(ah[mt], ad);
        LDSM4(al[mt], ad + TILE_E * 2);
      }
      #pragma unroll
      for (int np = 0; np < 4; ++np) {
        uint32_t bd = base + 2 * TILE_E * 2 +
                      (uint32_t)(((wn * 64 + np * 16 + b_r) * KP +
                                  ks * 16 + b_k) << 1);
        LDSM4(bh[np], bd);
        LDSM4(bl[np], bd + TILE_E * 2);
      }
      #pragma unroll
      for (int mt = 0; mt < 2; ++mt)
        #pragma unroll
        for (int nt = 0; nt < 8; ++nt) {
          uint32_t* bhp = &bh[nt >> 1][(nt & 1) * 2];
          uint32_t* blp = &bl[nt >> 1][(nt & 1) * 2];
          MMA_BF16(acc[mt][nt], ah[mt], bhp);
          MMA_BF16(acc[mt][nt], ah[mt], blp);
          MMA_BF16(acc[mt][nt], al[mt], bhp);
        }
    }
  };

  const int NC = K / KC;
  LDG(0); STS(0);
  __syncthreads();
  for (int ch = 0; ch < NC; ++ch) {
    if (ch + 1 < NC) LDG(ch + 1);
    COMP(ch & 1);
    if (ch + 1 < NC) STS((ch + 1) & 1);
    __syncthreads();
  }

  #pragma unroll
  for (int mt = 0; mt < 2; ++mt) {
    const int r0 = bm * 128 + wm * 32 + mt * 16 + (lane >> 2);
    #pragma unroll
    for (int nt = 0; nt < 8; ++nt) {
      const int c0 = bn * 128 + wn * 64 + nt * 8 + ((lane & 3) << 1);
      *(float2*)&C[(size_t)r0 * N + c0] =
          make_float2(acc[mt][nt][0], acc[mt][nt][1]);
      *(float2*)&C[(size_t)(r0 + 8) * N + c0] =
          make_float2(acc[mt][nt][2], acc[mt][nt][3]);
    }
  }
}

// ---------------------------------------------------------------------------
// Per-head RMSNorm + NeoX RoPE (unchanged)
// ---------------------------------------------------------------------------
__global__ __launch_bounds__(128) void norm_rope(
    float* __restrict__ qkv, const int* __restrict__ positions,
    const float* __restrict__ qw, const float* __restrict__ kw)
{
  const int t  = blockIdx.x;
  const int hh = blockIdx.y;
  const int d  = threadIdx.x;
  float* base = qkv + (size_t)t * QKV_N +
                (hh < NH ? hh * HD : NH * HD + (hh - NH) * HD);
  const float* w = (hh < NH) ? qw : kw;

  float x  = base[d];
  float ss = x * x;
  #pragma unroll
  for (int off = 16; off > 0; off >>= 1)
    ss += __shfl_xor_sync(0xffffffffu, ss, off);
  __shared__ float red[4];
  __shared__ float ybuf[HD];
  if ((d & 31) == 0) red[d >> 5] = ss;
  __syncthreads();
  float tot = red[0] + red[1] + red[2] + red[3];
  float y = x * rsqrtf(tot * (1.0f / HD) + 1e-6f) * w[d];
  ybuf[d] = y;
  __syncthreads();

  const float pos = (float)positions[t];
  const int   i   = d & 63;
  const float inv = exp2f(-(float)i * (19.931568569324174f / 64.0f));
  float s, c;
  sincosf(pos * inv, &s, &c);
  float out;
  if (d < 64) out = y * c - ybuf[d + 64] * s;
  else        out = ybuf[d - 64] * s + y * c;
  base[d] = out;
}

// ===========================================================================
// Flash attention with bf16-split HMMA. CTA: 128 q-rows x 1 head, 8 warps,
// warp owns 16 q-rows. K-tile = 64 keys. Causal, GQA.
// Q,K smem: [row][hd] stride QP=136; V^T smem: [hd][token] stride VTP=72.
// S = Qh*Kh + Qh*Kl + Ql*Kh; P reused as A-fragment (FA2), P*V also 3-term.
// ===========================================================================
#define ABM 128
#define ABN 64
#define QP  136
#define VTP 72
#define S_QH 0
#define S_QL (128*QP)
#define S_KH (2*128*QP)
#define S_KL (S_KH + 64*QP)
#define S_VH (S_KH + 2*64*QP)
#define S_VL (S_VH + 128*VTP)
#define FLASH_SMEM ((S_VL + 128*VTP) * 2)

__global__ __launch_bounds__(256, 1) void flash_mma(
    const float* __restrict__ qkv, float* __restrict__ o)
{
  extern __shared__ __nv_bfloat16 sb[];
  const uint32_t sbase = smem_u32(sb);
  const int tid  = threadIdx.x;
  const int lane = tid & 31;
  const int w    = tid >> 5;
  const int q0   = blockIdx.x * ABM;
  const int h    = blockIdx.y;
  const int kvh  = h >> 3;
  const float scale = 0.08838834764831845f;   // 1/sqrt(128)

  const int mi  = lane >> 3, li = lane & 7;
  const int a_r = ((mi & 1) << 3) + li;
  const int a_k = (mi >> 1) << 3;
  const int b_r = ((mi >> 1) << 3) + li;
  const int b_k = (mi & 1) << 3;

  // ---- load Q tile (pre-scaled), split into Qh/Ql ----
  #pragma unroll
  for (int it = 0; it < 16; ++it) {
    const int idx = tid + it * 256;
    const int r = idx >> 5, c = (idx & 31) << 2;
    float4 v = *(const float4*)(qkv + (size_t)(q0 + r) * QKV_N + h * HD + c);
    v.x *= scale; v.y *= scale; v.z *= scale; v.w *= scale;
    uint2 hi, lo; cvt_split(v, hi, lo);
    *(uint2*)(sb + S_QH + r * QP + c) = hi;
    *(uint2*)(sb + S_QL + r * QP + c) = lo;
  }

  float oacc[16][4];
  #pragma unroll
  for (int nt = 0; nt < 16; ++nt)
    #pragma unroll
    for (int q = 0; q < 4; ++q) oacc[nt][q] = 0.f;
  float mA = -1e30f, mB = -1e30f, lA = 0.f, lB = 0.f;

  const int ktmax = q0 / ABN + 1;
  for (int kt = 0; kt <= ktmax; ++kt) {
    const int k0 = kt * ABN;
    __syncthreads();   // prior compute done with K/V smem (Q load on iter 0)

    // ---- K tile: 64 x 128, split into Kh/Kl ----
    #pragma unroll
    for (int it = 0; it < 8; ++it) {
      const int idx = tid + it * 256;
      const int r = idx >> 5, c = (idx & 31) << 2;
      float4 v = *(const float4*)(qkv + (size_t)(k0 + r) * QKV_N +
                                  NH * HD + kvh * HD + c);
      uint2 hi, lo; cvt_split(v, hi, lo);
      *(uint2*)(sb + S_KH + r * QP + c) = hi;
      *(uint2*)(sb + S_KL + r * QP + c) = lo;
    }
    // ---- V tile: transpose to V^T[hd][token], split ----
    #pragma unroll
    for (int it = 0; it < 8; ++it) {
      const int idx = tid + it * 256;
      const int hd = idx & 127, tg = idx >> 7;   // tg: token group of 4
      const float* vb = qkv + (size_t)(k0 + tg * 4) * QKV_N +
                        (NH + NKV) * HD + kvh * HD + hd;
      float v0 = vb[0], v1 = vb[QKV_N], v2 = vb[2*QKV_N], v3 = vb[3*QKV_N];
      uint32_t h01, l01, h23, l23;
      split2(v0, v1, h01, l01);
      split2(v2, v3, h23, l23);
      *(uint2*)(sb + S_VH + hd * VTP + tg * 4) = make_uint2(h01, h23);
      *(uint2*)(sb + S_VL + hd * VTP + tg * 4) = make_uint2(l01, l23);
    }
    __syncthreads();

    // ---- S = Q @ K^T (m16 x n64, k=128) ----
    float sacc[8][4];
    #pragma unroll
    for (int nt = 0; nt < 8; ++nt)
      #pragma unroll
      for (int q = 0; q < 4; ++q) sacc[nt][q] = 0.f;

    #pragma unroll
    for (int ks = 0; ks < 8; ++ks) {
      uint32_t qh[4], ql[4], kh[4][4], kl[4][4];
      const uint32_t qa = sbase + (uint32_t)(((w * 16 + a_r) * QP +
                                             ks * 16 + a_k) << 1);
      LDSM4(qh, qa);
      LDSM4(ql, qa + S_QL * 2);
      #pragma unroll
      for (int np = 0; np < 4; ++np) {
        const uint32_t ka = sbase + (uint32_t)((S_KH + (np * 16 + b_r) * QP +
                                                ks * 16 + b_k) << 1);
        LDSM4(kh[np], ka);
        LDSM4(kl[np], ka + (S_KL - S_KH) * 2);
      }
      #pragma unroll
      for (int nt = 0; nt < 8; ++nt) {
        uint32_t* bhp = &kh[nt >> 1][(nt & 1) * 2];
        uint32_t* blp = &kl[nt >> 1][(nt & 1) * 2];
        MMA_BF16(sacc[nt], qh, bhp);
        MMA_BF16(sacc[nt], qh, blp);
        MMA_BF16(sacc[nt], ql, bhp);
      }
    }

    const int qrA = q0 + w * 16 + (lane >> 2);
    const int qrB = qrA + 8;
    if (k0 + ABN - 1 > q0) {   // causal mask (last two tiles only)
      #pragma unroll
      for (int nt = 0; nt < 8; ++nt) {
        const int kc = k0 + nt * 8 + ((lane & 3) << 1);
        if (kc     > qrA) sacc[nt][0] = -1e30f;
        if (kc + 1 > qrA) sacc[nt][1] = -1e30f;
        if (kc     > qrB) sacc[nt][2] = -1e30f;
        if (kc + 1 > qrB) sacc[nt][3] = -1e30f;
      }
    }

    // ---- online softmax (2 rows per thread) ----
    float mxA = -1e30f, mxB = -1e30f;
    #pragma unroll
    for (int nt = 0; nt < 8; ++nt) {
      mxA = fmaxf(mxA, fmaxf(sacc[nt][0], sacc[nt][1]));
      mxB = fmaxf(mxB, fmaxf(sacc[nt][2], sacc[nt][3]));
    }
    mxA = fmaxf(mxA, __shfl_xor_sync(0xffffffffu, mxA, 1));
    mxA = fmaxf(mxA, __shfl_xor_sync(0xffffffffu, mxA, 2));
    mxB = fmaxf(mxB, __shfl_xor_sync(0xffffffffu, mxB, 1));
    mxB = fmaxf(mxB, __shfl_xor_sync(0xffffffffu, mxB, 2));
    const float mnA = fmaxf(mA, mxA), mnB = fmaxf(mB, mxB);
    const float cA = __expf(mA - mnA), cB = __expf(mB - mnB);
    mA = mnA; mB = mnB;

    float rsA = 0.f, rsB = 0.f;
    #pragma unroll
    for (int nt = 0; nt < 8; ++nt) {
      sacc[nt][0] = __expf(sacc[nt][0] - mnA);
      sacc[nt][1] = __expf(sacc[nt][1] - mnA);
      sacc[nt][2] = __expf(sacc[nt][2] - mnB);
      sacc[nt][3] = __expf(sacc[nt][3] - mnB);
      rsA += sacc[nt][0] + sacc[nt][1];
      rsB += sacc[nt][2] + sacc[nt][3];
    }
    rsA += __shfl_xor_sync(0xffffffffu, rsA, 1);
    rsA += __shfl_xor_sync(0xffffffffu, rsA, 2);
    rsB += __shfl_xor_sync(0xffffffffu, rsB, 1);
    rsB += __shfl_xor_sync(0xffffffffu, rsB, 2);
    lA = lA * cA + rsA;
    lB = lB * cB + rsB;
    #pragma unroll
    for (int nt = 0; nt < 16; ++nt) {
      oacc[nt][0] *= cA; oacc[nt][1] *= cA;
      oacc[nt][2] *= cB; oacc[nt][3] *= cB;
    }

    // ---- O += P @ V (P from registers, V^T from smem) ----
    #pragma unroll
    for (int kk = 0; kk < 4; ++kk) {
      uint32_t ph[4], pl[4];
      split2(sacc[2*kk][0],   sacc[2*kk][1],   ph[0], pl[0]);
      split2(sacc[2*kk][2],   sacc[2*kk][3],   ph[1], pl[1]);
      split2(sacc[2*kk+1][0], sacc[2*kk+1][1], ph[2], pl[2]);
      split2(sacc[2*kk+1][2], sacc[2*kk+1][3], ph[3], pl[3]);
      #pragma unroll
      for (int np = 0; np < 8; ++np) {
        uint32_t vh[4], vl[4];
        const uint32_t va = sbase + (uint32_t)((S_VH + (np * 16 + b_r) * VTP +
                                                kk * 16 + b_k) << 1);
        LDSM4(vh, va);
        LDSM4(vl, va + (S_VL - S_VH) * 2);
        MMA_BF16(oacc[2*np],   ph, (&vh[0]));
        MMA_BF16(oacc[2*np],   ph, (&vl[0]));
        MMA_BF16(oacc[2*np],   pl, (&vh[0]));
        MMA_BF16(oacc[2*np+1], ph, (&vh[2]));
        MMA_BF16(oacc[2*np+1], ph, (&vl[2]));
        MMA_BF16(oacc[2*np+1], pl, (&vh[2]));
      }
    }
  }

  // ---- epilogue ----
  const float invA = 1.0f / lA, invB = 1.0f / lB;
  const int rowA = q0 + w * 16 + (lane >> 2);
  #pragma unroll
  for (int nt = 0; nt < 16; ++nt) {
    const int c0 = h * HD + nt * 8 + ((lane & 3) << 1);
    *(float2*)&o[(size_t)rowA * ON + c0] =
        make_float2(oacc[nt][0] * invA, oacc[nt][1] * invA);
    *(float2*)&o[(size_t)(rowA + 8) * ON + c0] =
        make_float2(oacc[nt][2] * invB, oacc[nt][3] * invB);
  }
}

// ---------------------------------------------------------------------------
extern "C" void kernel_launch(void* const* d_in, const int* in_sizes, int n_in,
                              void* d_out, int out_size)
{
  (void)in_sizes; (void)n_in; (void)out_size;
  const int*   positions = (const int*)  d_in[0];
  const float* hidden    = (const float*)d_in[1];
  const float* w_qkv     = (const float*)d_in[2];
  const float* w_o       = (const float*)d_in[3];
  const float* qw        = (const float*)d_in[4];
  const float* kw        = (const float*)d_in[5];
  float* out = (float*)d_out;

  float *qkv, *obuf;
  cudaGetSymbolAddress((void**)&qkv,  g_qkv);
  cudaGetSymbolAddress((void**)&obuf, g_o);

  cudaFuncSetAttribute(gemm_mma, cudaFuncAttributeMaxDynamicSharedMemorySize,
                       GEMM_SMEM);
  cudaFuncSetAttribute(flash_mma, cudaFuncAttributeMaxDynamicSharedMemorySize,
                       FLASH_SMEM);

  // 1) QKV projection (bf16-split HMMA)
  gemm_mma<<<dim3(QKV_N/128, T_TOK/128), 256, GEMM_SMEM>>>(
      hidden, w_qkv, qkv, T_TOK, QKV_N, HIDN);

  // 2) RMSNorm + RoPE in place on Q/K head slices
  norm_rope<<<dim3(T_TOK, NH + NKV), 128>>>(qkv, positions, qw, kw);

  // 3) Causal GQA flash attention (bf16-split HMMA)
  flash_mma<<<dim3(T_TOK/ABM, NH), 256, FLASH_SMEM>>>(qkv, obuf);

  // 4) Output projection (bf16-split HMMA)
  gemm_mma<<<dim3(HIDN/128, T_TOK/128), 256, GEMM_SMEM>>>(
      obuf, w_o, out, T_TOK, HIDN, ON);
}

// round 8
// speedup vs baseline: 2.5991x; 1.0273x over previous
#include <cuda_runtime.h>
#include <cuda_bf16.h>
#include <math.h>
#include <stdint.h>

#define T_TOK 2048
#define HIDN  2048
#define NH    32
#define NKV   4
#define HD    128
#define QKV_N ((NH + 2*NKV)*HD)   /* 5120 */
#define ON    (NH*HD)             /* 4096 */

// Scratch (static device globals: allocation-free)
__device__ float g_qkv[(size_t)T_TOK * QKV_N];   // ~40 MiB
__device__ float g_o  [(size_t)T_TOK * ON];      // ~32 MiB

// ===========================================================================
// Helpers
// ===========================================================================
__device__ __forceinline__ uint32_t smem_u32(const void* p) {
  uint32_t a;
  asm("{ .reg .u64 t; cvta.to.shared.u64 t, %1; cvt.u32.u64 %0, t; }"
      : "=r"(a) : "l"(p));
  return a;
}

// fp32 -> (hi, lo) bf16 split, 4 elements -> two 8B words
__device__ __forceinline__ void cvt_split(float4 v, uint2& hi, uint2& lo) {
  float f[4] = {v.x, v.y, v.z, v.w};
  uint32_t hs[4], ls[4];
  #pragma unroll
  for (int i = 0; i < 4; i++) {
    __nv_bfloat16 h = __float2bfloat16_rn(f[i]);
    float r = f[i] - __bfloat162float(h);
    __nv_bfloat16 l = __float2bfloat16_rn(r);
    hs[i] = (uint32_t)__bfloat16_as_ushort(h);
    ls[i] = (uint32_t)__bfloat16_as_ushort(l);
  }
  hi.x = hs[0] | (hs[1] << 16); hi.y = hs[2] | (hs[3] << 16);
  lo.x = ls[0] | (ls[1] << 16); lo.y = ls[2] | (ls[3] << 16);
}

// two fp32 -> packed bf16x2 hi + residual lo (low 16 bits = first arg)
__device__ __forceinline__ void split2(float a, float b,
                                       uint32_t& hi, uint32_t& lo) {
  __nv_bfloat162 h = __floats2bfloat162_rn(a, b);
  float ra = a - __bfloat162float(h.x);
  float rb = b - __bfloat162float(h.y);
  __nv_bfloat162 l = __floats2bfloat162_rn(ra, rb);
  hi = *reinterpret_cast<uint32_t*>(&h);
  lo = *reinterpret_cast<uint32_t*>(&l);
}

#define LDSM4(r, a)                                                          \
  asm volatile("ldmatrix.sync.aligned.m8n8.x4.shared.b16 {%0,%1,%2,%3}, [%4];" \
    : "=r"((r)[0]), "=r"((r)[1]), "=r"((r)[2]), "=r"((r)[3]) : "r"(a))

#define MMA_BF16(c, a, b)                                                    \
  asm volatile("mma.sync.aligned.m16n8k16.row.col.f32.bf16.bf16.f32 "        \
    "{%0,%1,%2,%3}, {%4,%5,%6,%7}, {%8,%9}, {%0,%1,%2,%3};"                  \
    : "+f"((c)[0]), "+f"((c)[1]), "+f"((c)[2]), "+f"((c)[3])                 \
    : "r"((a)[0]), "r"((a)[1]), "r"((a)[2]), "r"((a)[3]),                    \
      "r"((b)[0]), "r"((b)[1]))

// ===========================================================================
// bf16-split HMMA GEMM (NT): C[M,N] = A[M,K] @ B[N,K]^T, fp32 in/out.
// CTA tile 128x128, 512 threads / 16 warps (4x4), warp tile 32x32,
// K chunk 32, double-buffered smem (Ah/Al/Bh/Bl, padded stride 40 bf16).
// ===========================================================================
#define KC 32
#define KP 40
#define TILE_E (128 * KP)
#define STAGE_E (4 * TILE_E)
#define GEMM_SMEM (2 * STAGE_E * 2)

__global__ __launch_bounds__(512) void gemm_mma(
    const float* __restrict__ A, const float* __restrict__ B,
    float* __restrict__ C, int M, int N, int K)
{
  extern __shared__ __nv_bfloat16 sm[];
  const int tid  = threadIdx.x;
  const int lane = tid & 31;
  const int w    = tid >> 5;       // 0..15
  const int wm   = w & 3;          // M warp (0..3)
  const int wn   = w >> 2;         // N warp (0..3)
  const int bm   = blockIdx.y, bn = blockIdx.x;

  const float* Ab = A + (size_t)bm * 128 * K;
  const float* Bb = B + (size_t)bn * 128 * K;

  // loader: 1024 float4 per tile / 512 thr = 2 iters
  const int lr = tid >> 3;          // row 0..63 (+64/iter)
  const int lc = (tid & 7) << 2;    // k offset 0,4,...,28

  // ldmatrix per-thread source rows
  const int mi  = lane >> 3, li = lane & 7;
  const int a_r = ((mi & 1) << 3) + li;
  const int a_k = (mi >> 1) << 3;
  const int b_r = ((mi >> 1) << 3) + li;
  const int b_k = (mi & 1) << 3;

  float acc[2][4][4];
  #pragma unroll
  for (int mt = 0; mt < 2; ++mt)
    #pragma unroll
    for (int nt = 0; nt < 4; ++nt)
      #pragma unroll
      for (int q = 0; q < 4; ++q) acc[mt][nt][q] = 0.f;

  float4 ar[2], br[2];

  auto LDG = [&](int ch) {
    const size_t kb = (size_t)ch * KC;
    #pragma unroll
    for (int it = 0; it < 2; ++it) {
      const int r = lr + it * 64;
      ar[it] = *(const float4*)(Ab + (size_t)r * K + kb + lc);
      br[it] = *(const float4*)(Bb + (size_t)r * K + kb + lc);
    }
  };

  auto STS = [&](int s) {
    __nv_bfloat16* st = sm + s * STAGE_E;
    #pragma unroll
    for (int it = 0; it < 2; ++it) {
      const int r   = lr + it * 64;
      const int off = r * KP + lc;
      uint2 hi, lo;
      cvt_split(ar[it], hi, lo);
      *(uint2*)(st + off)              = hi;   // Ah
      *(uint2*)(st + TILE_E + off)     = lo;   // Al
      cvt_split(br[it], hi, lo);
      *(uint2*)(st + 2 * TILE_E + off) = hi;   // Bh
      *(uint2*)(st + 3 * TILE_E + off) = lo;   // Bl
    }
  };

  auto COMP = [&](int s) {
    const uint32_t base = smem_u32(sm + s * STAGE_E);
    #pragma unroll
    for (int ks = 0; ks < 2; ++ks) {
      uint32_t ah[2][4], al[2][4], bh[2][4], bl[2][4];
      #pragma unroll
      for (int mt = 0; mt < 2; ++mt) {
        uint32_t ad = base + (uint32_t)(((wm * 32 + mt * 16 + a_r) * KP +
                                         ks * 16 + a_k) << 1);
        LDSM4(ah[mt], ad);
        LDSM4(al[mt], ad + TILE_E * 2);
      }
      #pragma unroll
      for (int np = 0; np < 2; ++np) {
        uint32_t bd = base + 2 * TILE_E * 2 +
                      (uint32_t)(((wn * 32 + np * 16 + b_r) * KP +
                                  ks * 16 + b_k) << 1);
        LDSM4(bh[np], bd);
        LDSM4(bl[np], bd + TILE_E * 2);
      }
      #pragma unroll
      for (int mt = 0; mt < 2; ++mt)
        #pragma unroll
        for (int nt = 0; nt < 4; ++nt) {
          uint32_t* bhp = &bh[nt >> 1][(nt & 1) * 2];
          uint32_t* blp = &bl[nt >> 1][(nt & 1) * 2];
          MMA_BF16(acc[mt][nt], ah[mt], bhp);
          MMA_BF16(acc[mt][nt], ah[mt], blp);
          MMA_BF16(acc[mt][nt], al[mt], bhp);
        }
    }
  };

  const int NC = K / KC;
  LDG(0); STS(0);
  __syncthreads();
  for (int ch = 0; ch < NC; ++ch) {
    if (ch + 1 < NC) LDG(ch + 1);      // LDG latency hides behind COMP
    COMP(ch & 1);
    if (ch + 1 < NC) STS((ch + 1) & 1);
    __syncthreads();
  }

  // epilogue: fragment -> gmem (float2 stores)
  #pragma unroll
  for (int mt = 0; mt < 2; ++mt) {
    const int r0 = bm * 128 + wm * 32 + mt * 16 + (lane >> 2);
    #pragma unroll
    for (int nt = 0; nt < 4; ++nt) {
      const int c0 = bn * 128 + wn * 32 + nt * 8 + ((lane & 3) << 1);
      *(float2*)&C[(size_t)r0 * N + c0] =
          make_float2(acc[mt][nt][0], acc[mt][nt][1]);
      *(float2*)&C[(size_t)(r0 + 8) * N + c0] =
          make_float2(acc[mt][nt][2], acc[mt][nt][3]);
    }
  }
}

// ---------------------------------------------------------------------------
// Per-head RMSNorm + NeoX RoPE (unchanged)
// ---------------------------------------------------------------------------
__global__ __launch_bounds__(128) void norm_rope(
    float* __restrict__ qkv, const int* __restrict__ positions,
    const float* __restrict__ qw, const float* __restrict__ kw)
{
  const int t  = blockIdx.x;
  const int hh = blockIdx.y;
  const int d  = threadIdx.x;
  float* base = qkv + (size_t)t * QKV_N +
                (hh < NH ? hh * HD : NH * HD + (hh - NH) * HD);
  const float* w = (hh < NH) ? qw : kw;

  float x  = base[d];
  float ss = x * x;
  #pragma unroll
  for (int off = 16; off > 0; off >>= 1)
    ss += __shfl_xor_sync(0xffffffffu, ss, off);
  __shared__ float red[4];
  __shared__ float ybuf[HD];
  if ((d & 31) == 0) red[d >> 5] = ss;
  __syncthreads();
  float tot = red[0] + red[1] + red[2] + red[3];
  float y = x * rsqrtf(tot * (1.0f / HD) + 1e-6f) * w[d];
  ybuf[d] = y;
  __syncthreads();

  const float pos = (float)positions[t];
  const int   i   = d & 63;
  const float inv = exp2f(-(float)i * (19.931568569324174f / 64.0f));
  float s, c;
  sincosf(pos * inv, &s, &c);
  float out;
  if (d < 64) out = y * c - ybuf[d + 64] * s;
  else        out = ybuf[d - 64] * s + y * c;
  base[d] = out;
}

// ===========================================================================
// Flash attention with bf16-split HMMA (unchanged from R7 passing version).
// ===========================================================================
#define ABM 128
#define ABN 64
#define QP  136
#define VTP 72
#define S_QH 0
#define S_QL (128*QP)
#define S_KH (2*128*QP)
#define S_KL (S_KH + 64*QP)
#define S_VH (S_KH + 2*64*QP)
#define S_VL (S_VH + 128*VTP)
#define FLASH_SMEM ((S_VL + 128*VTP) * 2)

__global__ __launch_bounds__(256, 1) void flash_mma(
    const float* __restrict__ qkv, float* __restrict__ o)
{
  extern __shared__ __nv_bfloat16 sb[];
  const uint32_t sbase = smem_u32(sb);
  const int tid  = threadIdx.x;
  const int lane = tid & 31;
  const int w    = tid >> 5;
  const int q0   = blockIdx.x * ABM;
  const int h    = blockIdx.y;
  const int kvh  = h >> 3;
  const float scale = 0.08838834764831845f;   // 1/sqrt(128)

  const int mi  = lane >> 3, li = lane & 7;
  const int a_r = ((mi & 1) << 3) + li;
  const int a_k = (mi >> 1) << 3;
  const int b_r = ((mi >> 1) << 3) + li;
  const int b_k = (mi & 1) << 3;

  // ---- load Q tile (pre-scaled), split into Qh/Ql ----
  #pragma unroll
  for (int it = 0; it < 16; ++it) {
    const int idx = tid + it * 256;
    const int r = idx >> 5, c = (idx & 31) << 2;
    float4 v = *(const float4*)(qkv + (size_t)(q0 + r) * QKV_N + h * HD + c);
    v.x *= scale; v.y *= scale; v.z *= scale; v.w *= scale;
    uint2 hi, lo; cvt_split(v, hi, lo);
    *(uint2*)(sb + S_QH + r * QP + c) = hi;
    *(uint2*)(sb + S_QL + r * QP + c) = lo;
  }

  float oacc[16][4];
  #pragma unroll
  for (int nt = 0; nt < 16; ++nt)
    #pragma unroll
    for (int q = 0; q < 4; ++q) oacc[nt][q] = 0.f;
  float mA = -1e30f, mB = -1e30f, lA = 0.f, lB = 0.f;

  const int ktmax = q0 / ABN + 1;
  for (int kt = 0; kt <= ktmax; ++kt) {
    const int k0 = kt * ABN;
    __syncthreads();   // prior compute done with K/V smem (Q load on iter 0)

    // ---- K tile: 64 x 128, split into Kh/Kl ----
    #pragma unroll
    for (int it = 0; it < 8; ++it) {
      const int idx = tid + it * 256;
      const int r = idx >> 5, c = (idx & 31) << 2;
      float4 v = *(const float4*)(qkv + (size_t)(k0 + r) * QKV_N +
                                  NH * HD + kvh * HD + c);
      uint2 hi, lo; cvt_split(v, hi, lo);
      *(uint2*)(sb + S_KH + r * QP + c) = hi;
      *(uint2*)(sb + S_KL + r * QP + c) = lo;
    }
    // ---- V tile: transpose to V^T[hd][token], split ----
    #pragma unroll
    for (int it = 0; it < 8; ++it) {
      const int idx = tid + it * 256;
      const int hd = idx & 127, tg = idx >> 7;   // tg: token group of 4
      const float* vb = qkv + (size_t)(k0 + tg * 4) * QKV_N +
                        (NH + NKV) * HD + kvh * HD + hd;
      float v0 = vb[0], v1 = vb[QKV_N], v2 = vb[2*QKV_N], v3 = vb[3*QKV_N];
      uint32_t h01, l01, h23, l23;
      split2(v0, v1, h01, l01);
      split2(v2, v3, h23, l23);
      *(uint2*)(sb + S_VH + hd * VTP + tg * 4) = make_uint2(h01, h23);
      *(uint2*)(sb + S_VL + hd * VTP + tg * 4) = make_uint2(l01, l23);
    }
    __syncthreads();

    // ---- S = Q @ K^T (m16 x n64, k=128) ----
    float sacc[8][4];
    #pragma unroll
    for (int nt = 0; nt < 8; ++nt)
      #pragma unroll
      for (int q = 0; q < 4; ++q) sacc[nt][q] = 0.f;

    #pragma unroll
    for (int ks = 0; ks < 8; ++ks) {
      uint32_t qh[4], ql[4], kh[4][4], kl[4][4];
      const uint32_t qa = sbase + (uint32_t)(((w * 16 + a_r) * QP +
                                             ks * 16 + a_k) << 1);
      LDSM4(qh, qa);
      LDSM4(ql, qa + S_QL * 2);
      #pragma unroll
      for (int np = 0; np < 4; ++np) {
        const uint32_t ka = sbase + (uint32_t)((S_KH + (np * 16 + b_r) * QP +
                                                ks * 16 + b_k) << 1);
        LDSM4(kh[np], ka);
        LDSM4(kl[np], ka + (S_KL - S_KH) * 2);
      }
      #pragma unroll
      for (int nt = 0; nt < 8; ++nt) {
        uint32_t* bhp = &kh[nt >> 1][(nt & 1) * 2];
        uint32_t* blp = &kl[nt >> 1][(nt & 1) * 2];
        MMA_BF16(sacc[nt], qh, bhp);
        MMA_BF16(sacc[nt], qh, blp);
        MMA_BF16(sacc[nt], ql, bhp);
      }
    }

    const int qrA = q0 + w * 16 + (lane >> 2);
    const int qrB = qrA + 8;
    if (k0 + ABN - 1 > q0) {   // causal mask (last two tiles only)
      #pragma unroll
      for (int nt = 0; nt < 8; ++nt) {
        const int kc = k0 + nt * 8 + ((lane & 3) << 1);
        if (kc     > qrA) sacc[nt][0] = -1e30f;
        if (kc + 1 > qrA) sacc[nt][1] = -1e30f;
        if (kc     > qrB) sacc[nt][2] = -1e30f;
        if (kc + 1 > qrB) sacc[nt][3] = -1e30f;
      }
    }

    // ---- online softmax (2 rows per thread) ----
    float mxA = -1e30f, mxB = -1e30f;
    #pragma unroll
    for (int nt = 0; nt < 8; ++nt) {
      mxA = fmaxf(mxA, fmaxf(sacc[nt][0], sacc[nt][1]));
      mxB = fmaxf(mxB, fmaxf(sacc[nt][2], sacc[nt][3]));
    }
    mxA = fmaxf(mxA, __shfl_xor_sync(0xffffffffu, mxA, 1));
    mxA = fmaxf(mxA, __shfl_xor_sync(0xffffffffu, mxA, 2));
    mxB = fmaxf(mxB, __shfl_xor_sync(0xffffffffu, mxB, 1));
    mxB = fmaxf(mxB, __shfl_xor_sync(0xffffffffu, mxB, 2));
    const float mnA = fmaxf(mA, mxA), mnB = fmaxf(mB, mxB);
    const float cA = __expf(mA - mnA), cB = __expf(mB - mnB);
    mA = mnA; mB = mnB;

    float rsA = 0.f, rsB = 0.f;
    #pragma unroll
    for (int nt = 0; nt < 8; ++nt) {
      sacc[nt][0] = __expf(sacc[nt][0] - mnA);
      sacc[nt][1] = __expf(sacc[nt][1] - mnA);
      sacc[nt][2] = __expf(sacc[nt][2] - mnB);
      sacc[nt][3] = __expf(sacc[nt][3] - mnB);
      rsA += sacc[nt][0] + sacc[nt][1];
      rsB += sacc[nt][2] + sacc[nt][3];
    }
    rsA += __shfl_xor_sync(0xffffffffu, rsA, 1);
    rsA += __shfl_xor_sync(0xffffffffu, rsA, 2);
    rsB += __shfl_xor_sync(0xffffffffu, rsB, 1);
    rsB += __shfl_xor_sync(0xffffffffu, rsB, 2);
    lA = lA * cA + rsA;
    lB = lB * cB + rsB;
    #pragma unroll
    for (int nt = 0; nt < 16; ++nt) {
      oacc[nt][0] *= cA; oacc[nt][1] *= cA;
      oacc[nt][2] *= cB; oacc[nt][3] *= cB;
    }

    // ---- O += P @ V (P from registers, V^T from smem) ----
    #pragma unroll
    for (int kk = 0; kk < 4; ++kk) {
      uint32_t ph[4], pl[4];
      split2(sacc[2*kk][0],   sacc[2*kk][1],   ph[0], pl[0]);
      split2(sacc[2*kk][2],   sacc[2*kk][3],   ph[1], pl[1]);
      split2(sacc[2*kk+1][0], sacc[2*kk+1][1], ph[2], pl[2]);
      split2(sacc[2*kk+1][2], sacc[2*kk+1][3], ph[3], pl[3]);
      #pragma unroll
      for (int np = 0; np < 8; ++np) {
        uint32_t vh[4], vl[4];
        const uint32_t va = sbase + (uint32_t)((S_VH + (np * 16 + b_r) * VTP +
                                                kk * 16 + b_k) << 1);
        LDSM4(vh, va);
        LDSM4(vl, va + (S_VL - S_VH) * 2);
        MMA_BF16(oacc[2*np],   ph, (&vh[0]));
        MMA_BF16(oacc[2*np],   ph, (&vl[0]));
        MMA_BF16(oacc[2*np],   pl, (&vh[0]));
        MMA_BF16(oacc[2*np+1], ph, (&vh[2]));
        MMA_BF16(oacc[2*np+1], ph, (&vl[2]));
        MMA_BF16(oacc[2*np+1], pl, (&vh[2]));
      }
    }
  }

  // ---- epilogue ----
  const float invA = 1.0f / lA, invB = 1.0f / lB;
  const int rowA = q0 + w * 16 + (lane >> 2);
  #pragma unroll
  for (int nt = 0; nt < 16; ++nt) {
    const int c0 = h * HD + nt * 8 + ((lane & 3) << 1);
    *(float2*)&o[(size_t)rowA * ON + c0] =
        make_float2(oacc[nt][0] * invA, oacc[nt][1] * invA);
    *(float2*)&o[(size_t)(rowA + 8) * ON + c0] =
        make_float2(oacc[nt][2] * invB, oacc[nt][3] * invB);
  }
}

// ---------------------------------------------------------------------------
extern "C" void kernel_launch(void* const* d_in, const int* in_sizes, int n_in,
                              void* d_out, int out_size)
{
  (void)in_sizes; (void)n_in; (void)out_size;
  const int*   positions = (const int*)  d_in[0];
  const float* hidden    = (const float*)d_in[1];
  const float* w_qkv     = (const float*)d_in[2];
  const float* w_o       = (const float*)d_in[3];
  const float* qw        = (const float*)d_in[4];
  const float* kw        = (const float*)d_in[5];
  float* out = (float*)d_out;

  float *qkv, *obuf;
  cudaGetSymbolAddress((void**)&qkv,  g_qkv);
  cudaGetSymbolAddress((void**)&obuf, g_o);

  cudaFuncSetAttribute(gemm_mma, cudaFuncAttributeMaxDynamicSharedMemorySize,
                       GEMM_SMEM);
  cudaFuncSetAttribute(flash_mma, cudaFuncAttributeMaxDynamicSharedMemorySize,
                       FLASH_SMEM);

  // 1) QKV projection (bf16-split HMMA, 512 threads)
  gemm_mma<<<dim3(QKV_N/128, T_TOK/128), 512, GEMM_SMEM>>>(
      hidden, w_qkv, qkv, T_TOK, QKV_N, HIDN);

  // 2) RMSNorm + RoPE in place on Q/K head slices
  norm_rope<<<dim3(T_TOK, NH + NKV), 128>>>(qkv, positions, qw, kw);

  // 3) Causal GQA flash attention (bf16-split HMMA)
  flash_mma<<<dim3(T_TOK/ABM, NH), 256, FLASH_SMEM>>>(qkv, obuf);

  // 4) Output projection (bf16-split HMMA, 512 threads)
  gemm_mma<<<dim3(HIDN/128, T_TOK/128), 512, GEMM_SMEM>>>(
      obuf, w_o, out, T_TOK, HIDN, ON);
}

// round 10
// speedup vs baseline: 2.6785x; 1.0306x over previous
#include <cuda_runtime.h>
#include <cuda_bf16.h>
#include <math.h>
#include <stdint.h>

#define T_TOK 2048
#define HIDN  2048
#define NH    32
#define NKV   4
#define HD    128
#define QKV_N ((NH + 2*NKV)*HD)   /* 5120 */
#define ON    (NH*HD)             /* 4096 */

// Scratch (static device globals: allocation-free)
__device__ float g_qkv[(size_t)T_TOK * QKV_N];   // ~40 MiB
__device__ float g_o  [(size_t)T_TOK * ON];      // ~32 MiB

// Pre-split bf16 hi/lo operand buffers
__device__ __nv_bfloat16 g_hid_h [(size_t)T_TOK * HIDN];
__device__ __nv_bfloat16 g_hid_l [(size_t)T_TOK * HIDN];
__device__ __nv_bfloat16 g_wqkv_h[(size_t)QKV_N * HIDN];
__device__ __nv_bfloat16 g_wqkv_l[(size_t)QKV_N * HIDN];
__device__ __nv_bfloat16 g_wo_h  [(size_t)HIDN * ON];
__device__ __nv_bfloat16 g_wo_l  [(size_t)HIDN * ON];
__device__ __nv_bfloat16 g_ob_h  [(size_t)T_TOK * ON];
__device__ __nv_bfloat16 g_ob_l  [(size_t)T_TOK * ON];

// ===========================================================================
// Helpers
// ===========================================================================
__device__ __forceinline__ uint32_t smem_u32(const void* p) {
  uint32_t a;
  asm("{ .reg .u64 t; cvta.to.shared.u64 t, %1; cvt.u32.u64 %0, t; }"
      : "=r"(a) : "l"(p));
  return a;
}

// fp32 -> (hi, lo) bf16 split, 4 elements -> two 8B words
__device__ __forceinline__ void cvt_split(float4 v, uint2& hi, uint2& lo) {
  float f[4] = {v.x, v.y, v.z, v.w};
  uint32_t hs[4], ls[4];
  #pragma unroll
  for (int i = 0; i < 4; i++) {
    __nv_bfloat16 h = __float2bfloat16_rn(f[i]);
    float r = f[i] - __bfloat162float(h);
    __nv_bfloat16 l = __float2bfloat16_rn(r);
    hs[i] = (uint32_t)__bfloat16_as_ushort(h);
    ls[i] = (uint32_t)__bfloat16_as_ushort(l);
  }
  hi.x = hs[0] | (hs[1] << 16); hi.y = hs[2] | (hs[3] << 16);
  lo.x = ls[0] | (ls[1] << 16); lo.y = ls[2] | (ls[3] << 16);
}

// two fp32 -> packed bf16x2 hi + residual lo (low 16 bits = first arg)
__device__ __forceinline__ void split2(float a, float b,
                                       uint32_t& hi, uint32_t& lo) {
  __nv_bfloat162 h = __floats2bfloat162_rn(a, b);
  float ra = a - __bfloat162float(h.x);
  float rb = b - __bfloat162float(h.y);
  __nv_bfloat162 l = __floats2bfloat162_rn(ra, rb);
  hi = *reinterpret_cast<uint32_t*>(&h);
  lo = *reinterpret_cast<uint32_t*>(&l);
}

#define LDSM4(r, a)                                                          \
  asm volatile("ldmatrix.sync.aligned.m8n8.x4.shared.b16 {%0,%1,%2,%3}, [%4];" \
    : "=r"((r)[0]), "=r"((r)[1]), "=r"((r)[2]), "=r"((r)[3]) : "r"(a))

#define MMA_BF16(c, a, b)                                                    \
  asm volatile("mma.sync.aligned.m16n8k16.row.col.f32.bf16.bf16.f32 "        \
    "{%0,%1,%2,%3}, {%4,%5,%6,%7}, {%8,%9}, {%0,%1,%2,%3};"                  \
    : "+f"((c)[0]), "+f"((c)[1]), "+f"((c)[2]), "+f"((c)[3])                 \
    : "r"((a)[0]), "r"((a)[1]), "r"((a)[2]), "r"((a)[3]),                    \
      "r"((b)[0]), "r"((b)[1]))

#define CP_ASYNC8(dst, src)                                                  \
  asm volatile("cp.async.ca.shared.global [%0], [%1], 8;"                    \
               :: "r"(dst), "l"(src))
#define CP_COMMIT() asm volatile("cp.async.commit_group;" ::: "memory")
#define CP_WAIT2()  asm volatile("cp.async.wait_group 2;" ::: "memory")

// ---------------------------------------------------------------------------
// Split pass: fp32 -> bf16 hi/lo arrays (memory-bound, one shot per launch)
// ---------------------------------------------------------------------------
__global__ __launch_bounds__(256) void split_f32(
    const float* __restrict__ src, __nv_bfloat16* __restrict__ hi,
    __nv_bfloat16* __restrict__ lo, int n4)
{
  const int i = blockIdx.x * 256 + threadIdx.x;
  if (i < n4) {
    float4 v = ((const float4*)src)[i];
    uint2 h, l; cvt_split(v, h, l);
    ((uint2*)hi)[i] = h;
    ((uint2*)lo)[i] = l;
  }
}

// ===========================================================================
// bf16-split HMMA GEMM v2 (NT): pre-split bf16 operands, cp.async 4-stage
// pipeline. CTA 128x128, 512 threads / 16 warps (4x4), warp tile 32x32,
// K chunk 32. Smem stage: Ah/Al/Bh/Bl, 128 x KP bf16 each (KP=40).
// ===========================================================================
#define KC 32
#define KP 40
#define TILE_E (128 * KP)
#define STAGE_E (4 * TILE_E)
#define NSTAGE 4
#define GEMM_SMEM (NSTAGE * STAGE_E * 2)   /* 163840 B */

__global__ __launch_bounds__(512) void gemm_mma(
    const __nv_bfloat16* __restrict__ Ah, const __nv_bfloat16* __restrict__ Al,
    const __nv_bfloat16* __restrict__ Bh, const __nv_bfloat16* __restrict__ Bl,
    float* __restrict__ C, int M, int N, int K)
{
  extern __shared__ __nv_bfloat16 sm[];
  const uint32_t sbase = smem_u32(sm);
  const int tid  = threadIdx.x;
  const int lane = tid & 31;
  const int w    = tid >> 5;       // 0..15
  const int wm   = w & 3;          // M warp (0..3)
  const int wn   = w >> 2;         // N warp (0..3)
  const int bm   = blockIdx.y, bn = blockIdx.x;

  const __nv_bfloat16* tb[4] = {
    Ah + (size_t)bm * 128 * K, Al + (size_t)bm * 128 * K,
    Bh + (size_t)bn * 128 * K, Bl + (size_t)bn * 128 * K };

  // ldmatrix per-thread source rows
  const int mi  = lane >> 3, li = lane & 7;
  const int a_r = ((mi & 1) << 3) + li;
  const int a_k = (mi >> 1) << 3;
  const int b_r = ((mi >> 1) << 3) + li;
  const int b_k = (mi & 1) << 3;

  float acc[2][4][4];
  #pragma unroll
  for (int mt = 0; mt < 2; ++mt)
    #pragma unroll
    for (int nt = 0; nt < 4; ++nt)
      #pragma unroll
      for (int q = 0; q < 4; ++q) acc[mt][nt][q] = 0.f;

  // cp.async loader: 4 tiles x 128 rows x 8 8B-chunks = 4096 ops, 8/thread
  auto LOAD = [&](int ch) {
    const int s = ch & (NSTAGE - 1);
    const uint32_t st = sbase + (uint32_t)(s * STAGE_E * 2);
    const int kb = ch * KC;
    #pragma unroll
    for (int tile = 0; tile < 4; ++tile) {
      #pragma unroll
      for (int j = 0; j < 2; ++j) {
        const int c   = tid + j * 512;
        const int row = c >> 3;
        const int k8  = (c & 7) << 2;    // bf16 offset within chunk row
        const __nv_bfloat16* src = tb[tile] + (size_t)row * K + kb + k8;
        const uint32_t dst = st + (uint32_t)((tile * TILE_E + row * KP + k8) << 1);
        CP_ASYNC8(dst, src);
      }
    }
    CP_COMMIT();
  };

  auto COMP = [&](int ch) {
    const uint32_t base = sbase + (uint32_t)((ch & (NSTAGE - 1)) * STAGE_E * 2);
    #pragma unroll
    for (int ks = 0; ks < 2; ++ks) {
      uint32_t ah[2][4], al[2][4], bh[2][4], bl[2][4];
      #pragma unroll
      for (int mt = 0; mt < 2; ++mt) {
        uint32_t ad = base + (uint32_t)(((wm * 32 + mt * 16 + a_r) * KP +
                                         ks * 16 + a_k) << 1);
        LDSM4(ah[mt], ad);
        LDSM4(al[mt], ad + TILE_E * 2);
      }
      #pragma unroll
      for (int np = 0; np < 2; ++np) {
        uint32_t bd = base + 2 * TILE_E * 2 +
                      (uint32_t)(((wn * 32 + np * 16 + b_r) * KP +
                                  ks * 16 + b_k) << 1);
        LDSM4(bh[np], bd);
        LDSM4(bl[np], bd + TILE_E * 2);
      }
      #pragma unroll
      for (int mt = 0; mt < 2; ++mt)
        #pragma unroll
        for (int nt = 0; nt < 4; ++nt) {
          uint32_t* bhp = &bh[nt >> 1][(nt & 1) * 2];
          uint32_t* blp = &bl[nt >> 1][(nt & 1) * 2];
          MMA_BF16(acc[mt][nt], ah[mt], bhp);
          MMA_BF16(acc[mt][nt], ah[mt], blp);
          MMA_BF16(acc[mt][nt], al[mt], bhp);
        }
    }
  };

  const int NC = K / KC;
  LOAD(0); LOAD(1); LOAD(2);
  for (int ch = 0; ch < NC; ++ch) {
    CP_WAIT2();           // stage ch resident
    __syncthreads();      // all warps done reading stage (ch-1)&3
    if (ch + 3 < NC) LOAD(ch + 3);
    COMP(ch);
  }

  // epilogue: fragment -> gmem (float2 stores)
  #pragma unroll
  for (int mt = 0; mt < 2; ++mt) {
    const int r0 = bm * 128 + wm * 32 + mt * 16 + (lane >> 2);
    #pragma unroll
    for (int nt = 0; nt < 4; ++nt) {
      const int c0 = bn * 128 + wn * 32 + nt * 8 + ((lane & 3) << 1);
      *(float2*)&C[(size_t)r0 * N + c0] =
          make_float2(acc[mt][nt][0], acc[mt][nt][1]);
      *(float2*)&C[(size_t)(r0 + 8) * N + c0] =
          make_float2(acc[mt][nt][2], acc[mt][nt][3]);
    }
  }
}

// ---------------------------------------------------------------------------
// Per-head RMSNorm + NeoX RoPE (unchanged)
// ---------------------------------------------------------------------------
__global__ __launch_bounds__(128) void norm_rope(
    float* __restrict__ qkv, const int* __restrict__ positions,
    const float* __restrict__ qw, const float* __restrict__ kw)
{
  const int t  = blockIdx.x;
  const int hh = blockIdx.y;
  const int d  = threadIdx.x;
  float* base = qkv + (size_t)t * QKV_N +
                (hh < NH ? hh * HD : NH * HD + (hh - NH) * HD);
  const float* w = (hh < NH) ? qw : kw;

  float x  = base[d];
  float ss = x * x;
  #pragma unroll
  for (int off = 16; off > 0; off >>= 1)
    ss += __shfl_xor_sync(0xffffffffu, ss, off);
  __shared__ float red[4];
  __shared__ float ybuf[HD];
  if ((d & 31) == 0) red[d >> 5] = ss;
  __syncthreads();
  float tot = red[0] + red[1] + red[2] + red[3];
  float y = x * rsqrtf(tot * (1.0f / HD) + 1e-6f) * w[d];
  ybuf[d] = y;
  __syncthreads();

  const float pos = (float)positions[t];
  const int   i   = d & 63;
  const float inv = exp2f(-(float)i * (19.931568569324174f / 64.0f));
  float s, c;
  sincosf(pos * inv, &s, &c);
  float out;
  if (d < 64) out = y * c - ybuf[d + 64] * s;
  else        out = ybuf[d - 64] * s + y * c;
  base[d] = out;
}

// ===========================================================================
// Flash attention with bf16-split HMMA (unchanged from R7/R8 passing version)
// ===========================================================================
#define ABM 128
#define ABN 64
#define QP  136
#define VTP 72
#define S_QH 0
#define S_QL (128*QP)
#define S_KH (2*128*QP)
#define S_KL (S_KH + 64*QP)
#define S_VH (S_KH + 2*64*QP)
#define S_VL (S_VH + 128*VTP)
#define FLASH_SMEM ((S_VL + 128*VTP) * 2)

__global__ __launch_bounds__(256, 1) void flash_mma(
    const float* __restrict__ qkv, float* __restrict__ o)
{
  extern __shared__ __nv_bfloat16 sb[];
  const uint32_t sbase = smem_u32(sb);
  const int tid  = threadIdx.x;
  const int lane = tid & 31;
  const int w    = tid >> 5;
  const int q0   = blockIdx.x * ABM;
  const int h    = blockIdx.y;
  const int kvh  = h >> 3;
  const float scale = 0.08838834764831845f;   // 1/sqrt(128)

  const int mi  = lane >> 3, li = lane & 7;
  const int a_r = ((mi & 1) << 3) + li;
  const int a_k = (mi >> 1) << 3;
  const int b_r = ((mi >> 1) << 3) + li;
  const int b_k = (mi & 1) << 3;

  // ---- load Q tile (pre-scaled), split into Qh/Ql ----
  #pragma unroll
  for (int it = 0; it < 16; ++it) {
    const int idx = tid + it * 256;
    const int r = idx >> 5, c = (idx & 31) << 2;
    float4 v = *(const float4*)(qkv + (size_t)(q0 + r) * QKV_N + h * HD + c);
    v.x *= scale; v.y *= scale; v.z *= scale; v.w *= scale;
    uint2 hi, lo; cvt_split(v, hi, lo);
    *(uint2*)(sb + S_QH + r * QP + c) = hi;
    *(uint2*)(sb + S_QL + r * QP + c) = lo;
  }

  float oacc[16][4];
  #pragma unroll
  for (int nt = 0; nt < 16; ++nt)
    #pragma unroll
    for (int q = 0; q < 4; ++q) oacc[nt][q] = 0.f;
  float mA = -1e30f, mB = -1e30f, lA = 0.f, lB = 0.f;

  const int ktmax = q0 / ABN + 1;
  for (int kt = 0; kt <= ktmax; ++kt) {
    const int k0 = kt * ABN;
    __syncthreads();

    #pragma unroll
    for (int it = 0; it < 8; ++it) {
      const int idx = tid + it * 256;
      const int r = idx >> 5, c = (idx & 31) << 2;
      float4 v = *(const float4*)(qkv + (size_t)(k0 + r) * QKV_N +
                                  NH * HD + kvh * HD + c);
      uint2 hi, lo; cvt_split(v, hi, lo);
      *(uint2*)(sb + S_KH + r * QP + c) = hi;
      *(uint2*)(sb + S_KL + r * QP + c) = lo;
    }
    #pragma unroll
    for (int it = 0; it < 8; ++it) {
      const int idx = tid + it * 256;
      const int hd = idx & 127, tg = idx >> 7;
      const float* vb = qkv + (size_t)(k0 + tg * 4) * QKV_N +
                        (NH + NKV) * HD + kvh * HD + hd;
      float v0 = vb[0], v1 = vb[QKV_N], v2 = vb[2*QKV_N], v3 = vb[3*QKV_N];
      uint32_t h01, l01, h23, l23;
      split2(v0, v1, h01, l01);
      split2(v2, v3, h23, l23);
      *(uint2*)(sb + S_VH + hd * VTP + tg * 4) = make_uint2(h01, h23);
      *(uint2*)(sb + S_VL + hd * VTP + tg * 4) = make_uint2(l01, l23);
    }
    __syncthreads();

    float sacc[8][4];
    #pragma unroll
    for (int nt = 0; nt < 8; ++nt)
      #pragma unroll
      for (int q = 0; q < 4; ++q) sacc[nt][q] = 0.f;

    #pragma unroll
    for (int ks = 0; ks < 8; ++ks) {
      uint32_t qh[4], ql[4], kh[4][4], kl[4][4];
      const uint32_t qa = sbase + (uint32_t)(((w * 16 + a_r) * QP +
                                             ks * 16 + a_k) << 1);
      LDSM4(qh, qa);
      LDSM4(ql, qa + S_QL * 2);
      #pragma unroll
      for (int np = 0; np < 4; ++np) {
        const uint32_t ka = sbase + (uint32_t)((S_KH + (np * 16 + b_r) * QP +
                                                ks * 16 + b_k) << 1);
        LDSM4(kh[np], ka);
        LDSM4(kl[np], ka + (S_KL - S_KH) * 2);
      }
      #pragma unroll
      for (int nt = 0; nt < 8; ++nt) {
        uint32_t* bhp = &kh[nt >> 1][(nt & 1) * 2];
        uint32_t* blp = &kl[nt >> 1][(nt & 1) * 2];
        MMA_BF16(sacc[nt], qh, bhp);
        MMA_BF16(sacc[nt], qh, blp);
        MMA_BF16(sacc[nt], ql, bhp);
      }
    }

    const int qrA = q0 + w * 16 + (lane >> 2);
    const int qrB = qrA + 8;
    if (k0 + ABN - 1 > q0) {
      #pragma unroll
      for (int nt = 0; nt < 8; ++nt) {
        const int kc = k0 + nt * 8 + ((lane & 3) << 1);
        if (kc     > qrA) sacc[nt][0] = -1e30f;
        if (kc + 1 > qrA) sacc[nt][1] = -1e30f;
        if (kc     > qrB) sacc[nt][2] = -1e30f;
        if (kc + 1 > qrB) sacc[nt][3] = -1e30f;
      }
    }

    float mxA = -1e30f, mxB = -1e30f;
    #pragma unroll
    for (int nt = 0; nt < 8; ++nt) {
      mxA = fmaxf(mxA, fmaxf(sacc[nt][0], sacc[nt][1]));
      mxB = fmaxf(mxB, fmaxf(sacc[nt][2], sacc[nt][3]));
    }
    mxA = fmaxf(mxA, __shfl_xor_sync(0xffffffffu, mxA, 1));
    mxA = fmaxf(mxA, __shfl_xor_sync(0xffffffffu, mxA, 2));
    mxB = fmaxf(mxB, __shfl_xor_sync(0xffffffffu, mxB, 1));
    mxB = fmaxf(mxB, __shfl_xor_sync(0xffffffffu, mxB, 2));
    const float mnA = fmaxf(mA, mxA), mnB = fmaxf(mB, mxB);
    const float cA = __expf(mA - mnA), cB = __expf(mB - mnB);
    mA = mnA; mB = mnB;

    float rsA = 0.f, rsB = 0.f;
    #pragma unroll
    for (int nt = 0; nt < 8; ++nt) {
      sacc[nt][0] = __expf(sacc[nt][0] - mnA);
      sacc[nt][1] = __expf(sacc[nt][1] - mnA);
      sacc[nt][2] = __expf(sacc[nt][2] - mnB);
      sacc[nt][3] = __expf(sacc[nt][3] - mnB);
      rsA += sacc[nt][0] + sacc[nt][1];
      rsB += sacc[nt][2] + sacc[nt][3];
    }
    rsA += __shfl_xor_sync(0xffffffffu, rsA, 1);
    rsA += __shfl_xor_sync(0xffffffffu, rsA, 2);
    rsB += __shfl_xor_sync(0xffffffffu, rsB, 1);
    rsB += __shfl_xor_sync(0xffffffffu, rsB, 2);
    lA = lA * cA + rsA;
    lB = lB * cB + rsB;
    #pragma unroll
    for (int nt = 0; nt < 16; ++nt) {
      oacc[nt][0] *= cA; oacc[nt][1] *= cA;
      oacc[nt][2] *= cB; oacc[nt][3] *= cB;
    }

    #pragma unroll
    for (int kk = 0; kk < 4; ++kk) {
      uint32_t ph[4], pl[4];
      split2(sacc[2*kk][0],   sacc[2*kk][1],   ph[0], pl[0]);
      split2(sacc[2*kk][2],   sacc[2*kk][3],   ph[1], pl[1]);
      split2(sacc[2*kk+1][0], sacc[2*kk+1][1], ph[2], pl[2]);
      split2(sacc[2*kk+1][2], sacc[2*kk+1][3], ph[3], pl[3]);
      #pragma unroll
      for (int np = 0; np < 8; ++np) {
        uint32_t vh[4], vl[4];
        const uint32_t va = sbase + (uint32_t)((S_VH + (np * 16 + b_r) * VTP +
                                                kk * 16 + b_k) << 1);
        LDSM4(vh, va);
        LDSM4(vl, va + (S_VL - S_VH) * 2);
        MMA_BF16(oacc[2*np],   ph, (&vh[0]));
        MMA_BF16(oacc[2*np],   ph, (&vl[0]));
        MMA_BF16(oacc[2*np],   pl, (&vh[0]));
        MMA_BF16(oacc[2*np+1], ph, (&vh[2]));
        MMA_BF16(oacc[2*np+1], ph, (&vl[2]));
        MMA_BF16(oacc[2*np+1], pl, (&vh[2]));
      }
    }
  }

  const float invA = 1.0f / lA, invB = 1.0f / lB;
  const int rowA = q0 + w * 16 + (lane >> 2);
  #pragma unroll
  for (int nt = 0; nt < 16; ++nt) {
    const int c0 = h * HD + nt * 8 + ((lane & 3) << 1);
    *(float2*)&o[(size_t)rowA * ON + c0] =
        make_float2(oacc[nt][0] * invA, oacc[nt][1] * invA);
    *(float2*)&o[(size_t)(rowA + 8) * ON + c0] =
        make_float2(oacc[nt][2] * invB, oacc[nt][3] * invB);
  }
}

// ---------------------------------------------------------------------------
extern "C" void kernel_launch(void* const* d_in, const int* in_sizes, int n_in,
                              void* d_out, int out_size)
{
  (void)in_sizes; (void)n_in; (void)out_size;
  const int*   positions = (const int*)  d_in[0];
  const float* hidden    = (const float*)d_in[1];
  const float* w_qkv     = (const float*)d_in[2];
  const float* w_o       = (const float*)d_in[3];
  const float* qw        = (const float*)d_in[4];
  const float* kw        = (const float*)d_in[5];
  float* out = (float*)d_out;

  float *qkv, *obuf;
  cudaGetSymbolAddress((void**)&qkv,  g_qkv);
  cudaGetSymbolAddress((void**)&obuf, g_o);
  __nv_bfloat16 *hid_h, *hid_l, *wqkv_h, *wqkv_l, *wo_h, *wo_l, *ob_h, *ob_l;
  cudaGetSymbolAddress((void**)&hid_h,  g_hid_h);
  cudaGetSymbolAddress((void**)&hid_l,  g_hid_l);
  cudaGetSymbolAddress((void**)&wqkv_h, g_wqkv_h);
  cudaGetSymbolAddress((void**)&wqkv_l, g_wqkv_l);
  cudaGetSymbolAddress((void**)&wo_h,   g_wo_h);
  cudaGetSymbolAddress((void**)&wo_l,   g_wo_l);
  cudaGetSymbolAddress((void**)&ob_h,   g_ob_h);
  cudaGetSymbolAddress((void**)&ob_l,   g_ob_l);

  cudaFuncSetAttribute(gemm_mma, cudaFuncAttributeMaxDynamicSharedMemorySize,
                       GEMM_SMEM);
  cudaFuncSetAttribute(flash_mma, cudaFuncAttributeMaxDynamicSharedMemorySize,
                       FLASH_SMEM);

  // 0) pre-split GEMM1 operands
  {
    int n4 = T_TOK * HIDN / 4;
    split_f32<<<(n4 + 255) / 256, 256>>>(hidden, hid_h, hid_l, n4);
    n4 = QKV_N * HIDN / 4;
    split_f32<<<(n4 + 255) / 256, 256>>>(w_qkv, wqkv_h, wqkv_l, n4);
  }

  // 1) QKV projection (cp.async 4-stage bf16-split HMMA)
  gemm_mma<<<dim3(QKV_N/128, T_TOK/128), 512, GEMM_SMEM>>>(
      hid_h, hid_l, wqkv_h, wqkv_l, qkv, T_TOK, QKV_N, HIDN);

  // 2) RMSNorm + RoPE in place on Q/K head slices
  norm_rope<<<dim3(T_TOK, NH + NKV), 128>>>(qkv, positions, qw, kw);

  // 3) Causal GQA flash attention (bf16-split HMMA)
  flash_mma<<<dim3(T_TOK/ABM, NH), 256, FLASH_SMEM>>>(qkv, obuf);

  // 4) pre-split GEMM2 operands
  {
    int n4 = T_TOK * ON / 4;
    split_f32<<<(n4 + 255) / 256, 256>>>(obuf, ob_h, ob_l, n4);
    n4 = HIDN * ON / 4;
    split_f32<<<(n4 + 255) / 256, 256>>>(w_o, wo_h, wo_l, n4);
  }

  // 5) Output projection (cp.async 4-stage bf16-split HMMA)
  gemm_mma<<<dim3(HIDN/128, T_TOK/128), 512, GEMM_SMEM>>>(
      ob_h, ob_l, wo_h, wo_l, out, T_TOK, HIDN, ON);
}

// round 11
// speedup vs baseline: 2.7761x; 1.0364x over previous
#include <cuda_runtime.h>
#include <cuda_bf16.h>
#include <math.h>
#include <stdint.h>

#define T_TOK 2048
#define HIDN  2048
#define NH    32
#define NKV   4
#define HD    128
#define QKV_N ((NH + 2*NKV)*HD)   /* 5120 */
#define ON    (NH*HD)             /* 4096 */
#define KVW   (NKV*HD)            /* 512 */

// Scratch (static device globals: allocation-free)
__device__ float g_qkv[(size_t)T_TOK * QKV_N];   // ~40 MiB
__device__ float g_o  [(size_t)T_TOK * ON];      // ~32 MiB

// Pre-split bf16 hi/lo operand buffers (GEMMs)
__device__ __nv_bfloat16 g_hid_h [(size_t)T_TOK * HIDN];
__device__ __nv_bfloat16 g_hid_l [(size_t)T_TOK * HIDN];
__device__ __nv_bfloat16 g_wqkv_h[(size_t)QKV_N * HIDN];
__device__ __nv_bfloat16 g_wqkv_l[(size_t)QKV_N * HIDN];
__device__ __nv_bfloat16 g_wo_h  [(size_t)HIDN * ON];
__device__ __nv_bfloat16 g_wo_l  [(size_t)HIDN * ON];
__device__ __nv_bfloat16 g_ob_h  [(size_t)T_TOK * ON];
__device__ __nv_bfloat16 g_ob_l  [(size_t)T_TOK * ON];

// Pre-split flash operands
__device__ __nv_bfloat16 g_q_h [(size_t)T_TOK * ON];    // scaled Q
__device__ __nv_bfloat16 g_q_l [(size_t)T_TOK * ON];
__device__ __nv_bfloat16 g_k_h [(size_t)T_TOK * KVW];
__device__ __nv_bfloat16 g_k_l [(size_t)T_TOK * KVW];
__device__ __nv_bfloat16 g_vt_h[(size_t)NKV * HD * T_TOK];  // V^T
__device__ __nv_bfloat16 g_vt_l[(size_t)NKV * HD * T_TOK];

// ===========================================================================
// Helpers
// ===========================================================================
__device__ __forceinline__ uint32_t smem_u32(const void* p) {
  uint32_t a;
  asm("{ .reg .u64 t; cvta.to.shared.u64 t, %1; cvt.u32.u64 %0, t; }"
      : "=r"(a) : "l"(p));
  return a;
}

__device__ __forceinline__ void cvt_split(float4 v, uint2& hi, uint2& lo) {
  float f[4] = {v.x, v.y, v.z, v.w};
  uint32_t hs[4], ls[4];
  #pragma unroll
  for (int i = 0; i < 4; i++) {
    __nv_bfloat16 h = __float2bfloat16_rn(f[i]);
    float r = f[i] - __bfloat162float(h);
    __nv_bfloat16 l = __float2bfloat16_rn(r);
    hs[i] = (uint32_t)__bfloat16_as_ushort(h);
    ls[i] = (uint32_t)__bfloat16_as_ushort(l);
  }
  hi.x = hs[0] | (hs[1] << 16); hi.y = hs[2] | (hs[3] << 16);
  lo.x = ls[0] | (ls[1] << 16); lo.y = ls[2] | (ls[3] << 16);
}

__device__ __forceinline__ void split2(float a, float b,
                                       uint32_t& hi, uint32_t& lo) {
  __nv_bfloat162 h = __floats2bfloat162_rn(a, b);
  float ra = a - __bfloat162float(h.x);
  float rb = b - __bfloat162float(h.y);
  __nv_bfloat162 l = __floats2bfloat162_rn(ra, rb);
  hi = *reinterpret_cast<uint32_t*>(&h);
  lo = *reinterpret_cast<uint32_t*>(&l);
}

#define LDSM4(r, a)                                                          \
  asm volatile("ldmatrix.sync.aligned.m8n8.x4.shared.b16 {%0,%1,%2,%3}, [%4];" \
    : "=r"((r)[0]), "=r"((r)[1]), "=r"((r)[2]), "=r"((r)[3]) : "r"(a))

#define MMA_BF16(c, a, b)                                                    \
  asm volatile("mma.sync.aligned.m16n8k16.row.col.f32.bf16.bf16.f32 "        \
    "{%0,%1,%2,%3}, {%4,%5,%6,%7}, {%8,%9}, {%0,%1,%2,%3};"                  \
    : "+f"((c)[0]), "+f"((c)[1]), "+f"((c)[2]), "+f"((c)[3])                 \
    : "r"((a)[0]), "r"((a)[1]), "r"((a)[2]), "r"((a)[3]),                    \
      "r"((b)[0]), "r"((b)[1]))

#define CP_ASYNC8(dst, src)                                                  \
  asm volatile("cp.async.ca.shared.global [%0], [%1], 8;" :: "r"(dst), "l"(src))
#define CP_ASYNC16(dst, src)                                                 \
  asm volatile("cp.async.cg.shared.global [%0], [%1], 16;" :: "r"(dst), "l"(src))
#define CP_COMMIT() asm volatile("cp.async.commit_group;" ::: "memory")
#define CP_WAIT2()  asm volatile("cp.async.wait_group 2;" ::: "memory")
#define CP_WAIT1()  asm volatile("cp.async.wait_group 1;" ::: "memory")
#define CP_WAIT0()  asm volatile("cp.async.wait_group 0;" ::: "memory")

// ---------------------------------------------------------------------------
// Split pass: fp32 -> bf16 hi/lo arrays
// ---------------------------------------------------------------------------
__global__ __launch_bounds__(256) void split_f32(
    const float* __restrict__ src, __nv_bfloat16* __restrict__ hi,
    __nv_bfloat16* __restrict__ lo, int n4)
{
  const int i = blockIdx.x * 256 + threadIdx.x;
  if (i < n4) {
    float4 v = ((const float4*)src)[i];
    uint2 h, l; cvt_split(v, h, l);
    ((uint2*)hi)[i] = h;
    ((uint2*)lo)[i] = l;
  }
}

// ===========================================================================
// bf16-split HMMA GEMM (unchanged from R10 passing version)
// ===========================================================================
#define KC 32
#define KP 40
#define TILE_E (128 * KP)
#define STAGE_E (4 * TILE_E)
#define NSTAGE 4
#define GEMM_SMEM (NSTAGE * STAGE_E * 2)

__global__ __launch_bounds__(512) void gemm_mma(
    const __nv_bfloat16* __restrict__ Ah, const __nv_bfloat16* __restrict__ Al,
    const __nv_bfloat16* __restrict__ Bh, const __nv_bfloat16* __restrict__ Bl,
    float* __restrict__ C, int M, int N, int K)
{
  extern __shared__ __nv_bfloat16 sm[];
  const uint32_t sbase = smem_u32(sm);
  const int tid  = threadIdx.x;
  const int lane = tid & 31;
  const int w    = tid >> 5;
  const int wm   = w & 3;
  const int wn   = w >> 2;
  const int bm   = blockIdx.y, bn = blockIdx.x;

  const __nv_bfloat16* tb[4] = {
    Ah + (size_t)bm * 128 * K, Al + (size_t)bm * 128 * K,
    Bh + (size_t)bn * 128 * K, Bl + (size_t)bn * 128 * K };

  const int mi  = lane >> 3, li = lane & 7;
  const int a_r = ((mi & 1) << 3) + li;
  const int a_k = (mi >> 1) << 3;
  const int b_r = ((mi >> 1) << 3) + li;
  const int b_k = (mi & 1) << 3;

  float acc[2][4][4];
  #pragma unroll
  for (int mt = 0; mt < 2; ++mt)
    #pragma unroll
    for (int nt = 0; nt < 4; ++nt)
      #pragma unroll
      for (int q = 0; q < 4; ++q) acc[mt][nt][q] = 0.f;

  auto LOAD = [&](int ch) {
    const int s = ch & (NSTAGE - 1);
    const uint32_t st = sbase + (uint32_t)(s * STAGE_E * 2);
    const int kb = ch * KC;
    #pragma unroll
    for (int tile = 0; tile < 4; ++tile) {
      #pragma unroll
      for (int j = 0; j < 2; ++j) {
        const int c   = tid + j * 512;
        const int row = c >> 3;
        const int k8  = (c & 7) << 2;
        const __nv_bfloat16* src = tb[tile] + (size_t)row * K + kb + k8;
        const uint32_t dst = st + (uint32_t)((tile * TILE_E + row * KP + k8) << 1);
        CP_ASYNC8(dst, src);
      }
    }
    CP_COMMIT();
  };

  auto COMP = [&](int ch) {
    const uint32_t base = sbase + (uint32_t)((ch & (NSTAGE - 1)) * STAGE_E * 2);
    #pragma unroll
    for (int ks = 0; ks < 2; ++ks) {
      uint32_t ah[2][4], al[2][4], bh[2][4], bl[2][4];
      #pragma unroll
      for (int mt = 0; mt < 2; ++mt) {
        uint32_t ad = base + (uint32_t)(((wm * 32 + mt * 16 + a_r) * KP +
                                         ks * 16 + a_k) << 1);
        LDSM4(ah[mt], ad);
        LDSM4(al[mt], ad + TILE_E * 2);
      }
      #pragma unroll
      for (int np = 0; np < 2; ++np) {
        uint32_t bd = base + 2 * TILE_E * 2 +
                      (uint32_t)(((wn * 32 + np * 16 + b_r) * KP +
                                  ks * 16 + b_k) << 1);
        LDSM4(bh[np], bd);
        LDSM4(bl[np], bd + TILE_E * 2);
      }
      #pragma unroll
      for (int mt = 0; mt < 2; ++mt)
        #pragma unroll
        for (int nt = 0; nt < 4; ++nt) {
          uint32_t* bhp = &bh[nt >> 1][(nt & 1) * 2];
          uint32_t* blp = &bl[nt >> 1][(nt & 1) * 2];
          MMA_BF16(acc[mt][nt], ah[mt], bhp);
          MMA_BF16(acc[mt][nt], ah[mt], blp);
          MMA_BF16(acc[mt][nt], al[mt], bhp);
        }
    }
  };

  const int NC = K / KC;
  LOAD(0); LOAD(1); LOAD(2);
  for (int ch = 0; ch < NC; ++ch) {
    CP_WAIT2();
    __syncthreads();
    if (ch + 3 < NC) LOAD(ch + 3);
    COMP(ch);
  }

  #pragma unroll
  for (int mt = 0; mt < 2; ++mt) {
    const int r0 = bm * 128 + wm * 32 + mt * 16 + (lane >> 2);
    #pragma unroll
    for (int nt = 0; nt < 4; ++nt) {
      const int c0 = bn * 128 + wn * 32 + nt * 8 + ((lane & 3) << 1);
      *(float2*)&C[(size_t)r0 * N + c0] =
          make_float2(acc[mt][nt][0], acc[mt][nt][1]);
      *(float2*)&C[(size_t)(r0 + 8) * N + c0] =
          make_float2(acc[mt][nt][2], acc[mt][nt][3]);
    }
  }
}

// ---------------------------------------------------------------------------
// Per-head RMSNorm + NeoX RoPE -> writes SPLIT bf16 Q (scaled) and K directly
// ---------------------------------------------------------------------------
__global__ __launch_bounds__(128) void norm_rope(
    const float* __restrict__ qkv, const int* __restrict__ positions,
    const float* __restrict__ qw, const float* __restrict__ kw,
    __nv_bfloat16* __restrict__ Qh, __nv_bfloat16* __restrict__ Ql,
    __nv_bfloat16* __restrict__ Kh, __nv_bfloat16* __restrict__ Kl)
{
  const int t  = blockIdx.x;
  const int hh = blockIdx.y;
  const int d  = threadIdx.x;
  const float* base = qkv + (size_t)t * QKV_N +
                      (hh < NH ? hh * HD : NH * HD + (hh - NH) * HD);
  const float* w = (hh < NH) ? qw : kw;

  float x  = base[d];
  float ss = x * x;
  #pragma unroll
  for (int off = 16; off > 0; off >>= 1)
    ss += __shfl_xor_sync(0xffffffffu, ss, off);
  __shared__ float red[4];
  __shared__ float ybuf[HD];
  if ((d & 31) == 0) red[d >> 5] = ss;
  __syncthreads();
  float tot = red[0] + red[1] + red[2] + red[3];
  float y = x * rsqrtf(tot * (1.0f / HD) + 1e-6f) * w[d];
  ybuf[d] = y;
  __syncthreads();

  const float pos = (float)positions[t];
  const int   i   = d & 63;
  const float inv = exp2f(-(float)i * (19.931568569324174f / 64.0f));
  float s, c;
  sincosf(pos * inv, &s, &c);
  float out;
  if (d < 64) out = y * c - ybuf[d + 64] * s;
  else        out = ybuf[d - 64] * s + y * c;

  if (hh < NH) {
    const float v = out * 0.08838834764831845f;   // pre-scale Q
    __nv_bfloat16 h = __float2bfloat16_rn(v);
    __nv_bfloat16 l = __float2bfloat16_rn(v - __bfloat162float(h));
    const size_t o = (size_t)t * ON + hh * HD + d;
    Qh[o] = h; Ql[o] = l;
  } else {
    __nv_bfloat16 h = __float2bfloat16_rn(out);
    __nv_bfloat16 l = __float2bfloat16_rn(out - __bfloat162float(h));
    const size_t o = (size_t)t * KVW + (hh - NH) * HD + d;
    Kh[o] = h; Kl[o] = l;
  }
}

// ---------------------------------------------------------------------------
// V transpose + split: qkv V slice -> VT[kvh][hd][t] bf16 hi/lo
// grid (T/64, NKV), 256 threads
// ---------------------------------------------------------------------------
__global__ __launch_bounds__(256) void vtrans(
    const float* __restrict__ qkv,
    __nv_bfloat16* __restrict__ Vh, __nv_bfloat16* __restrict__ Vl)
{
  __shared__ float vs[HD][65];
  const int tid = threadIdx.x;
  const int t0  = blockIdx.x * 64;
  const int kvh = blockIdx.y;

  #pragma unroll
  for (int it = 0; it < 8; ++it) {
    const int idx = tid + it * 256;
    const int r = idx >> 5, c = (idx & 31) << 2;
    float4 v = *(const float4*)(qkv + (size_t)(t0 + r) * QKV_N +
                                (NH + NKV) * HD + kvh * HD + c);
    vs[c+0][r] = v.x; vs[c+1][r] = v.y; vs[c+2][r] = v.z; vs[c+3][r] = v.w;
  }
  __syncthreads();

  #pragma unroll
  for (int it = 0; it < 8; ++it) {
    const int idx = tid + it * 256;
    const int hd = idx >> 4, tg = (idx & 15) << 2;
    float v0 = vs[hd][tg], v1 = vs[hd][tg+1], v2 = vs[hd][tg+2], v3 = vs[hd][tg+3];
    uint32_t h01, l01, h23, l23;
    split2(v0, v1, h01, l01);
    split2(v2, v3, h23, l23);
    const size_t o = ((size_t)kvh * HD + hd) * T_TOK + t0 + tg;
    *(uint2*)(Vh + o) = make_uint2(h01, h23);
    *(uint2*)(Vl + o) = make_uint2(l01, l23);
  }
}

// ===========================================================================
// Flash attention v2: pre-split bf16 operands, cp.async double-buffered.
// CTA: 128 q-rows x 1 head, 8 warps x 16 q-rows. K-tile 64. Causal, GQA.
// ===========================================================================
#define ABM 128
#define ABN 64
#define QP  136
#define VTP 72
#define SQH 0
#define SQL 17408
#define SST 34816                       /* stage area start (elems) */
#define STG 35840                       /* elems per stage */
#define FK_L 8704                       /* Kl offset within stage */
#define FV_H 17408                      /* VTh offset within stage */
#define FV_L 26624                      /* VTl offset within stage */
#define FLASH_SMEM ((SST + 2 * STG) * 2)   /* 212992 B */

__global__ __launch_bounds__(256, 1) void flash_mma(
    const __nv_bfloat16* __restrict__ Qh, const __nv_bfloat16* __restrict__ Ql,
    const __nv_bfloat16* __restrict__ Kh, const __nv_bfloat16* __restrict__ Kl,
    const __nv_bfloat16* __restrict__ Vh, const __nv_bfloat16* __restrict__ Vl,
    float* __restrict__ o)
{
  extern __shared__ __nv_bfloat16 sb[];
  const uint32_t sbase = smem_u32(sb);
  const int tid  = threadIdx.x;
  const int lane = tid & 31;
  const int w    = tid >> 5;
  const int q0   = blockIdx.x * ABM;
  const int h    = blockIdx.y;
  const int kvh  = h >> 3;

  const int mi  = lane >> 3, li = lane & 7;
  const int a_r = ((mi & 1) << 3) + li;
  const int a_k = (mi >> 1) << 3;
  const int b_r = ((mi >> 1) << 3) + li;
  const int b_k = (mi & 1) << 3;

  // ---- Q tile: 2 x 2048 16B-chunks via cp.async ----
  {
    #pragma unroll
    for (int it = 0; it < 16; ++it) {
      const int c  = tid + it * 256;       // 0..4095
      const int tl = c >> 11;              // 0=hi 1=lo
      const int cc = c & 2047;
      const int row = cc >> 4, col = (cc & 15) << 3;
      const __nv_bfloat16* src = (tl ? Ql : Qh) +
          (size_t)(q0 + row) * ON + h * HD + col;
      const uint32_t dst = sbase +
          (uint32_t)(((tl ? SQL : SQH) + row * QP + col) << 1);
      CP_ASYNC16(dst, src);
    }
  }

  auto LOADKV = [&](int kt) {
    const int s  = kt & 1;
    const int k0 = kt * ABN;
    const uint32_t stb = sbase + (uint32_t)((SST + s * STG) << 1);
    #pragma unroll
    for (int it = 0; it < 16; ++it) {
      const int c    = tid + it * 256;     // 0..4095
      const int tile = c >> 10;
      const int cc   = c & 1023;
      const __nv_bfloat16* src;
      uint32_t doff;
      if (tile < 2) {                      // Kh / Kl: 64 rows x 16 chunks
        const int row = cc >> 4, col = (cc & 15) << 3;
        src  = (tile ? Kl : Kh) + (size_t)(k0 + row) * KVW + kvh * HD + col;
        doff = (tile ? FK_L : 0u) + row * QP + col;
      } else {                             // VTh / VTl: 128 rows x 8 chunks
        const int row = cc >> 3, col = (cc & 7) << 3;
        src  = (tile == 2 ? Vh : Vl) + ((size_t)kvh * HD + row) * T_TOK + k0 + col;
        doff = (tile == 2 ? FV_H : FV_L) + row * VTP + col;
      }
      CP_ASYNC16(stb + (doff << 1), src);
    }
    CP_COMMIT();
  };

  float oacc[16][4];
  #pragma unroll
  for (int nt = 0; nt < 16; ++nt)
    #pragma unroll
    for (int q = 0; q < 4; ++q) oacc[nt][q] = 0.f;
  float mA = -1e30f, mB = -1e30f, lA = 0.f, lB = 0.f;

  const int ktmax = q0 / ABN + 1;
  LOADKV(0);   // group 0 = Q + stage0
  if (ktmax >= 1) LOADKV(1);

  for (int kt = 0; kt <= ktmax; ++kt) {
    const int k0 = kt * ABN;
    if (kt < ktmax) { CP_WAIT1(); } else { CP_WAIT0(); }
    __syncthreads();

    const uint32_t stb = sbase + (uint32_t)((SST + (kt & 1) * STG) << 1);

    // ---- S = Q @ K^T ----
    float sacc[8][4];
    #pragma unroll
    for (int nt = 0; nt < 8; ++nt)
      #pragma unroll
      for (int q = 0; q < 4; ++q) sacc[nt][q] = 0.f;

    #pragma unroll
    for (int ks = 0; ks < 8; ++ks) {
      uint32_t qfh[4], qfl[4], kfh[4][4], kfl[4][4];
      const uint32_t qa = sbase + (uint32_t)(((w * 16 + a_r) * QP +
                                             ks * 16 + a_k) << 1);
      LDSM4(qfh, qa);
      LDSM4(qfl, qa + (SQL << 1));
      #pragma unroll
      for (int np = 0; np < 4; ++np) {
        const uint32_t ka = stb + (uint32_t)(((np * 16 + b_r) * QP +
                                              ks * 16 + b_k) << 1);
        LDSM4(kfh[np], ka);
        LDSM4(kfl[np], ka + (FK_L << 1));
      }
      #pragma unroll
      for (int nt = 0; nt < 8; ++nt) {
        uint32_t* bhp = &kfh[nt >> 1][(nt & 1) * 2];
        uint32_t* blp = &kfl[nt >> 1][(nt & 1) * 2];
        MMA_BF16(sacc[nt], qfh, bhp);
        MMA_BF16(sacc[nt], qfh, blp);
        MMA_BF16(sacc[nt], qfl, bhp);
      }
    }

    const int qrA = q0 + w * 16 + (lane >> 2);
    const int qrB = qrA + 8;
    if (k0 + ABN - 1 > q0) {   // causal mask
      #pragma unroll
      for (int nt = 0; nt < 8; ++nt) {
        const int kc = k0 + nt * 8 + ((lane & 3) << 1);
        if (kc     > qrA) sacc[nt][0] = -1e30f;
        if (kc + 1 > qrA) sacc[nt][1] = -1e30f;
        if (kc     > qrB) sacc[nt][2] = -1e30f;
        if (kc + 1 > qrB) sacc[nt][3] = -1e30f;
      }
    }

    // ---- online softmax ----
    float mxA = -1e30f, mxB = -1e30f;
    #pragma unroll
    for (int nt = 0; nt < 8; ++nt) {
      mxA = fmaxf(mxA, fmaxf(sacc[nt][0], sacc[nt][1]));
      mxB = fmaxf(mxB, fmaxf(sacc[nt][2], sacc[nt][3]));
    }
    mxA = fmaxf(mxA, __shfl_xor_sync(0xffffffffu, mxA, 1));
    mxA = fmaxf(mxA, __shfl_xor_sync(0xffffffffu, mxA, 2));
    mxB = fmaxf(mxB, __shfl_xor_sync(0xffffffffu, mxB, 1));
    mxB = fmaxf(mxB, __shfl_xor_sync(0xffffffffu, mxB, 2));
    const float mnA = fmaxf(mA, mxA), mnB = fmaxf(mB, mxB);
    const float cA = __expf(mA - mnA), cB = __expf(mB - mnB);
    mA = mnA; mB = mnB;

    float rsA = 0.f, rsB = 0.f;
    #pragma unroll
    for (int nt = 0; nt < 8; ++nt) {
      sacc[nt][0] = __expf(sacc[nt][0] - mnA);
      sacc[nt][1] = __expf(sacc[nt][1] - mnA);
      sacc[nt][2] = __expf(sacc[nt][2] - mnB);
      sacc[nt][3] = __expf(sacc[nt][3] - mnB);
      rsA += sacc[nt][0] + sacc[nt][1];
      rsB += sacc[nt][2] + sacc[nt][3];
    }
    rsA += __shfl_xor_sync(0xffffffffu, rsA, 1);
    rsA += __shfl_xor_sync(0xffffffffu, rsA, 2);
    rsB += __shfl_xor_sync(0xffffffffu, rsB, 1);
    rsB += __shfl_xor_sync(0xffffffffu, rsB, 2);
    lA = lA * cA + rsA;
    lB = lB * cB + rsB;
    #pragma unroll
    for (int nt = 0; nt < 16; ++nt) {
      oacc[nt][0] *= cA; oacc[nt][1] *= cA;
      oacc[nt][2] *= cB; oacc[nt][3] *= cB;
    }

    // ---- O += P @ V ----
    #pragma unroll
    for (int kk = 0; kk < 4; ++kk) {
      uint32_t ph[4], pl[4];
      split2(sacc[2*kk][0],   sacc[2*kk][1],   ph[0], pl[0]);
      split2(sacc[2*kk][2],   sacc[2*kk][3],   ph[1], pl[1]);
      split2(sacc[2*kk+1][0], sacc[2*kk+1][1], ph[2], pl[2]);
      split2(sacc[2*kk+1][2], sacc[2*kk+1][3], ph[3], pl[3]);
      #pragma unroll
      for (int np = 0; np < 8; ++np) {
        uint32_t vfh[4], vfl[4];
        const uint32_t va = stb + (uint32_t)((FV_H + (np * 16 + b_r) * VTP +
                                              kk * 16 + b_k) << 1);
        LDSM4(vfh, va);
        LDSM4(vfl, va + ((FV_L - FV_H) << 1));
        MMA_BF16(oacc[2*np],   ph, (&vfh[0]));
        MMA_BF16(oacc[2*np],   ph, (&vfl[0]));
        MMA_BF16(oacc[2*np],   pl, (&vfh[0]));
        MMA_BF16(oacc[2*np+1], ph, (&vfh[2]));
        MMA_BF16(oacc[2*np+1], ph, (&vfl[2]));
        MMA_BF16(oacc[2*np+1], pl, (&vfh[2]));
      }
    }

    __syncthreads();           // all warps done with stage kt
    if (kt + 2 <= ktmax) LOADKV(kt + 2);
  }

  // ---- epilogue ----
  const float invA = 1.0f / lA, invB = 1.0f / lB;
  const int rowA = q0 + w * 16 + (lane >> 2);
  #pragma unroll
  for (int nt = 0; nt < 16; ++nt) {
    const int c0 = h * HD + nt * 8 + ((lane & 3) << 1);
    *(float2*)&o[(size_t)rowA * ON + c0] =
        make_float2(oacc[nt][0] * invA, oacc[nt][1] * invA);
    *(float2*)&o[(size_t)(rowA + 8) * ON + c0] =
        make_float2(oacc[nt][2] * invB, oacc[nt][3] * invB);
  }
}

// ---------------------------------------------------------------------------
extern "C" void kernel_launch(void* const* d_in, const int* in_sizes, int n_in,
                              void* d_out, int out_size)
{
  (void)in_sizes; (void)n_in; (void)out_size;
  const int*   positions = (const int*)  d_in[0];
  const float* hidden    = (const float*)d_in[1];
  const float* w_qkv     = (const float*)d_in[2];
  const float* w_o       = (const float*)d_in[3];
  const float* qw        = (const float*)d_in[4];
  const float* kw        = (const float*)d_in[5];
  float* out = (float*)d_out;

  float *qkv, *obuf;
  cudaGetSymbolAddress((void**)&qkv,  g_qkv);
  cudaGetSymbolAddress((void**)&obuf, g_o);
  __nv_bfloat16 *hid_h, *hid_l, *wqkv_h, *wqkv_l, *wo_h, *wo_l, *ob_h, *ob_l;
  __nv_bfloat16 *q_h, *q_l, *k_h, *k_l, *vt_h, *vt_l;
  cudaGetSymbolAddress((void**)&hid_h,  g_hid_h);
  cudaGetSymbolAddress((void**)&hid_l,  g_hid_l);
  cudaGetSymbolAddress((void**)&wqkv_h, g_wqkv_h);
  cudaGetSymbolAddress((void**)&wqkv_l, g_wqkv_l);
  cudaGetSymbolAddress((void**)&wo_h,   g_wo_h);
  cudaGetSymbolAddress((void**)&wo_l,   g_wo_l);
  cudaGetSymbolAddress((void**)&ob_h,   g_ob_h);
  cudaGetSymbolAddress((void**)&ob_l,   g_ob_l);
  cudaGetSymbolAddress((void**)&q_h,    g_q_h);
  cudaGetSymbolAddress((void**)&q_l,    g_q_l);
  cudaGetSymbolAddress((void**)&k_h,    g_k_h);
  cudaGetSymbolAddress((void**)&k_l,    g_k_l);
  cudaGetSymbolAddress((void**)&vt_h,   g_vt_h);
  cudaGetSymbolAddress((void**)&vt_l,   g_vt_l);

  cudaFuncSetAttribute(gemm_mma, cudaFuncAttributeMaxDynamicSharedMemorySize,
                       GEMM_SMEM);
  cudaFuncSetAttribute(flash_mma, cudaFuncAttributeMaxDynamicSharedMemorySize,
                       FLASH_SMEM);

  // 0) pre-split GEMM1 operands
  {
    int n4 = T_TOK * HIDN / 4;
    split_f32<<<(n4 + 255) / 256, 256>>>(hidden, hid_h, hid_l, n4);
    n4 = QKV_N * HIDN / 4;
    split_f32<<<(n4 + 255) / 256, 256>>>(w_qkv, wqkv_h, wqkv_l, n4);
  }

  // 1) QKV projection
  gemm_mma<<<dim3(QKV_N/128, T_TOK/128), 512, GEMM_SMEM>>>(
      hid_h, hid_l, wqkv_h, wqkv_l, qkv, T_TOK, QKV_N, HIDN);

  // 2) RMSNorm + RoPE -> split bf16 Q (scaled) / K ; V transpose+split
  norm_rope<<<dim3(T_TOK, NH + NKV), 128>>>(qkv, positions, qw, kw,
                                            q_h, q_l, k_h, k_l);
  vtrans<<<dim3(T_TOK/64, NKV), 256>>>(qkv, vt_h, vt_l);

  // 3) Causal GQA flash attention (pre-split, cp.async double-buffered)
  flash_mma<<<dim3(T_TOK/ABM, NH), 256, FLASH_SMEM>>>(
      q_h, q_l, k_h, k_l, vt_h, vt_l, obuf);

  // 4) pre-split GEMM2 operands
  {
    int n4 = T_TOK * ON / 4;
    split_f32<<<(n4 + 255) / 256, 256>>>(obuf, ob_h, ob_l, n4);
    n4 = HIDN * ON / 4;
    split_f32<<<(n4 + 255) / 256, 256>>>(w_o, wo_h, wo_l, n4);
  }

  // 5) Output projection
  gemm_mma<<<dim3(HIDN/128, T_TOK/128), 512, GEMM_SMEM>>>(
      ob_h, ob_l, wo_h, wo_l, out, T_TOK, HIDN, ON);
}

// round 12
// speedup vs baseline: 4.6067x; 1.6594x over previous
#include <cuda_runtime.h>
#include <cuda_bf16.h>
#include <cuda_fp16.h>
#include <math.h>
#include <stdint.h>

#define T_TOK 2048
#define HIDN  2048
#define NH    32
#define NKV   4
#define HD    128
#define QKV_N ((NH + 2*NKV)*HD)   /* 5120 */
#define ON    (NH*HD)             /* 4096 */
#define KVW   (NKV*HD)            /* 512 */

// Scratch (static device globals: allocation-free)
__device__ float g_qkv[(size_t)T_TOK * QKV_N];   // ~40 MiB

// fp16 GEMM operands
__device__ __half g_hid_h [(size_t)T_TOK * HIDN];
__device__ __half g_wqkv_h[(size_t)QKV_N * HIDN];
__device__ __half g_wo_h  [(size_t)HIDN * ON];
__device__ __half g_ob    [(size_t)T_TOK * ON];   // flash output (fp16)

// Pre-split flash operands (bf16 3-term path)
__device__ __nv_bfloat16 g_q_h [(size_t)T_TOK * ON];    // scaled Q
__device__ __nv_bfloat16 g_q_l [(size_t)T_TOK * ON];
__device__ __nv_bfloat16 g_k_h [(size_t)T_TOK * KVW];
__device__ __nv_bfloat16 g_k_l [(size_t)T_TOK * KVW];
__device__ __nv_bfloat16 g_vt_h[(size_t)NKV * HD * T_TOK];  // V^T
__device__ __nv_bfloat16 g_vt_l[(size_t)NKV * HD * T_TOK];

// ===========================================================================
// Helpers
// ===========================================================================
__device__ __forceinline__ uint32_t smem_u32(const void* p) {
  uint32_t a;
  asm("{ .reg .u64 t; cvta.to.shared.u64 t, %1; cvt.u32.u64 %0, t; }"
      : "=r"(a) : "l"(p));
  return a;
}

__device__ __forceinline__ void split2(float a, float b,
                                       uint32_t& hi, uint32_t& lo) {
  __nv_bfloat162 h = __floats2bfloat162_rn(a, b);
  float ra = a - __bfloat162float(h.x);
  float rb = b - __bfloat162float(h.y);
  __nv_bfloat162 l = __floats2bfloat162_rn(ra, rb);
  hi = *reinterpret_cast<uint32_t*>(&h);
  lo = *reinterpret_cast<uint32_t*>(&l);
}

#define LDSM4(r, a)                                                          \
  asm volatile("ldmatrix.sync.aligned.m8n8.x4.shared.b16 {%0,%1,%2,%3}, [%4];" \
    : "=r"((r)[0]), "=r"((r)[1]), "=r"((r)[2]), "=r"((r)[3]) : "r"(a))

#define MMA_BF16(c, a, b)                                                    \
  asm volatile("mma.sync.aligned.m16n8k16.row.col.f32.bf16.bf16.f32 "        \
    "{%0,%1,%2,%3}, {%4,%5,%6,%7}, {%8,%9}, {%0,%1,%2,%3};"                  \
    : "+f"((c)[0]), "+f"((c)[1]), "+f"((c)[2]), "+f"((c)[3])                 \
    : "r"((a)[0]), "r"((a)[1]), "r"((a)[2]), "r"((a)[3]),                    \
      "r"((b)[0]), "r"((b)[1]))

#define MMA_F16(c, a, b)                                                     \
  asm volatile("mma.sync.aligned.m16n8k16.row.col.f32.f16.f16.f32 "          \
    "{%0,%1,%2,%3}, {%4,%5,%6,%7}, {%8,%9}, {%0,%1,%2,%3};"                  \
    : "+f"((c)[0]), "+f"((c)[1]), "+f"((c)[2]), "+f"((c)[3])                 \
    : "r"((a)[0]), "r"((a)[1]), "r"((a)[2]), "r"((a)[3]),                    \
      "r"((b)[0]), "r"((b)[1]))

#define CP_ASYNC8(dst, src)                                                  \
  asm volatile("cp.async.ca.shared.global [%0], [%1], 8;" :: "r"(dst), "l"(src))
#define CP_ASYNC16(dst, src)                                                 \
  asm volatile("cp.async.cg.shared.global [%0], [%1], 16;" :: "r"(dst), "l"(src))
#define CP_COMMIT() asm volatile("cp.async.commit_group;" ::: "memory")
#define CP_WAIT2()  asm volatile("cp.async.wait_group 2;" ::: "memory")
#define CP_WAIT1()  asm volatile("cp.async.wait_group 1;" ::: "memory")
#define CP_WAIT0()  asm volatile("cp.async.wait_group 0;" ::: "memory")

// ---------------------------------------------------------------------------
// Convert pass: fp32 -> fp16
// ---------------------------------------------------------------------------
__global__ __launch_bounds__(256) void cvt_f16(
    const float* __restrict__ src, __half* __restrict__ dst, int n4)
{
  const int i = blockIdx.x * 256 + threadIdx.x;
  if (i < n4) {
    float4 v = ((const float4*)src)[i];
    __half2 a = __floats2half2_rn(v.x, v.y);
    __half2 b = __floats2half2_rn(v.z, v.w);
    ((uint2*)dst)[i] = make_uint2(*reinterpret_cast<uint32_t*>(&a),
                                  *reinterpret_cast<uint32_t*>(&b));
  }
}

// ===========================================================================
// fp16 single-term HMMA GEMM (NT): C[M,N] = A[M,K] @ B[N,K]^T.
// CTA 128x128, 512 threads / 16 warps (4x4), warp tile 32x32, K chunk 32,
// 4-stage cp.async pipeline. Stage: A,B fp16 tiles, 128 x KP (KP=40).
// ===========================================================================
#define KC 32
#define KP 40
#define TILE_E (128 * KP)          /* 5120 elems */
#define STAGE_E (2 * TILE_E)       /* 10240 elems */
#define NSTAGE 4
#define GEMM_SMEM (NSTAGE * STAGE_E * 2)   /* 81920 B */

__global__ __launch_bounds__(512) void gemm_mma(
    const __half* __restrict__ A, const __half* __restrict__ B,
    float* __restrict__ C, int M, int N, int K)
{
  extern __shared__ __half sm[];
  const uint32_t sbase = smem_u32(sm);
  const int tid  = threadIdx.x;
  const int lane = tid & 31;
  const int w    = tid >> 5;
  const int wm   = w & 3;
  const int wn   = w >> 2;
  const int bm   = blockIdx.y, bn = blockIdx.x;

  const __half* tb[2] = { A + (size_t)bm * 128 * K, B + (size_t)bn * 128 * K };

  const int mi  = lane >> 3, li = lane & 7;
  const int a_r = ((mi & 1) << 3) + li;
  const int a_k = (mi >> 1) << 3;
  const int b_r = ((mi >> 1) << 3) + li;
  const int b_k = (mi & 1) << 3;

  float acc[2][4][4];
  #pragma unroll
  for (int mt = 0; mt < 2; ++mt)
    #pragma unroll
    for (int nt = 0; nt < 4; ++nt)
      #pragma unroll
      for (int q = 0; q < 4; ++q) acc[mt][nt][q] = 0.f;

  // loader: 2 tiles x 128 rows x 8 8B-chunks = 2048 ops, 4/thread
  auto LOAD = [&](int ch) {
    const int s = ch & (NSTAGE - 1);
    const uint32_t st = sbase + (uint32_t)(s * STAGE_E * 2);
    const int kb = ch * KC;
    #pragma unroll
    for (int tile = 0; tile < 2; ++tile) {
      #pragma unroll
      for (int j = 0; j < 2; ++j) {
        const int c   = tid + j * 512;
        const int row = c >> 3;
        const int k8  = (c & 7) << 2;
        const __half* src = tb[tile] + (size_t)row * K + kb + k8;
        const uint32_t dst = st + (uint32_t)((tile * TILE_E + row * KP + k8) << 1);
        CP_ASYNC8(dst, src);
      }
    }
    CP_COMMIT();
  };

  auto COMP = [&](int ch) {
    const uint32_t base = sbase + (uint32_t)((ch & (NSTAGE - 1)) * STAGE_E * 2);
    #pragma unroll
    for (int ks = 0; ks < 2; ++ks) {
      uint32_t af[2][4], bf[2][4];
      #pragma unroll
      for (int mt = 0; mt < 2; ++mt) {
        uint32_t ad = base + (uint32_t)(((wm * 32 + mt * 16 + a_r) * KP +
                                         ks * 16 + a_k) << 1);
        LDSM4(af[mt], ad);
      }
      #pragma unroll
      for (int np = 0; np < 2; ++np) {
        uint32_t bd = base + (uint32_t)((TILE_E + (wn * 32 + np * 16 + b_r) * KP +
                                         ks * 16 + b_k) << 1);
        LDSM4(bf[np], bd);
      }
      #pragma unroll
      for (int mt = 0; mt < 2; ++mt)
        #pragma unroll
        for (int nt = 0; nt < 4; ++nt)
          MMA_F16(acc[mt][nt], af[mt], (&bf[nt >> 1][(nt & 1) * 2]));
    }
  };

  const int NC = K / KC;
  LOAD(0); LOAD(1); LOAD(2);
  for (int ch = 0; ch < NC; ++ch) {
    CP_WAIT2();
    __syncthreads();
    if (ch + 3 < NC) LOAD(ch + 3);
    COMP(ch);
  }

  #pragma unroll
  for (int mt = 0; mt < 2; ++mt) {
    const int r0 = bm * 128 + wm * 32 + mt * 16 + (lane >> 2);
    #pragma unroll
    for (int nt = 0; nt < 4; ++nt) {
      const int c0 = bn * 128 + wn * 32 + nt * 8 + ((lane & 3) << 1);
      *(float2*)&C[(size_t)r0 * N + c0] =
          make_float2(acc[mt][nt][0], acc[mt][nt][1]);
      *(float2*)&C[(size_t)(r0 + 8) * N + c0] =
          make_float2(acc[mt][nt][2], acc[mt][nt][3]);
    }
  }
}

// ---------------------------------------------------------------------------
// Per-head RMSNorm + NeoX RoPE -> split bf16 Q (scaled) / K (for flash)
// ---------------------------------------------------------------------------
__global__ __launch_bounds__(128) void norm_rope(
    const float* __restrict__ qkv, const int* __restrict__ positions,
    const float* __restrict__ qw, const float* __restrict__ kw,
    __nv_bfloat16* __restrict__ Qh, __nv_bfloat16* __restrict__ Ql,
    __nv_bfloat16* __restrict__ Kh, __nv_bfloat16* __restrict__ Kl)
{
  const int t  = blockIdx.x;
  const int hh = blockIdx.y;
  const int d  = threadIdx.x;
  const float* base = qkv + (size_t)t * QKV_N +
                      (hh < NH ? hh * HD : NH * HD + (hh - NH) * HD);
  const float* w = (hh < NH) ? qw : kw;

  float x  = base[d];
  float ss = x * x;
  #pragma unroll
  for (int off = 16; off > 0; off >>= 1)
    ss += __shfl_xor_sync(0xffffffffu, ss, off);
  __shared__ float red[4];
  __shared__ float ybuf[HD];
  if ((d & 31) == 0) red[d >> 5] = ss;
  __syncthreads();
  float tot = red[0] + red[1] + red[2] + red[3];
  float y = x * rsqrtf(tot * (1.0f / HD) + 1e-6f) * w[d];
  ybuf[d] = y;
  __syncthreads();

  const float pos = (float)positions[t];
  const int   i   = d & 63;
  const float inv = exp2f(-(float)i * (19.931568569324174f / 64.0f));
  float s, c;
  sincosf(pos * inv, &s, &c);
  float out;
  if (d < 64) out = y * c - ybuf[d + 64] * s;
  else        out = ybuf[d - 64] * s + y * c;

  if (hh < NH) {
    const float v = out * 0.08838834764831845f;   // pre-scale Q
    __nv_bfloat16 h = __float2bfloat16_rn(v);
    __nv_bfloat16 l = __float2bfloat16_rn(v - __bfloat162float(h));
    const size_t o = (size_t)t * ON + hh * HD + d;
    Qh[o] = h; Ql[o] = l;
  } else {
    __nv_bfloat16 h = __float2bfloat16_rn(out);
    __nv_bfloat16 l = __float2bfloat16_rn(out - __bfloat162float(h));
    const size_t o = (size_t)t * KVW + (hh - NH) * HD + d;
    Kh[o] = h; Kl[o] = l;
  }
}

// ---------------------------------------------------------------------------
// V transpose + split: qkv V slice -> VT[kvh][hd][t] bf16 hi/lo
// ---------------------------------------------------------------------------
__global__ __launch_bounds__(256) void vtrans(
    const float* __restrict__ qkv,
    __nv_bfloat16* __restrict__ Vh, __nv_bfloat16* __restrict__ Vl)
{
  __shared__ float vs[HD][65];
  const int tid = threadIdx.x;
  const int t0  = blockIdx.x * 64;
  const int kvh = blockIdx.y;

  #pragma unroll
  for (int it = 0; it < 8; ++it) {
    const int idx = tid + it * 256;
    const int r = idx >> 5, c = (idx & 31) << 2;
    float4 v = *(const float4*)(qkv + (size_t)(t0 + r) * QKV_N +
                                (NH + NKV) * HD + kvh * HD + c);
    vs[c+0][r] = v.x; vs[c+1][r] = v.y; vs[c+2][r] = v.z; vs[c+3][r] = v.w;
  }
  __syncthreads();

  #pragma unroll
  for (int it = 0; it < 8; ++it) {
    const int idx = tid + it * 256;
    const int hd = idx >> 4, tg = (idx & 15) << 2;
    float v0 = vs[hd][tg], v1 = vs[hd][tg+1], v2 = vs[hd][tg+2], v3 = vs[hd][tg+3];
    uint32_t h01, l01, h23, l23;
    split2(v0, v1, h01, l01);
    split2(v2, v3, h23, l23);
    const size_t o = ((size_t)kvh * HD + hd) * T_TOK + t0 + tg;
    *(uint2*)(Vh + o) = make_uint2(h01, h23);
    *(uint2*)(Vl + o) = make_uint2(l01, l23);
  }
}

// ===========================================================================
// Flash attention (bf16 3-term, cp.async double-buffered) — epilogue now
// writes fp16 directly (feeds GEMM2). Otherwise identical to R11 passing.
// ===========================================================================
#define ABM 128
#define ABN 64
#define QP  136
#define VTP 72
#define SQH 0
#define SQL 17408
#define SST 34816
#define STG 35840
#define FK_L 8704
#define FV_H 17408
#define FV_L 26624
#define FLASH_SMEM ((SST + 2 * STG) * 2)

__global__ __launch_bounds__(256, 1) void flash_mma(
    const __nv_bfloat16* __restrict__ Qh, const __nv_bfloat16* __restrict__ Ql,
    const __nv_bfloat16* __restrict__ Kh, const __nv_bfloat16* __restrict__ Kl,
    const __nv_bfloat16* __restrict__ Vh, const __nv_bfloat16* __restrict__ Vl,
    __half* __restrict__ ob)
{
  extern __shared__ __nv_bfloat16 sb[];
  const uint32_t sbase = smem_u32(sb);
  const int tid  = threadIdx.x;
  const int lane = tid & 31;
  const int w    = tid >> 5;
  const int q0   = blockIdx.x * ABM;
  const int h    = blockIdx.y;
  const int kvh  = h >> 3;

  const int mi  = lane >> 3, li = lane & 7;
  const int a_r = ((mi & 1) << 3) + li;
  const int a_k = (mi >> 1) << 3;
  const int b_r = ((mi >> 1) << 3) + li;
  const int b_k = (mi & 1) << 3;

  {
    #pragma unroll
    for (int it = 0; it < 16; ++it) {
      const int c  = tid + it * 256;
      const int tl = c >> 11;
      const int cc = c & 2047;
      const int row = cc >> 4, col = (cc & 15) << 3;
      const __nv_bfloat16* src = (tl ? Ql : Qh) +
          (size_t)(q0 + row) * ON + h * HD + col;
      const uint32_t dst = sbase +
          (uint32_t)(((tl ? SQL : SQH) + row * QP + col) << 1);
      CP_ASYNC16(dst, src);
    }
  }

  auto LOADKV = [&](int kt) {
    const int s  = kt & 1;
    const int k0 = kt * ABN;
    const uint32_t stb = sbase + (uint32_t)((SST + s * STG) << 1);
    #pragma unroll
    for (int it = 0; it < 16; ++it) {
      const int c    = tid + it * 256;
      const int tile = c >> 10;
      const int cc   = c & 1023;
      const __nv_bfloat16* src;
      uint32_t doff;
      if (tile < 2) {
        const int row = cc >> 4, col = (cc & 15) << 3;
        src  = (tile ? Kl : Kh) + (size_t)(k0 + row) * KVW + kvh * HD + col;
        doff = (tile ? FK_L : 0u) + row * QP + col;
      } else {
        const int row = cc >> 3, col = (cc & 7) << 3;
        src  = (tile == 2 ? Vh : Vl) + ((size_t)kvh * HD + row) * T_TOK + k0 + col;
        doff = (tile == 2 ? FV_H : FV_L) + row * VTP + col;
      }
      CP_ASYNC16(stb + (doff << 1), src);
    }
    CP_COMMIT();
  };

  float oacc[16][4];
  #pragma unroll
  for (int nt = 0; nt < 16; ++nt)
    #pragma unroll
    for (int q = 0; q < 4; ++q) oacc[nt][q] = 0.f;
  float mA = -1e30f, mB = -1e30f, lA = 0.f, lB = 0.f;

  const int ktmax = q0 / ABN + 1;
  LOADKV(0);
  if (ktmax >= 1) LOADKV(1);

  for (int kt = 0; kt <= ktmax; ++kt) {
    const int k0 = kt * ABN;
    if (kt < ktmax) { CP_WAIT1(); } else { CP_WAIT0(); }
    __syncthreads();

    const uint32_t stb = sbase + (uint32_t)((SST + (kt & 1) * STG) << 1);

    float sacc[8][4];
    #pragma unroll
    for (int nt = 0; nt < 8; ++nt)
      #pragma unroll
      for (int q = 0; q < 4; ++q) sacc[nt][q] = 0.f;

    #pragma unroll
    for (int ks = 0; ks < 8; ++ks) {
      uint32_t qfh[4], qfl[4], kfh[4][4], kfl[4][4];
      const uint32_t qa = sbase + (uint32_t)(((w * 16 + a_r) * QP +
                                             ks * 16 + a_k) << 1);
      LDSM4(qfh, qa);
      LDSM4(qfl, qa + (SQL << 1));
      #pragma unroll
      for (int np = 0; np < 4; ++np) {
        const uint32_t ka = stb + (uint32_t)(((np * 16 + b_r) * QP +
                                              ks * 16 + b_k) << 1);
        LDSM4(kfh[np], ka);
        LDSM4(kfl[np], ka + (FK_L << 1));
      }
      #pragma unroll
      for (int nt = 0; nt < 8; ++nt) {
        uint32_t* bhp = &kfh[nt >> 1][(nt & 1) * 2];
        uint32_t* blp = &kfl[nt >> 1][(nt & 1) * 2];
        MMA_BF16(sacc[nt], qfh, bhp);
        MMA_BF16(sacc[nt], qfh, blp);
        MMA_BF16(sacc[nt], qfl, bhp);
      }
    }

    const int qrA = q0 + w * 16 + (lane >> 2);
    const int qrB = qrA + 8;
    if (k0 + ABN - 1 > q0) {
      #pragma unroll
      for (int nt = 0; nt < 8; ++nt) {
        const int kc = k0 + nt * 8 + ((lane & 3) << 1);
        if (kc     > qrA) sacc[nt][0] = -1e30f;
        if (kc + 1 > qrA) sacc[nt][1] = -1e30f;
        if (kc     > qrB) sacc[nt][2] = -1e30f;
        if (kc + 1 > qrB) sacc[nt][3] = -1e30f;
      }
    }

    float mxA = -1e30f, mxB = -1e30f;
    #pragma unroll
    for (int nt = 0; nt < 8; ++nt) {
      mxA = fmaxf(mxA, fmaxf(sacc[nt][0], sacc[nt][1]));
      mxB = fmaxf(mxB, fmaxf(sacc[nt][2], sacc[nt][3]));
    }
    mxA = fmaxf(mxA, __shfl_xor_sync(0xffffffffu, mxA, 1));
    mxA = fmaxf(mxA, __shfl_xor_sync(0xffffffffu, mxA, 2));
    mxB = fmaxf(mxB, __shfl_xor_sync(0xffffffffu, mxB, 1));
    mxB = fmaxf(mxB, __shfl_xor_sync(0xffffffffu, mxB, 2));
    const float mnA = fmaxf(mA, mxA), mnB = fmaxf(mB, mxB);
    const float cA = __expf(mA - mnA), cB = __expf(mB - mnB);
    mA = mnA; mB = mnB;

    float rsA = 0.f, rsB = 0.f;
    #pragma unroll
    for (int nt = 0; nt < 8; ++nt) {
      sacc[nt][0] = __expf(sacc[nt][0] - mnA);
      sacc[nt][1] = __expf(sacc[nt][1] - mnA);
      sacc[nt][2] = __expf(sacc[nt][2] - mnB);
      sacc[nt][3] = __expf(sacc[nt][3] - mnB);
      rsA += sacc[nt][0] + sacc[nt][1];
      rsB += sacc[nt][2] + sacc[nt][3];
    }
    rsA += __shfl_xor_sync(0xffffffffu, rsA, 1);
    rsA += __shfl_xor_sync(0xffffffffu, rsA, 2);
    rsB += __shfl_xor_sync(0xffffffffu, rsB, 1);
    rsB += __shfl_xor_sync(0xffffffffu, rsB, 2);
    lA = lA * cA + rsA;
    lB = lB * cB + rsB;
    #pragma unroll
    for (int nt = 0; nt < 16; ++nt) {
      oacc[nt][0] *= cA; oacc[nt][1] *= cA;
      oacc[nt][2] *= cB; oacc[nt][3] *= cB;
    }

    #pragma unroll
    for (int kk = 0; kk < 4; ++kk) {
      uint32_t ph[4], pl[4];
      split2(sacc[2*kk][0],   sacc[2*kk][1],   ph[0], pl[0]);
      split2(sacc[2*kk][2],   sacc[2*kk][3],   ph[1], pl[1]);
      split2(sacc[2*kk+1][0], sacc[2*kk+1][1], ph[2], pl[2]);
      split2(sacc[2*kk+1][2], sacc[2*kk+1][3], ph[3], pl[3]);
      #pragma unroll
      for (int np = 0; np < 8; ++np) {
        uint32_t vfh[4], vfl[4];
        const uint32_t va = stb + (uint32_t)((FV_H + (np * 16 + b_r) * VTP +
                                              kk * 16 + b_k) << 1);
        LDSM4(vfh, va);
        LDSM4(vfl, va + ((FV_L - FV_H) << 1));
        MMA_BF16(oacc[2*np],   ph, (&vfh[0]));
        MMA_BF16(oacc[2*np],   ph, (&vfl[0]));
        MMA_BF16(oacc[2*np],   pl, (&vfh[0]));
        MMA_BF16(oacc[2*np+1], ph, (&vfh[2]));
        MMA_BF16(oacc[2*np+1], ph, (&vfl[2]));
        MMA_BF16(oacc[2*np+1], pl, (&vfh[2]));
      }
    }

    __syncthreads();
    if (kt + 2 <= ktmax) LOADKV(kt + 2);
  }

  // ---- epilogue: write fp16 directly (GEMM2 A operand) ----
  const float invA = 1.0f / lA, invB = 1.0f / lB;
  const int rowA = q0 + w * 16 + (lane >> 2);
  #pragma unroll
  for (int nt = 0; nt < 16; ++nt) {
    const int c0 = h * HD + nt * 8 + ((lane & 3) << 1);
    __half2 pa = __floats2half2_rn(oacc[nt][0] * invA, oacc[nt][1] * invA);
    __half2 pb = __floats2half2_rn(oacc[nt][2] * invB, oacc[nt][3] * invB);
    *(__half2*)&ob[(size_t)rowA * ON + c0]       = pa;
    *(__half2*)&ob[(size_t)(rowA + 8) * ON + c0] = pb;
  }
}

// ---------------------------------------------------------------------------
extern "C" void kernel_launch(void* const* d_in, const int* in_sizes, int n_in,
                              void* d_out, int out_size)
{
  (void)in_sizes; (void)n_in; (void)out_size;
  const int*   positions = (const int*)  d_in[0];
  const float* hidden    = (const float*)d_in[1];
  const float* w_qkv     = (const float*)d_in[2];
  const float* w_o       = (const float*)d_in[3];
  const float* qw        = (const float*)d_in[4];
  const float* kw        = (const float*)d_in[5];
  float* out = (float*)d_out;

  float* qkv;
  cudaGetSymbolAddress((void**)&qkv, g_qkv);
  __half *hid_h, *wqkv_h, *wo_h, *ob;
  cudaGetSymbolAddress((void**)&hid_h,  g_hid_h);
  cudaGetSymbolAddress((void**)&wqkv_h, g_wqkv_h);
  cudaGetSymbolAddress((void**)&wo_h,   g_wo_h);
  cudaGetSymbolAddress((void**)&ob,     g_ob);
  __nv_bfloat16 *q_h, *q_l, *k_h, *k_l, *vt_h, *vt_l;
  cudaGetSymbolAddress((void**)&q_h,  g_q_h);
  cudaGetSymbolAddress((void**)&q_l,  g_q_l);
  cudaGetSymbolAddress((void**)&k_h,  g_k_h);
  cudaGetSymbolAddress((void**)&k_l,  g_k_l);
  cudaGetSymbolAddress((void**)&vt_h, g_vt_h);
  cudaGetSymbolAddress((void**)&vt_l, g_vt_l);

  cudaFuncSetAttribute(gemm_mma, cudaFuncAttributeMaxDynamicSharedMemorySize,
                       GEMM_SMEM);
  cudaFuncSetAttribute(flash_mma, cudaFuncAttributeMaxDynamicSharedMemorySize,
                       FLASH_SMEM);

  // 0) fp32 -> fp16 operand converts for GEMM1
  {
    int n4 = T_TOK * HIDN / 4;
    cvt_f16<<<(n4 + 255) / 256, 256>>>(hidden, hid_h, n4);
    n4 = QKV_N * HIDN / 4;
    cvt_f16<<<(n4 + 255) / 256, 256>>>(w_qkv, wqkv_h, n4);
  }

  // 1) QKV projection (fp16 single-term HMMA)
  gemm_mma<<<dim3(QKV_N/128, T_TOK/128), 512, GEMM_SMEM>>>(
      hid_h, wqkv_h, qkv, T_TOK, QKV_N, HIDN);

  // 2) RMSNorm + RoPE -> split bf16 Q/K ; V transpose+split
  norm_rope<<<dim3(T_TOK, NH + NKV), 128>>>(qkv, positions, qw, kw,
                                            q_h, q_l, k_h, k_l);
  vtrans<<<dim3(T_TOK/64, NKV), 256>>>(qkv, vt_h, vt_l);

  // 3) Causal GQA flash attention (bf16 3-term) -> fp16 output
  flash_mma<<<dim3(T_TOK/ABM, NH), 256, FLASH_SMEM>>>(
      q_h, q_l, k_h, k_l, vt_h, vt_l, ob);

  // 4) fp32 -> fp16 convert for w_o
  {
    int n4 = HIDN * ON / 4;
    cvt_f16<<<(n4 + 255) / 256, 256>>>(w_o, wo_h, n4);
  }

  // 5) Output projection (fp16 single-term HMMA)
  gemm_mma<<<dim3(HIDN/128, T_TOK/128), 512, GEMM_SMEM>>>(
      ob, wo_h, out, T_TOK, HIDN, ON);
}

// round 13
// speedup vs baseline: 5.3256x; 1.1560x over previous
#include <cuda_runtime.h>
#include <cuda_bf16.h>
#include <cuda_fp16.h>
#include <math.h>
#include <stdint.h>

#define T_TOK 2048
#define HIDN  2048
#define NH    32
#define NKV   4
#define HD    128
#define QKV_N ((NH + 2*NKV)*HD)   /* 5120 */
#define ON    (NH*HD)             /* 4096 */
#define KVW   (NKV*HD)            /* 512 */

// Scratch (static device globals: allocation-free)
__device__ float g_qkv[(size_t)T_TOK * QKV_N];   // ~40 MiB

// fp16 GEMM operands
__device__ __half g_hid_h [(size_t)T_TOK * HIDN];
__device__ __half g_wqkv_h[(size_t)QKV_N * HIDN];
__device__ __half g_wo_h  [(size_t)HIDN * ON];
__device__ __half g_ob    [(size_t)T_TOK * ON];   // flash output (fp16)

// Flash operands: Q/K bf16 split (3-term S), V fp16 single (1-term PV)
__device__ __nv_bfloat16 g_q_h [(size_t)T_TOK * ON];    // scaled Q
__device__ __nv_bfloat16 g_q_l [(size_t)T_TOK * ON];
__device__ __nv_bfloat16 g_k_h [(size_t)T_TOK * KVW];
__device__ __nv_bfloat16 g_k_l [(size_t)T_TOK * KVW];
__device__ __half        g_vt  [(size_t)NKV * HD * T_TOK];  // V^T fp16

// ===========================================================================
// Helpers
// ===========================================================================
__device__ __forceinline__ uint32_t smem_u32(const void* p) {
  uint32_t a;
  asm("{ .reg .u64 t; cvta.to.shared.u64 t, %1; cvt.u32.u64 %0, t; }"
      : "=r"(a) : "l"(p));
  return a;
}

__device__ __forceinline__ void split2(float a, float b,
                                       uint32_t& hi, uint32_t& lo) {
  __nv_bfloat162 h = __floats2bfloat162_rn(a, b);
  float ra = a - __bfloat162float(h.x);
  float rb = b - __bfloat162float(h.y);
  __nv_bfloat162 l = __floats2bfloat162_rn(ra, rb);
  hi = *reinterpret_cast<uint32_t*>(&h);
  lo = *reinterpret_cast<uint32_t*>(&l);
}

#define LDSM4(r, a)                                                          \
  asm volatile("ldmatrix.sync.aligned.m8n8.x4.shared.b16 {%0,%1,%2,%3}, [%4];" \
    : "=r"((r)[0]), "=r"((r)[1]), "=r"((r)[2]), "=r"((r)[3]) : "r"(a))

#define MMA_BF16(c, a, b)                                                    \
  asm volatile("mma.sync.aligned.m16n8k16.row.col.f32.bf16.bf16.f32 "        \
    "{%0,%1,%2,%3}, {%4,%5,%6,%7}, {%8,%9}, {%0,%1,%2,%3};"                  \
    : "+f"((c)[0]), "+f"((c)[1]), "+f"((c)[2]), "+f"((c)[3])                 \
    : "r"((a)[0]), "r"((a)[1]), "r"((a)[2]), "r"((a)[3]),                    \
      "r"((b)[0]), "r"((b)[1]))

#define MMA_F16(c, a, b)                                                     \
  asm volatile("mma.sync.aligned.m16n8k16.row.col.f32.f16.f16.f32 "          \
    "{%0,%1,%2,%3}, {%4,%5,%6,%7}, {%8,%9}, {%0,%1,%2,%3};"                  \
    : "+f"((c)[0]), "+f"((c)[1]), "+f"((c)[2]), "+f"((c)[3])                 \
    : "r"((a)[0]), "r"((a)[1]), "r"((a)[2]), "r"((a)[3]),                    \
      "r"((b)[0]), "r"((b)[1]))

#define CP_ASYNC8(dst, src)                                                  \
  asm volatile("cp.async.ca.shared.global [%0], [%1], 8;" :: "r"(dst), "l"(src))
#define CP_ASYNC16(dst, src)                                                 \
  asm volatile("cp.async.cg.shared.global [%0], [%1], 16;" :: "r"(dst), "l"(src))
#define CP_COMMIT() asm volatile("cp.async.commit_group;" ::: "memory")
#define CP_WAIT2()  asm volatile("cp.async.wait_group 2;" ::: "memory")
#define CP_WAIT1()  asm volatile("cp.async.wait_group 1;" ::: "memory")
#define CP_WAIT0()  asm volatile("cp.async.wait_group 0;" ::: "memory")

// ---------------------------------------------------------------------------
// Convert pass: fp32 -> fp16
// ---------------------------------------------------------------------------
__global__ __launch_bounds__(256) void cvt_f16(
    const float* __restrict__ src, __half* __restrict__ dst, int n4)
{
  const int i = blockIdx.x * 256 + threadIdx.x;
  if (i < n4) {
    float4 v = ((const float4*)src)[i];
    __half2 a = __floats2half2_rn(v.x, v.y);
    __half2 b = __floats2half2_rn(v.z, v.w);
    ((uint2*)dst)[i] = make_uint2(*reinterpret_cast<uint32_t*>(&a),
                                  *reinterpret_cast<uint32_t*>(&b));
  }
}

// ===========================================================================
// fp16 single-term HMMA GEMM (unchanged from R12 passing version)
// ===========================================================================
#define KC 32
#define KP 40
#define TILE_E (128 * KP)
#define STAGE_E (2 * TILE_E)
#define NSTAGE 4
#define GEMM_SMEM (NSTAGE * STAGE_E * 2)

__global__ __launch_bounds__(512) void gemm_mma(
    const __half* __restrict__ A, const __half* __restrict__ B,
    float* __restrict__ C, int M, int N, int K)
{
  extern __shared__ __half sm[];
  const uint32_t sbase = smem_u32(sm);
  const int tid  = threadIdx.x;
  const int lane = tid & 31;
  const int w    = tid >> 5;
  const int wm   = w & 3;
  const int wn   = w >> 2;
  const int bm   = blockIdx.y, bn = blockIdx.x;

  const __half* tb[2] = { A + (size_t)bm * 128 * K, B + (size_t)bn * 128 * K };

  const int mi  = lane >> 3, li = lane & 7;
  const int a_r = ((mi & 1) << 3) + li;
  const int a_k = (mi >> 1) << 3;
  const int b_r = ((mi >> 1) << 3) + li;
  const int b_k = (mi & 1) << 3;

  float acc[2][4][4];
  #pragma unroll
  for (int mt = 0; mt < 2; ++mt)
    #pragma unroll
    for (int nt = 0; nt < 4; ++nt)
      #pragma unroll
      for (int q = 0; q < 4; ++q) acc[mt][nt][q] = 0.f;

  auto LOAD = [&](int ch) {
    const int s = ch & (NSTAGE - 1);
    const uint32_t st = sbase + (uint32_t)(s * STAGE_E * 2);
    const int kb = ch * KC;
    #pragma unroll
    for (int tile = 0; tile < 2; ++tile) {
      #pragma unroll
      for (int j = 0; j < 2; ++j) {
        const int c   = tid + j * 512;
        const int row = c >> 3;
        const int k8  = (c & 7) << 2;
        const __half* src = tb[tile] + (size_t)row * K + kb + k8;
        const uint32_t dst = st + (uint32_t)((tile * TILE_E + row * KP + k8) << 1);
        CP_ASYNC8(dst, src);
      }
    }
    CP_COMMIT();
  };

  auto COMP = [&](int ch) {
    const uint32_t base = sbase + (uint32_t)((ch & (NSTAGE - 1)) * STAGE_E * 2);
    #pragma unroll
    for (int ks = 0; ks < 2; ++ks) {
      uint32_t af[2][4], bf[2][4];
      #pragma unroll
      for (int mt = 0; mt < 2; ++mt) {
        uint32_t ad = base + (uint32_t)(((wm * 32 + mt * 16 + a_r) * KP +
                                         ks * 16 + a_k) << 1);
        LDSM4(af[mt], ad);
      }
      #pragma unroll
      for (int np = 0; np < 2; ++np) {
        uint32_t bd = base + (uint32_t)((TILE_E + (wn * 32 + np * 16 + b_r) * KP +
                                         ks * 16 + b_k) << 1);
        LDSM4(bf[np], bd);
      }
      #pragma unroll
      for (int mt = 0; mt < 2; ++mt)
        #pragma unroll
        for (int nt = 0; nt < 4; ++nt)
          MMA_F16(acc[mt][nt], af[mt], (&bf[nt >> 1][(nt & 1) * 2]));
    }
  };

  const int NC = K / KC;
  LOAD(0); LOAD(1); LOAD(2);
  for (int ch = 0; ch < NC; ++ch) {
    CP_WAIT2();
    __syncthreads();
    if (ch + 3 < NC) LOAD(ch + 3);
    COMP(ch);
  }

  #pragma unroll
  for (int mt = 0; mt < 2; ++mt) {
    const int r0 = bm * 128 + wm * 32 + mt * 16 + (lane >> 2);
    #pragma unroll
    for (int nt = 0; nt < 4; ++nt) {
      const int c0 = bn * 128 + wn * 32 + nt * 8 + ((lane & 3) << 1);
      *(float2*)&C[(size_t)r0 * N + c0] =
          make_float2(acc[mt][nt][0], acc[mt][nt][1]);
      *(float2*)&C[(size_t)(r0 + 8) * N + c0] =
          make_float2(acc[mt][nt][2], acc[mt][nt][3]);
    }
  }
}

// ---------------------------------------------------------------------------
// Per-head RMSNorm + NeoX RoPE -> split bf16 Q (scaled) / K (for flash)
// ---------------------------------------------------------------------------
__global__ __launch_bounds__(128) void norm_rope(
    const float* __restrict__ qkv, const int* __restrict__ positions,
    const float* __restrict__ qw, const float* __restrict__ kw,
    __nv_bfloat16* __restrict__ Qh, __nv_bfloat16* __restrict__ Ql,
    __nv_bfloat16* __restrict__ Kh, __nv_bfloat16* __restrict__ Kl)
{
  const int t  = blockIdx.x;
  const int hh = blockIdx.y;
  const int d  = threadIdx.x;
  const float* base = qkv + (size_t)t * QKV_N +
                      (hh < NH ? hh * HD : NH * HD + (hh - NH) * HD);
  const float* w = (hh < NH) ? qw : kw;

  float x  = base[d];
  float ss = x * x;
  #pragma unroll
  for (int off = 16; off > 0; off >>= 1)
    ss += __shfl_xor_sync(0xffffffffu, ss, off);
  __shared__ float red[4];
  __shared__ float ybuf[HD];
  if ((d & 31) == 0) red[d >> 5] = ss;
  __syncthreads();
  float tot = red[0] + red[1] + red[2] + red[3];
  float y = x * rsqrtf(tot * (1.0f / HD) + 1e-6f) * w[d];
  ybuf[d] = y;
  __syncthreads();

  const float pos = (float)positions[t];
  const int   i   = d & 63;
  const float inv = exp2f(-(float)i * (19.931568569324174f / 64.0f));
  float s, c;
  sincosf(pos * inv, &s, &c);
  float out;
  if (d < 64) out = y * c - ybuf[d + 64] * s;
  else        out = ybuf[d - 64] * s + y * c;

  if (hh < NH) {
    const float v = out * 0.08838834764831845f;   // pre-scale Q
    __nv_bfloat16 h = __float2bfloat16_rn(v);
    __nv_bfloat16 l = __float2bfloat16_rn(v - __bfloat162float(h));
    const size_t o = (size_t)t * ON + hh * HD + d;
    Qh[o] = h; Ql[o] = l;
  } else {
    __nv_bfloat16 h = __float2bfloat16_rn(out);
    __nv_bfloat16 l = __float2bfloat16_rn(out - __bfloat162float(h));
    const size_t o = (size_t)t * KVW + (hh - NH) * HD + d;
    Kh[o] = h; Kl[o] = l;
  }
}

// ---------------------------------------------------------------------------
// V transpose: qkv V slice -> VT[kvh][hd][t] fp16 (single term)
// ---------------------------------------------------------------------------
__global__ __launch_bounds__(256) void vtrans(
    const float* __restrict__ qkv, __half* __restrict__ Vt)
{
  __shared__ float vs[HD][65];
  const int tid = threadIdx.x;
  const int t0  = blockIdx.x * 64;
  const int kvh = blockIdx.y;

  #pragma unroll
  for (int it = 0; it < 8; ++it) {
    const int idx = tid + it * 256;
    const int r = idx >> 5, c = (idx & 31) << 2;
    float4 v = *(const float4*)(qkv + (size_t)(t0 + r) * QKV_N +
                                (NH + NKV) * HD + kvh * HD + c);
    vs[c+0][r] = v.x; vs[c+1][r] = v.y; vs[c+2][r] = v.z; vs[c+3][r] = v.w;
  }
  __syncthreads();

  #pragma unroll
  for (int it = 0; it < 8; ++it) {
    const int idx = tid + it * 256;
    const int hd = idx >> 4, tg = (idx & 15) << 2;
    __half2 a = __floats2half2_rn(vs[hd][tg],   vs[hd][tg+1]);
    __half2 b = __floats2half2_rn(vs[hd][tg+2], vs[hd][tg+3]);
    const size_t o = ((size_t)kvh * HD + hd) * T_TOK + t0 + tg;
    *(uint2*)(Vt + o) = make_uint2(*reinterpret_cast<uint32_t*>(&a),
                                   *reinterpret_cast<uint32_t*>(&b));
  }
}

// ===========================================================================
// Flash attention: S = bf16 3-term, P*V = fp16 single-term.
// CTA: 128 q-rows x 1 head, 8 warps x 16 q-rows. K-tile 64. Causal, GQA.
// ===========================================================================
#define ABM 128
#define ABN 64
#define QP  136
#define VTP 72
#define SQH 0
#define SQL 17408
#define SST 34816                 /* stage area start (elems) */
#define STG 26624                 /* per stage: K h/l (2x8704) + V (9216) */
#define FK_L 8704
#define FV   17408
#define FLASH_SMEM ((SST + 2 * STG) * 2)   /* 176128 B */

__global__ __launch_bounds__(256, 1) void flash_mma(
    const __nv_bfloat16* __restrict__ Qh, const __nv_bfloat16* __restrict__ Ql,
    const __nv_bfloat16* __restrict__ Kh, const __nv_bfloat16* __restrict__ Kl,
    const __half* __restrict__ Vt, __half* __restrict__ ob)
{
  extern __shared__ __nv_bfloat16 sb[];
  const uint32_t sbase = smem_u32(sb);
  const int tid  = threadIdx.x;
  const int lane = tid & 31;
  const int w    = tid >> 5;
  const int q0   = blockIdx.x * ABM;
  const int h    = blockIdx.y;
  const int kvh  = h >> 3;

  const int mi  = lane >> 3, li = lane & 7;
  const int a_r = ((mi & 1) << 3) + li;
  const int a_k = (mi >> 1) << 3;
  const int b_r = ((mi >> 1) << 3) + li;
  const int b_k = (mi & 1) << 3;

  // ---- Q tile via cp.async ----
  {
    #pragma unroll
    for (int it = 0; it < 16; ++it) {
      const int c  = tid + it * 256;
      const int tl = c >> 11;
      const int cc = c & 2047;
      const int row = cc >> 4, col = (cc & 15) << 3;
      const __nv_bfloat16* src = (tl ? Ql : Qh) +
          (size_t)(q0 + row) * ON + h * HD + col;
      const uint32_t dst = sbase +
          (uint32_t)(((tl ? SQL : SQH) + row * QP + col) << 1);
      CP_ASYNC16(dst, src);
    }
  }

  auto LOADKV = [&](int kt) {
    const int s  = kt & 1;
    const int k0 = kt * ABN;
    const uint32_t stb = sbase + (uint32_t)((SST + s * STG) << 1);
    #pragma unroll
    for (int it = 0; it < 12; ++it) {
      const int c    = tid + it * 256;     // 0..3071
      const int tile = c >> 10;            // 0=Kh 1=Kl 2=V
      const int cc   = c & 1023;
      if (tile < 2) {                      // K: 64 rows x 16 chunks
        const int row = cc >> 4, col = (cc & 15) << 3;
        const __nv_bfloat16* src = (tile ? Kl : Kh) +
            (size_t)(k0 + row) * KVW + kvh * HD + col;
        CP_ASYNC16(stb + (uint32_t)((((tile ? FK_L : 0u)) + row * QP + col) << 1), src);
      } else {                             // V fp16: 128 rows x 8 chunks
        const int row = cc >> 3, col = (cc & 7) << 3;
        const __half* src = Vt + ((size_t)kvh * HD + row) * T_TOK + k0 + col;
        CP_ASYNC16(stb + (uint32_t)((FV + row * VTP + col) << 1), src);
      }
    }
    CP_COMMIT();
  };

  float oacc[16][4];
  #pragma unroll
  for (int nt = 0; nt < 16; ++nt)
    #pragma unroll
    for (int q = 0; q < 4; ++q) oacc[nt][q] = 0.f;
  float mA = -1e30f, mB = -1e30f, lA = 0.f, lB = 0.f;

  const int ktmax = q0 / ABN + 1;
  LOADKV(0);
  if (ktmax >= 1) LOADKV(1);

  for (int kt = 0; kt <= ktmax; ++kt) {
    const int k0 = kt * ABN;
    if (kt < ktmax) { CP_WAIT1(); } else { CP_WAIT0(); }
    __syncthreads();

    const uint32_t stb = sbase + (uint32_t)((SST + (kt & 1) * STG) << 1);

    // ---- S = Q @ K^T (bf16 3-term) ----
    float sacc[8][4];
    #pragma unroll
    for (int nt = 0; nt < 8; ++nt)
      #pragma unroll
      for (int q = 0; q < 4; ++q) sacc[nt][q] = 0.f;

    #pragma unroll
    for (int ks = 0; ks < 8; ++ks) {
      uint32_t qfh[4], qfl[4], kfh[4][4], kfl[4][4];
      const uint32_t qa = sbase + (uint32_t)(((w * 16 + a_r) * QP +
                                             ks * 16 + a_k) << 1);
      LDSM4(qfh, qa);
      LDSM4(qfl, qa + (SQL << 1));
      #pragma unroll
      for (int np = 0; np < 4; ++np) {
        const uint32_t ka = stb + (uint32_t)(((np * 16 + b_r) * QP +
                                              ks * 16 + b_k) << 1);
        LDSM4(kfh[np], ka);
        LDSM4(kfl[np], ka + (FK_L << 1));
      }
      #pragma unroll
      for (int nt = 0; nt < 8; ++nt) {
        uint32_t* bhp = &kfh[nt >> 1][(nt & 1) * 2];
        uint32_t* blp = &kfl[nt >> 1][(nt & 1) * 2];
        MMA_BF16(sacc[nt], qfh, bhp);
        MMA_BF16(sacc[nt], qfh, blp);
        MMA_BF16(sacc[nt], qfl, bhp);
      }
    }

    const int qrA = q0 + w * 16 + (lane >> 2);
    const int qrB = qrA + 8;
    if (k0 + ABN - 1 > q0) {   // causal mask
      #pragma unroll
      for (int nt = 0; nt < 8; ++nt) {
        const int kc = k0 + nt * 8 + ((lane & 3) << 1);
        if (kc     > qrA) sacc[nt][0] = -1e30f;
        if (kc + 1 > qrA) sacc[nt][1] = -1e30f;
        if (kc     > qrB) sacc[nt][2] = -1e30f;
        if (kc + 1 > qrB) sacc[nt][3] = -1e30f;
      }
    }

    // ---- online softmax ----
    float mxA = -1e30f, mxB = -1e30f;
    #pragma unroll
    for (int nt = 0; nt < 8; ++nt) {
      mxA = fmaxf(mxA, fmaxf(sacc[nt][0], sacc[nt][1]));
      mxB = fmaxf(mxB, fmaxf(sacc[nt][2], sacc[nt][3]));
    }
    mxA = fmaxf(mxA, __shfl_xor_sync(0xffffffffu, mxA, 1));
    mxA = fmaxf(mxA, __shfl_xor_sync(0xffffffffu, mxA, 2));
    mxB = fmaxf(mxB, __shfl_xor_sync(0xffffffffu, mxB, 1));
    mxB = fmaxf(mxB, __shfl_xor_sync(0xffffffffu, mxB, 2));
    const float mnA = fmaxf(mA, mxA), mnB = fmaxf(mB, mxB);
    const float cA = __expf(mA - mnA), cB = __expf(mB - mnB);
    mA = mnA; mB = mnB;

    float rsA = 0.f, rsB = 0.f;
    #pragma unroll
    for (int nt = 0; nt < 8; ++nt) {
      sacc[nt][0] = __expf(sacc[nt][0] - mnA);
      sacc[nt][1] = __expf(sacc[nt][1] - mnA);
      sacc[nt][2] = __expf(sacc[nt][2] - mnB);
      sacc[nt][3] = __expf(sacc[nt][3] - mnB);
      rsA += sacc[nt][0] + sacc[nt][1];
      rsB += sacc[nt][2] + sacc[nt][3];
    }
    rsA += __shfl_xor_sync(0xffffffffu, rsA, 1);
    rsA += __shfl_xor_sync(0xffffffffu, rsA, 2);
    rsB += __shfl_xor_sync(0xffffffffu, rsB, 1);
    rsB += __shfl_xor_sync(0xffffffffu, rsB, 2);
    lA = lA * cA + rsA;
    lB = lB * cB + rsB;
    #pragma unroll
    for (int nt = 0; nt < 16; ++nt) {
      oacc[nt][0] *= cA; oacc[nt][1] *= cA;
      oacc[nt][2] *= cB; oacc[nt][3] *= cB;
    }

    // ---- O += P @ V (fp16 single-term) ----
    #pragma unroll
    for (int kk = 0; kk < 4; ++kk) {
      uint32_t ph[4];
      __half2 p0 = __floats2half2_rn(sacc[2*kk][0],   sacc[2*kk][1]);
      __half2 p1 = __floats2half2_rn(sacc[2*kk][2],   sacc[2*kk][3]);
      __half2 p2 = __floats2half2_rn(sacc[2*kk+1][0], sacc[2*kk+1][1]);
      __half2 p3 = __floats2half2_rn(sacc[2*kk+1][2], sacc[2*kk+1][3]);
      ph[0] = *reinterpret_cast<uint32_t*>(&p0);
      ph[1] = *reinterpret_cast<uint32_t*>(&p1);
      ph[2] = *reinterpret_cast<uint32_t*>(&p2);
      ph[3] = *reinterpret_cast<uint32_t*>(&p3);
      #pragma unroll
      for (int np = 0; np < 8; ++np) {
        uint32_t vf[4];
        const uint32_t va = stb + (uint32_t)((FV + (np * 16 + b_r) * VTP +
                                              kk * 16 + b_k) << 1);
        LDSM4(vf, va);
        MMA_F16(oacc[2*np],   ph, (&vf[0]));
        MMA_F16(oacc[2*np+1], ph, (&vf[2]));
      }
    }

    __syncthreads();
    if (kt + 2 <= ktmax) LOADKV(kt + 2);
  }

  // ---- epilogue: write fp16 (GEMM2 A operand) ----
  const float invA = 1.0f / lA, invB = 1.0f / lB;
  const int rowA = q0 + w * 16 + (lane >> 2);
  #pragma unroll
  for (int nt = 0; nt < 16; ++nt) {
    const int c0 = h * HD + nt * 8 + ((lane & 3) << 1);
    __half2 pa = __floats2half2_rn(oacc[nt][0] * invA, oacc[nt][1] * invA);
    __half2 pb = __floats2half2_rn(oacc[nt][2] * invB, oacc[nt][3] * invB);
    *(__half2*)&ob[(size_t)rowA * ON + c0]       = pa;
    *(__half2*)&ob[(size_t)(rowA + 8) * ON + c0] = pb;
  }
}

// ---------------------------------------------------------------------------
extern "C" void kernel_launch(void* const* d_in, const int* in_sizes, int n_in,
                              void* d_out, int out_size)
{
  (void)in_sizes; (void)n_in; (void)out_size;
  const int*   positions = (const int*)  d_in[0];
  const float* hidden    = (const float*)d_in[1];
  const float* w_qkv     = (const float*)d_in[2];
  const float* w_o       = (const float*)d_in[3];
  const float* qw        = (const float*)d_in[4];
  const float* kw        = (const float*)d_in[5];
  float* out = (float*)d_out;

  float* qkv;
  cudaGetSymbolAddress((void**)&qkv, g_qkv);
  __half *hid_h, *wqkv_h, *wo_h, *ob, *vt;
  cudaGetSymbolAddress((void**)&hid_h,  g_hid_h);
  cudaGetSymbolAddress((void**)&wqkv_h, g_wqkv_h);
  cudaGetSymbolAddress((void**)&wo_h,   g_wo_h);
  cudaGetSymbolAddress((void**)&ob,     g_ob);
  cudaGetSymbolAddress((void**)&vt,     g_vt);
  __nv_bfloat16 *q_h, *q_l, *k_h, *k_l;
  cudaGetSymbolAddress((void**)&q_h,  g_q_h);
  cudaGetSymbolAddress((void**)&q_l,  g_q_l);
  cudaGetSymbolAddress((void**)&k_h,  g_k_h);
  cudaGetSymbolAddress((void**)&k_l,  g_k_l);

  cudaFuncSetAttribute(gemm_mma, cudaFuncAttributeMaxDynamicSharedMemorySize,
                       GEMM_SMEM);
  cudaFuncSetAttribute(flash_mma, cudaFuncAttributeMaxDynamicSharedMemorySize,
                       FLASH_SMEM);

  // 0) fp32 -> fp16 operand converts for GEMM1
  {
    int n4 = T_TOK * HIDN / 4;
    cvt_f16<<<(n4 + 255) / 256, 256>>>(hidden, hid_h, n4);
    n4 = QKV_N * HIDN / 4;
    cvt_f16<<<(n4 + 255) / 256, 256>>>(w_qkv, wqkv_h, n4);
  }

  // 1) QKV projection (fp16 single-term HMMA)
  gemm_mma<<<dim3(QKV_N/128, T_TOK/128), 512, GEMM_SMEM>>>(
      hid_h, wqkv_h, qkv, T_TOK, QKV_N, HIDN);

  // 2) RMSNorm + RoPE -> split bf16 Q/K ; V transpose (fp16)
  norm_rope<<<dim3(T_TOK, NH + NKV), 128>>>(qkv, positions, qw, kw,
                                            q_h, q_l, k_h, k_l);
  vtrans<<<dim3(T_TOK/64, NKV), 256>>>(qkv, vt);

  // 3) Causal GQA flash attention (S bf16 3-term, PV fp16 1-term)
  flash_mma<<<dim3(T_TOK/ABM, NH), 256, FLASH_SMEM>>>(
      q_h, q_l, k_h, k_l, vt, ob);

  // 4) fp32 -> fp16 convert for w_o
  {
    int n4 = HIDN * ON / 4;
    cvt_f16<<<(n4 + 255) / 256, 256>>>(w_o, wo_h, n4);
  }

  // 5) Output projection (fp16 single-term HMMA)
  gemm_mma<<<dim3(HIDN/128, T_TOK/128), 512, GEMM_SMEM>>>(
      ob, wo_h, out, T_TOK, HIDN, ON);
}

// round 14
// speedup vs baseline: 5.8574x; 1.0999x over previous
#include <cuda_runtime.h>
#include <cuda_bf16.h>
#include <cuda_fp16.h>
#include <math.h>
#include <stdint.h>

#define T_TOK 2048
#define HIDN  2048
#define NH    32
#define NKV   4
#define HD    128
#define QKV_N ((NH + 2*NKV)*HD)   /* 5120 */
#define ON    (NH*HD)             /* 4096 */
#define KVW   (NKV*HD)            /* 512 */

// Scratch (static device globals: allocation-free)
__device__ float g_qkv[(size_t)T_TOK * QKV_N];   // ~40 MiB

// fp16 GEMM operands
__device__ __half g_hid_h [(size_t)T_TOK * HIDN];
__device__ __half g_wqkv_h[(size_t)QKV_N * HIDN];
__device__ __half g_wo_h  [(size_t)HIDN * ON];
__device__ __half g_ob    [(size_t)T_TOK * ON];   // flash output (fp16)

// Flash operands: Q fp16 2-term split, K fp16 single, V fp16 single
__device__ __half g_q_h [(size_t)T_TOK * ON];    // scaled Q hi
__device__ __half g_q_l [(size_t)T_TOK * ON];    // scaled Q lo (residual)
__device__ __half g_k   [(size_t)T_TOK * KVW];
__device__ __half g_vt  [(size_t)NKV * HD * T_TOK];  // V^T fp16

// ===========================================================================
// Helpers
// ===========================================================================
__device__ __forceinline__ uint32_t smem_u32(const void* p) {
  uint32_t a;
  asm("{ .reg .u64 t; cvta.to.shared.u64 t, %1; cvt.u32.u64 %0, t; }"
      : "=r"(a) : "l"(p));
  return a;
}

#define LDSM4(r, a)                                                          \
  asm volatile("ldmatrix.sync.aligned.m8n8.x4.shared.b16 {%0,%1,%2,%3}, [%4];" \
    : "=r"((r)[0]), "=r"((r)[1]), "=r"((r)[2]), "=r"((r)[3]) : "r"(a))

#define MMA_F16(c, a, b)                                                     \
  asm volatile("mma.sync.aligned.m16n8k16.row.col.f32.f16.f16.f32 "          \
    "{%0,%1,%2,%3}, {%4,%5,%6,%7}, {%8,%9}, {%0,%1,%2,%3};"                  \
    : "+f"((c)[0]), "+f"((c)[1]), "+f"((c)[2]), "+f"((c)[3])                 \
    : "r"((a)[0]), "r"((a)[1]), "r"((a)[2]), "r"((a)[3]),                    \
      "r"((b)[0]), "r"((b)[1]))

#define CP_ASYNC8(dst, src)                                                  \
  asm volatile("cp.async.ca.shared.global [%0], [%1], 8;" :: "r"(dst), "l"(src))
#define CP_ASYNC16(dst, src)                                                 \
  asm volatile("cp.async.cg.shared.global [%0], [%1], 16;" :: "r"(dst), "l"(src))
#define CP_COMMIT() asm volatile("cp.async.commit_group;" ::: "memory")
#define CP_WAIT2()  asm volatile("cp.async.wait_group 2;" ::: "memory")
#define CP_WAIT1()  asm volatile("cp.async.wait_group 1;" ::: "memory")
#define CP_WAIT0()  asm volatile("cp.async.wait_group 0;" ::: "memory")

// ---------------------------------------------------------------------------
// Convert pass: fp32 -> fp16
// ---------------------------------------------------------------------------
__global__ __launch_bounds__(256) void cvt_f16(
    const float* __restrict__ src, __half* __restrict__ dst, int n4)
{
  const int i = blockIdx.x * 256 + threadIdx.x;
  if (i < n4) {
    float4 v = ((const float4*)src)[i];
    __half2 a = __floats2half2_rn(v.x, v.y);
    __half2 b = __floats2half2_rn(v.z, v.w);
    ((uint2*)dst)[i] = make_uint2(*reinterpret_cast<uint32_t*>(&a),
                                  *reinterpret_cast<uint32_t*>(&b));
  }
}

// ===========================================================================
// fp16 single-term HMMA GEMM (unchanged from R12/R13 passing version)
// ===========================================================================
#define KC 32
#define KP 40
#define TILE_E (128 * KP)
#define STAGE_E (2 * TILE_E)
#define NSTAGE 4
#define GEMM_SMEM (NSTAGE * STAGE_E * 2)

__global__ __launch_bounds__(512) void gemm_mma(
    const __half* __restrict__ A, const __half* __restrict__ B,
    float* __restrict__ C, int M, int N, int K)
{
  extern __shared__ __half sm[];
  const uint32_t sbase = smem_u32(sm);
  const int tid  = threadIdx.x;
  const int lane = tid & 31;
  const int w    = tid >> 5;
  const int wm   = w & 3;
  const int wn   = w >> 2;
  const int bm   = blockIdx.y, bn = blockIdx.x;

  const __half* tb[2] = { A + (size_t)bm * 128 * K, B + (size_t)bn * 128 * K };

  const int mi  = lane >> 3, li = lane & 7;
  const int a_r = ((mi & 1) << 3) + li;
  const int a_k = (mi >> 1) << 3;
  const int b_r = ((mi >> 1) << 3) + li;
  const int b_k = (mi & 1) << 3;

  float acc[2][4][4];
  #pragma unroll
  for (int mt = 0; mt < 2; ++mt)
    #pragma unroll
    for (int nt = 0; nt < 4; ++nt)
      #pragma unroll
      for (int q = 0; q < 4; ++q) acc[mt][nt][q] = 0.f;

  auto LOAD = [&](int ch) {
    const int s = ch & (NSTAGE - 1);
    const uint32_t st = sbase + (uint32_t)(s * STAGE_E * 2);
    const int kb = ch * KC;
    #pragma unroll
    for (int tile = 0; tile < 2; ++tile) {
      #pragma unroll
      for (int j = 0; j < 2; ++j) {
        const int c   = tid + j * 512;
        const int row = c >> 3;
        const int k8  = (c & 7) << 2;
        const __half* src = tb[tile] + (size_t)row * K + kb + k8;
        const uint32_t dst = st + (uint32_t)((tile * TILE_E + row * KP + k8) << 1);
        CP_ASYNC8(dst, src);
      }
    }
    CP_COMMIT();
  };

  auto COMP = [&](int ch) {
    const uint32_t base = sbase + (uint32_t)((ch & (NSTAGE - 1)) * STAGE_E * 2);
    #pragma unroll
    for (int ks = 0; ks < 2; ++ks) {
      uint32_t af[2][4], bf[2][4];
      #pragma unroll
      for (int mt = 0; mt < 2; ++mt) {
        uint32_t ad = base + (uint32_t)(((wm * 32 + mt * 16 + a_r) * KP +
                                         ks * 16 + a_k) << 1);
        LDSM4(af[mt], ad);
      }
      #pragma unroll
      for (int np = 0; np < 2; ++np) {
        uint32_t bd = base + (uint32_t)((TILE_E + (wn * 32 + np * 16 + b_r) * KP +
                                         ks * 16 + b_k) << 1);
        LDSM4(bf[np], bd);
      }
      #pragma unroll
      for (int mt = 0; mt < 2; ++mt)
        #pragma unroll
        for (int nt = 0; nt < 4; ++nt)
          MMA_F16(acc[mt][nt], af[mt], (&bf[nt >> 1][(nt & 1) * 2]));
    }
  };

  const int NC = K / KC;
  LOAD(0); LOAD(1); LOAD(2);
  for (int ch = 0; ch < NC; ++ch) {
    CP_WAIT2();
    __syncthreads();
    if (ch + 3 < NC) LOAD(ch + 3);
    COMP(ch);
  }

  #pragma unroll
  for (int mt = 0; mt < 2; ++mt) {
    const int r0 = bm * 128 + wm * 32 + mt * 16 + (lane >> 2);
    #pragma unroll
    for (int nt = 0; nt < 4; ++nt) {
      const int c0 = bn * 128 + wn * 32 + nt * 8 + ((lane & 3) << 1);
      *(float2*)&C[(size_t)r0 * N + c0] =
          make_float2(acc[mt][nt][0], acc[mt][nt][1]);
      *(float2*)&C[(size_t)(r0 + 8) * N + c0] =
          make_float2(acc[mt][nt][2], acc[mt][nt][3]);
    }
  }
}

// ---------------------------------------------------------------------------
// Per-head RMSNorm + NeoX RoPE -> Q fp16 2-term split (scaled), K fp16 single
// ---------------------------------------------------------------------------
__global__ __launch_bounds__(128) void norm_rope(
    const float* __restrict__ qkv, const int* __restrict__ positions,
    const float* __restrict__ qw, const float* __restrict__ kw,
    __half* __restrict__ Qh, __half* __restrict__ Ql,
    __half* __restrict__ Kf)
{
  const int t  = blockIdx.x;
  const int hh = blockIdx.y;
  const int d  = threadIdx.x;
  const float* base = qkv + (size_t)t * QKV_N +
                      (hh < NH ? hh * HD : NH * HD + (hh - NH) * HD);
  const float* w = (hh < NH) ? qw : kw;

  float x  = base[d];
  float ss = x * x;
  #pragma unroll
  for (int off = 16; off > 0; off >>= 1)
    ss += __shfl_xor_sync(0xffffffffu, ss, off);
  __shared__ float red[4];
  __shared__ float ybuf[HD];
  if ((d & 31) == 0) red[d >> 5] = ss;
  __syncthreads();
  float tot = red[0] + red[1] + red[2] + red[3];
  float y = x * rsqrtf(tot * (1.0f / HD) + 1e-6f) * w[d];
  ybuf[d] = y;
  __syncthreads();

  const float pos = (float)positions[t];
  const int   i   = d & 63;
  const float inv = exp2f(-(float)i * (19.931568569324174f / 64.0f));
  float s, c;
  sincosf(pos * inv, &s, &c);
  float out;
  if (d < 64) out = y * c - ybuf[d + 64] * s;
  else        out = ybuf[d - 64] * s + y * c;

  if (hh < NH) {
    const float v = out * 0.08838834764831845f;   // pre-scale Q
    __half h = __float2half_rn(v);
    __half l = __float2half_rn(v - __half2float(h));
    const size_t o = (size_t)t * ON + hh * HD + d;
    Qh[o] = h; Ql[o] = l;
  } else {
    const size_t o = (size_t)t * KVW + (hh - NH) * HD + d;
    Kf[o] = __float2half_rn(out);
  }
}

// ---------------------------------------------------------------------------
// V transpose: qkv V slice -> VT[kvh][hd][t] fp16
// ---------------------------------------------------------------------------
__global__ __launch_bounds__(256) void vtrans(
    const float* __restrict__ qkv, __half* __restrict__ Vt)
{
  __shared__ float vs[HD][65];
  const int tid = threadIdx.x;
  const int t0  = blockIdx.x * 64;
  const int kvh = blockIdx.y;

  #pragma unroll
  for (int it = 0; it < 8; ++it) {
    const int idx = tid + it * 256;
    const int r = idx >> 5, c = (idx & 31) << 2;
    float4 v = *(const float4*)(qkv + (size_t)(t0 + r) * QKV_N +
                                (NH + NKV) * HD + kvh * HD + c);
    vs[c+0][r] = v.x; vs[c+1][r] = v.y; vs[c+2][r] = v.z; vs[c+3][r] = v.w;
  }
  __syncthreads();

  #pragma unroll
  for (int it = 0; it < 8; ++it) {
    const int idx = tid + it * 256;
    const int hd = idx >> 4, tg = (idx & 15) << 2;
    __half2 a = __floats2half2_rn(vs[hd][tg],   vs[hd][tg+1]);
    __half2 b = __floats2half2_rn(vs[hd][tg+2], vs[hd][tg+3]);
    const size_t o = ((size_t)kvh * HD + hd) * T_TOK + t0 + tg;
    *(uint2*)(Vt + o) = make_uint2(*reinterpret_cast<uint32_t*>(&a),
                                   *reinterpret_cast<uint32_t*>(&b));
  }
}

// ===========================================================================
// Flash attention: S = fp16 2-term (Qh,Ql split x K single), PV = fp16 1-term
// CTA: 128 q-rows x 1 head, 8 warps x 16 q-rows. K-tile 64. Causal, GQA.
// LPT: largest q-blocks launch first.
// ===========================================================================
#define ABM 128
#define ABN 64
#define QP  136
#define VTP 72
#define SQH 0
#define SQL 17408
#define SST 34816                 /* stage area start (elems) */
#define STG 17920                 /* per stage: K (8704) + V (9216) */
#define FV  8704
#define FLASH_SMEM ((SST + 2 * STG) * 2)   /* 141312 B */

__global__ __launch_bounds__(256, 1) void flash_mma(
    const __half* __restrict__ Qh, const __half* __restrict__ Ql,
    const __half* __restrict__ Kf, const __half* __restrict__ Vt,
    __half* __restrict__ ob)
{
  extern __shared__ __half sb[];
  const uint32_t sbase = smem_u32(sb);
  const int tid  = threadIdx.x;
  const int lane = tid & 31;
  const int w    = tid >> 5;
  const int qblk = (int)gridDim.x - 1 - (int)blockIdx.x;   // LPT: big first
  const int q0   = qblk * ABM;
  const int h    = blockIdx.y;
  const int kvh  = h >> 3;

  const int mi  = lane >> 3, li = lane & 7;
  const int a_r = ((mi & 1) << 3) + li;
  const int a_k = (mi >> 1) << 3;
  const int b_r = ((mi >> 1) << 3) + li;
  const int b_k = (mi & 1) << 3;

  // ---- Q tile (hi+lo) via cp.async ----
  {
    #pragma unroll
    for (int it = 0; it < 16; ++it) {
      const int c  = tid + it * 256;
      const int tl = c >> 11;
      const int cc = c & 2047;
      const int row = cc >> 4, col = (cc & 15) << 3;
      const __half* src = (tl ? Ql : Qh) +
          (size_t)(q0 + row) * ON + h * HD + col;
      const uint32_t dst = sbase +
          (uint32_t)(((tl ? SQL : SQH) + row * QP + col) << 1);
      CP_ASYNC16(dst, src);
    }
  }

  auto LOADKV = [&](int kt) {
    const int s  = kt & 1;
    const int k0 = kt * ABN;
    const uint32_t stb = sbase + (uint32_t)((SST + s * STG) << 1);
    #pragma unroll
    for (int it = 0; it < 8; ++it) {
      const int c    = tid + it * 256;     // 0..2047
      const int tile = c >> 10;            // 0=K 1=V
      const int cc   = c & 1023;
      if (tile == 0) {                     // K: 64 rows x 16 chunks
        const int row = cc >> 4, col = (cc & 15) << 3;
        const __half* src = Kf + (size_t)(k0 + row) * KVW + kvh * HD + col;
        CP_ASYNC16(stb + (uint32_t)((row * QP + col) << 1), src);
      } else {                             // V: 128 rows x 8 chunks
        const int row = cc >> 3, col = (cc & 7) << 3;
        const __half* src = Vt + ((size_t)kvh * HD + row) * T_TOK + k0 + col;
        CP_ASYNC16(stb + (uint32_t)((FV + row * VTP + col) << 1), src);
      }
    }
    CP_COMMIT();
  };

  float oacc[16][4];
  #pragma unroll
  for (int nt = 0; nt < 16; ++nt)
    #pragma unroll
    for (int q = 0; q < 4; ++q) oacc[nt][q] = 0.f;
  float mA = -1e30f, mB = -1e30f, lA = 0.f, lB = 0.f;

  const int ktmax = q0 / ABN + 1;
  LOADKV(0);
  if (ktmax >= 1) LOADKV(1);

  for (int kt = 0; kt <= ktmax; ++kt) {
    const int k0 = kt * ABN;
    if (kt < ktmax) { CP_WAIT1(); } else { CP_WAIT0(); }
    __syncthreads();

    const uint32_t stb = sbase + (uint32_t)((SST + (kt & 1) * STG) << 1);

    // ---- S = Q @ K^T (fp16 2-term) ----
    float sacc[8][4];
    #pragma unroll
    for (int nt = 0; nt < 8; ++nt)
      #pragma unroll
      for (int q = 0; q < 4; ++q) sacc[nt][q] = 0.f;

    #pragma unroll
    for (int ks = 0; ks < 8; ++ks) {
      uint32_t qfh[4], qfl[4], kf[4][4];
      const uint32_t qa = sbase + (uint32_t)(((w * 16 + a_r) * QP +
                                             ks * 16 + a_k) << 1);
      LDSM4(qfh, qa);
      LDSM4(qfl, qa + (SQL << 1));
      #pragma unroll
      for (int np = 0; np < 4; ++np) {
        const uint32_t ka = stb + (uint32_t)(((np * 16 + b_r) * QP +
                                              ks * 16 + b_k) << 1);
        LDSM4(kf[np], ka);
      }
      #pragma unroll
      for (int nt = 0; nt < 8; ++nt) {
        uint32_t* bp = &kf[nt >> 1][(nt & 1) * 2];
        MMA_F16(sacc[nt], qfh, bp);
        MMA_F16(sacc[nt], qfl, bp);
      }
    }

    const int qrA = q0 + w * 16 + (lane >> 2);
    const int qrB = qrA + 8;
    if (k0 + ABN - 1 > q0) {   // causal mask
      #pragma unroll
      for (int nt = 0; nt < 8; ++nt) {
        const int kc = k0 + nt * 8 + ((lane & 3) << 1);
        if (kc     > qrA) sacc[nt][0] = -1e30f;
        if (kc + 1 > qrA) sacc[nt][1] = -1e30f;
        if (kc     > qrB) sacc[nt][2] = -1e30f;
        if (kc + 1 > qrB) sacc[nt][3] = -1e30f;
      }
    }

    // ---- online softmax ----
    float mxA = -1e30f, mxB = -1e30f;
    #pragma unroll
    for (int nt = 0; nt < 8; ++nt) {
      mxA = fmaxf(mxA, fmaxf(sacc[nt][0], sacc[nt][1]));
      mxB = fmaxf(mxB, fmaxf(sacc[nt][2], sacc[nt][3]));
    }
    mxA = fmaxf(mxA, __shfl_xor_sync(0xffffffffu, mxA, 1));
    mxA = fmaxf(mxA, __shfl_xor_sync(0xffffffffu, mxA, 2));
    mxB = fmaxf(mxB, __shfl_xor_sync(0xffffffffu, mxB, 1));
    mxB = fmaxf(mxB, __shfl_xor_sync(0xffffffffu, mxB, 2));
    const float mnA = fmaxf(mA, mxA), mnB = fmaxf(mB, mxB);
    const float cA = __expf(mA - mnA), cB = __expf(mB - mnB);
    mA = mnA; mB = mnB;

    float rsA = 0.f, rsB = 0.f;
    #pragma unroll
    for (int nt = 0; nt < 8; ++nt) {
      sacc[nt][0] = __expf(sacc[nt][0] - mnA);
      sacc[nt][1] = __expf(sacc[nt][1] - mnA);
      sacc[nt][2] = __expf(sacc[nt][2] - mnB);
      sacc[nt][3] = __expf(sacc[nt][3] - mnB);
      rsA += sacc[nt][0] + sacc[nt][1];
      rsB += sacc[nt][2] + sacc[nt][3];
    }
    rsA += __shfl_xor_sync(0xffffffffu, rsA, 1);
    rsA += __shfl_xor_sync(0xffffffffu, rsA, 2);
    rsB += __shfl_xor_sync(0xffffffffu, rsB, 1);
    rsB += __shfl_xor_sync(0xffffffffu, rsB, 2);
    lA = lA * cA + rsA;
    lB = lB * cB + rsB;
    #pragma unroll
    for (int nt = 0; nt < 16; ++nt) {
      oacc[nt][0] *= cA; oacc[nt][1] *= cA;
      oacc[nt][2] *= cB; oacc[nt][3] *= cB;
    }

    // ---- O += P @ V (fp16 single-term) ----
    #pragma unroll
    for (int kk = 0; kk < 4; ++kk) {
      uint32_t ph[4];
      __half2 p0 = __floats2half2_rn(sacc[2*kk][0],   sacc[2*kk][1]);
      __half2 p1 = __floats2half2_rn(sacc[2*kk][2],   sacc[2*kk][3]);
      __half2 p2 = __floats2half2_rn(sacc[2*kk+1][0], sacc[2*kk+1][1]);
      __half2 p3 = __floats2half2_rn(sacc[2*kk+1][2], sacc[2*kk+1][3]);
      ph[0] = *reinterpret_cast<uint32_t*>(&p0);
      ph[1] = *reinterpret_cast<uint32_t*>(&p1);
      ph[2] = *reinterpret_cast<uint32_t*>(&p2);
      ph[3] = *reinterpret_cast<uint32_t*>(&p3);
      #pragma unroll
      for (int np = 0; np < 8; ++np) {
        uint32_t vf[4];
        const uint32_t va = stb + (uint32_t)((FV + (np * 16 + b_r) * VTP +
                                              kk * 16 + b_k) << 1);
        LDSM4(vf, va);
        MMA_F16(oacc[2*np],   ph, (&vf[0]));
        MMA_F16(oacc[2*np+1], ph, (&vf[2]));
      }
    }

    __syncthreads();
    if (kt + 2 <= ktmax) LOADKV(kt + 2);
  }

  // ---- epilogue: write fp16 (GEMM2 A operand) ----
  const float invA = 1.0f / lA, invB = 1.0f / lB;
  const int rowA = q0 + w * 16 + (lane >> 2);
  #pragma unroll
  for (int nt = 0; nt < 16; ++nt) {
    const int c0 = h * HD + nt * 8 + ((lane & 3) << 1);
    __half2 pa = __floats2half2_rn(oacc[nt][0] * invA, oacc[nt][1] * invA);
    __half2 pb = __floats2half2_rn(oacc[nt][2] * invB, oacc[nt][3] * invB);
    *(__half2*)&ob[(size_t)rowA * ON + c0]       = pa;
    *(__half2*)&ob[(size_t)(rowA + 8) * ON + c0] = pb;
  }
}

// ---------------------------------------------------------------------------
extern "C" void kernel_launch(void* const* d_in, const int* in_sizes, int n_in,
                              void* d_out, int out_size)
{
  (void)in_sizes; (void)n_in; (void)out_size;
  const int*   positions = (const int*)  d_in[0];
  const float* hidden    = (const float*)d_in[1];
  const float* w_qkv     = (const float*)d_in[2];
  const float* w_o       = (const float*)d_in[3];
  const float* qw        = (const float*)d_in[4];
  const float* kw        = (const float*)d_in[5];
  float* out = (float*)d_out;

  float* qkv;
  cudaGetSymbolAddress((void**)&qkv, g_qkv);
  __half *hid_h, *wqkv_h, *wo_h, *ob, *vt, *q_h, *q_l, *kf;
  cudaGetSymbolAddress((void**)&hid_h,  g_hid_h);
  cudaGetSymbolAddress((void**)&wqkv_h, g_wqkv_h);
  cudaGetSymbolAddress((void**)&wo_h,   g_wo_h);
  cudaGetSymbolAddress((void**)&ob,     g_ob);
  cudaGetSymbolAddress((void**)&vt,     g_vt);
  cudaGetSymbolAddress((void**)&q_h,    g_q_h);
  cudaGetSymbolAddress((void**)&q_l,    g_q_l);
  cudaGetSymbolAddress((void**)&kf,     g_k);

  cudaFuncSetAttribute(gemm_mma, cudaFuncAttributeMaxDynamicSharedMemorySize,
                       GEMM_SMEM);
  cudaFuncSetAttribute(flash_mma, cudaFuncAttributeMaxDynamicSharedMemorySize,
                       FLASH_SMEM);

  // 0) fp32 -> fp16 operand converts for GEMM1
  {
    int n4 = T_TOK * HIDN / 4;
    cvt_f16<<<(n4 + 255) / 256, 256>>>(hidden, hid_h, n4);
    n4 = QKV_N * HIDN / 4;
    cvt_f16<<<(n4 + 255) / 256, 256>>>(w_qkv, wqkv_h, n4);
  }

  // 1) QKV projection (fp16 single-term HMMA)
  gemm_mma<<<dim3(QKV_N/128, T_TOK/128), 512, GEMM_SMEM>>>(
      hid_h, wqkv_h, qkv, T_TOK, QKV_N, HIDN);

  // 2) RMSNorm + RoPE -> Q fp16 split / K fp16 ; V transpose (fp16)
  norm_rope<<<dim3(T_TOK, NH + NKV), 128>>>(qkv, positions, qw, kw,
                                            q_h, q_l, kf);
  vtrans<<<dim3(T_TOK/64, NKV), 256>>>(qkv, vt);

  // 3) Causal GQA flash attention (S fp16 2-term, PV fp16 1-term, LPT)
  flash_mma<<<dim3(T_TOK/ABM, NH), 256, FLASH_SMEM>>>(
      q_h, q_l, kf, vt, ob);

  // 4) fp32 -> fp16 convert for w_o
  {
    int n4 = HIDN * ON / 4;
    cvt_f16<<<(n4 + 255) / 256, 256>>>(w_o, wo_h, n4);
  }

  // 5) Output projection (fp16 single-term HMMA)
  gemm_mma<<<dim3(HIDN/128, T_TOK/128), 512, GEMM_SMEM>>>(
      ob, wo_h, out, T_TOK, HIDN, ON);
}

// round 15
// speedup vs baseline: 6.1935x; 1.0574x over previous
#include <cuda_runtime.h>
#include <cuda_bf16.h>
#include <cuda_fp16.h>
#include <math.h>
#include <stdint.h>

#define T_TOK 2048
#define HIDN  2048
#define NH    32
#define NKV   4
#define HD    128
#define QKV_N ((NH + 2*NKV)*HD)   /* 5120 */
#define ON    (NH*HD)             /* 4096 */
#define KVW   (NKV*HD)            /* 512 */

// Scratch (static device globals: allocation-free)
__device__ float g_qkv[(size_t)T_TOK * QKV_N];   // ~40 MiB

// fp16 GEMM operands
__device__ __half g_hid_h [(size_t)T_TOK * HIDN];
__device__ __half g_wqkv_h[(size_t)QKV_N * HIDN];
__device__ __half g_wo_h  [(size_t)HIDN * ON];
__device__ __half g_ob    [(size_t)T_TOK * ON];   // flash output (fp16)

// Flash operands: all fp16 single
__device__ __half g_q   [(size_t)T_TOK * ON];    // scaled Q
__device__ __half g_k   [(size_t)T_TOK * KVW];
__device__ __half g_vt  [(size_t)NKV * HD * T_TOK];  // V^T fp16

// ===========================================================================
// Helpers
// ===========================================================================
__device__ __forceinline__ uint32_t smem_u32(const void* p) {
  uint32_t a;
  asm("{ .reg .u64 t; cvta.to.shared.u64 t, %1; cvt.u32.u64 %0, t; }"
      : "=r"(a) : "l"(p));
  return a;
}

#define LDSM4(r, a)                                                          \
  asm volatile("ldmatrix.sync.aligned.m8n8.x4.shared.b16 {%0,%1,%2,%3}, [%4];" \
    : "=r"((r)[0]), "=r"((r)[1]), "=r"((r)[2]), "=r"((r)[3]) : "r"(a))

#define MMA_F16(c, a, b)                                                     \
  asm volatile("mma.sync.aligned.m16n8k16.row.col.f32.f16.f16.f32 "          \
    "{%0,%1,%2,%3}, {%4,%5,%6,%7}, {%8,%9}, {%0,%1,%2,%3};"                  \
    : "+f"((c)[0]), "+f"((c)[1]), "+f"((c)[2]), "+f"((c)[3])                 \
    : "r"((a)[0]), "r"((a)[1]), "r"((a)[2]), "r"((a)[3]),                    \
      "r"((b)[0]), "r"((b)[1]))

#define CP_ASYNC8(dst, src)                                                  \
  asm volatile("cp.async.ca.shared.global [%0], [%1], 8;" :: "r"(dst), "l"(src))
#define CP_ASYNC16(dst, src)                                                 \
  asm volatile("cp.async.cg.shared.global [%0], [%1], 16;" :: "r"(dst), "l"(src))
#define CP_COMMIT() asm volatile("cp.async.commit_group;" ::: "memory")
#define CP_WAIT2()  asm volatile("cp.async.wait_group 2;" ::: "memory")
#define CP_WAIT1()  asm volatile("cp.async.wait_group 1;" ::: "memory")
#define CP_WAIT0()  asm volatile("cp.async.wait_group 0;" ::: "memory")

// ---------------------------------------------------------------------------
// Convert pass: fp32 -> fp16
// ---------------------------------------------------------------------------
__global__ __launch_bounds__(256) void cvt_f16(
    const float* __restrict__ src, __half* __restrict__ dst, int n4)
{
  const int i = blockIdx.x * 256 + threadIdx.x;
  if (i < n4) {
    float4 v = ((const float4*)src)[i];
    __half2 a = __floats2half2_rn(v.x, v.y);
    __half2 b = __floats2half2_rn(v.z, v.w);
    ((uint2*)dst)[i] = make_uint2(*reinterpret_cast<uint32_t*>(&a),
                                  *reinterpret_cast<uint32_t*>(&b));
  }
}

// ===========================================================================
// fp16 single-term HMMA GEMM (unchanged from R12-R14 passing versions)
// ===========================================================================
#define KC 32
#define KP 40
#define TILE_E (128 * KP)
#define STAGE_E (2 * TILE_E)
#define NSTAGE 4
#define GEMM_SMEM (NSTAGE * STAGE_E * 2)

__global__ __launch_bounds__(512) void gemm_mma(
    const __half* __restrict__ A, const __half* __restrict__ B,
    float* __restrict__ C, int M, int N, int K)
{
  extern __shared__ __half sm[];
  const uint32_t sbase = smem_u32(sm);
  const int tid  = threadIdx.x;
  const int lane = tid & 31;
  const int w    = tid >> 5;
  const int wm   = w & 3;
  const int wn   = w >> 2;
  const int bm   = blockIdx.y, bn = blockIdx.x;

  const __half* tb[2] = { A + (size_t)bm * 128 * K, B + (size_t)bn * 128 * K };

  const int mi  = lane >> 3, li = lane & 7;
  const int a_r = ((mi & 1) << 3) + li;
  const int a_k = (mi >> 1) << 3;
  const int b_r = ((mi >> 1) << 3) + li;
  const int b_k = (mi & 1) << 3;

  float acc[2][4][4];
  #pragma unroll
  for (int mt = 0; mt < 2; ++mt)
    #pragma unroll
    for (int nt = 0; nt < 4; ++nt)
      #pragma unroll
      for (int q = 0; q < 4; ++q) acc[mt][nt][q] = 0.f;

  auto LOAD = [&](int ch) {
    const int s = ch & (NSTAGE - 1);
    const uint32_t st = sbase + (uint32_t)(s * STAGE_E * 2);
    const int kb = ch * KC;
    #pragma unroll
    for (int tile = 0; tile < 2; ++tile) {
      #pragma unroll
      for (int j = 0; j < 2; ++j) {
        const int c   = tid + j * 512;
        const int row = c >> 3;
        const int k8  = (c & 7) << 2;
        const __half* src = tb[tile] + (size_t)row * K + kb + k8;
        const uint32_t dst = st + (uint32_t)((tile * TILE_E + row * KP + k8) << 1);
        CP_ASYNC8(dst, src);
      }
    }
    CP_COMMIT();
  };

  auto COMP = [&](int ch) {
    const uint32_t base = sbase + (uint32_t)((ch & (NSTAGE - 1)) * STAGE_E * 2);
    #pragma unroll
    for (int ks = 0; ks < 2; ++ks) {
      uint32_t af[2][4], bf[2][4];
      #pragma unroll
      for (int mt = 0; mt < 2; ++mt) {
        uint32_t ad = base + (uint32_t)(((wm * 32 + mt * 16 + a_r) * KP +
                                         ks * 16 + a_k) << 1);
        LDSM4(af[mt], ad);
      }
      #pragma unroll
      for (int np = 0; np < 2; ++np) {
        uint32_t bd = base + (uint32_t)((TILE_E + (wn * 32 + np * 16 + b_r) * KP +
                                         ks * 16 + b_k) << 1);
        LDSM4(bf[np], bd);
      }
      #pragma unroll
      for (int mt = 0; mt < 2; ++mt)
        #pragma unroll
        for (int nt = 0; nt < 4; ++nt)
          MMA_F16(acc[mt][nt], af[mt], (&bf[nt >> 1][(nt & 1) * 2]));
    }
  };

  const int NC = K / KC;
  LOAD(0); LOAD(1); LOAD(2);
  for (int ch = 0; ch < NC; ++ch) {
    CP_WAIT2();
    __syncthreads();
    if (ch + 3 < NC) LOAD(ch + 3);
    COMP(ch);
  }

  #pragma unroll
  for (int mt = 0; mt < 2; ++mt) {
    const int r0 = bm * 128 + wm * 32 + mt * 16 + (lane >> 2);
    #pragma unroll
    for (int nt = 0; nt < 4; ++nt) {
      const int c0 = bn * 128 + wn * 32 + nt * 8 + ((lane & 3) << 1);
      *(float2*)&C[(size_t)r0 * N + c0] =
          make_float2(acc[mt][nt][0], acc[mt][nt][1]);
      *(float2*)&C[(size_t)(r0 + 8) * N + c0] =
          make_float2(acc[mt][nt][2], acc[mt][nt][3]);
    }
  }
}

// ---------------------------------------------------------------------------
// Per-head RMSNorm + NeoX RoPE -> Q fp16 (scaled), K fp16
// ---------------------------------------------------------------------------
__global__ __launch_bounds__(128) void norm_rope(
    const float* __restrict__ qkv, const int* __restrict__ positions,
    const float* __restrict__ qw, const float* __restrict__ kw,
    __half* __restrict__ Qf, __half* __restrict__ Kf)
{
  const int t  = blockIdx.x;
  const int hh = blockIdx.y;
  const int d  = threadIdx.x;
  const float* base = qkv + (size_t)t * QKV_N +
                      (hh < NH ? hh * HD : NH * HD + (hh - NH) * HD);
  const float* w = (hh < NH) ? qw : kw;

  float x  = base[d];
  float ss = x * x;
  #pragma unroll
  for (int off = 16; off > 0; off >>= 1)
    ss += __shfl_xor_sync(0xffffffffu, ss, off);
  __shared__ float red[4];
  __shared__ float ybuf[HD];
  if ((d & 31) == 0) red[d >> 5] = ss;
  __syncthreads();
  float tot = red[0] + red[1] + red[2] + red[3];
  float y = x * rsqrtf(tot * (1.0f / HD) + 1e-6f) * w[d];
  ybuf[d] = y;
  __syncthreads();

  const float pos = (float)positions[t];
  const int   i   = d & 63;
  const float inv = exp2f(-(float)i * (19.931568569324174f / 64.0f));
  float s, c;
  sincosf(pos * inv, &s, &c);
  float out;
  if (d < 64) out = y * c - ybuf[d + 64] * s;
  else        out = ybuf[d - 64] * s + y * c;

  if (hh < NH) {
    const float v = out * 0.08838834764831845f;   // pre-scale Q
    Qf[(size_t)t * ON + hh * HD + d] = __float2half_rn(v);
  } else {
    Kf[(size_t)t * KVW + (hh - NH) * HD + d] = __float2half_rn(out);
  }
}

// ---------------------------------------------------------------------------
// V transpose: qkv V slice -> VT[kvh][hd][t] fp16
// ---------------------------------------------------------------------------
__global__ __launch_bounds__(256) void vtrans(
    const float* __restrict__ qkv, __half* __restrict__ Vt)
{
  __shared__ float vs[HD][65];
  const int tid = threadIdx.x;
  const int t0  = blockIdx.x * 64;
  const int kvh = blockIdx.y;

  #pragma unroll
  for (int it = 0; it < 8; ++it) {
    const int idx = tid + it * 256;
    const int r = idx >> 5, c = (idx & 31) << 2;
    float4 v = *(const float4*)(qkv + (size_t)(t0 + r) * QKV_N +
                                (NH + NKV) * HD + kvh * HD + c);
    vs[c+0][r] = v.x; vs[c+1][r] = v.y; vs[c+2][r] = v.z; vs[c+3][r] = v.w;
  }
  __syncthreads();

  #pragma unroll
  for (int it = 0; it < 8; ++it) {
    const int idx = tid + it * 256;
    const int hd = idx >> 4, tg = (idx & 15) << 2;
    __half2 a = __floats2half2_rn(vs[hd][tg],   vs[hd][tg+1]);
    __half2 b = __floats2half2_rn(vs[hd][tg+2], vs[hd][tg+3]);
    const size_t o = ((size_t)kvh * HD + hd) * T_TOK + t0 + tg;
    *(uint2*)(Vt + o) = make_uint2(*reinterpret_cast<uint32_t*>(&a),
                                   *reinterpret_cast<uint32_t*>(&b));
  }
}

// ===========================================================================
// Flash attention: S = fp16 1-term, PV = fp16 1-term.
// CTA: 128 q-rows x 1 head, 8 warps x 16 q-rows. K-tile 64. Causal, GQA.
// LPT: largest q-blocks launch first.
// ===========================================================================
#define ABM 128
#define ABN 64
#define QP  136
#define VTP 72
#define SQH 0
#define SST 17408                 /* stage area start (elems) */
#define STG 17920                 /* per stage: K (8704) + V (9216) */
#define FV  8704
#define FLASH_SMEM ((SST + 2 * STG) * 2)   /* 106496 B */

__global__ __launch_bounds__(256, 1) void flash_mma(
    const __half* __restrict__ Qf, const __half* __restrict__ Kf,
    const __half* __restrict__ Vt, __half* __restrict__ ob)
{
  extern __shared__ __half sb[];
  const uint32_t sbase = smem_u32(sb);
  const int tid  = threadIdx.x;
  const int lane = tid & 31;
  const int w    = tid >> 5;
  const int qblk = (int)gridDim.x - 1 - (int)blockIdx.x;   // LPT: big first
  const int q0   = qblk * ABM;
  const int h    = blockIdx.y;
  const int kvh  = h >> 3;

  const int mi  = lane >> 3, li = lane & 7;
  const int a_r = ((mi & 1) << 3) + li;
  const int a_k = (mi >> 1) << 3;
  const int b_r = ((mi >> 1) << 3) + li;
  const int b_k = (mi & 1) << 3;

  // ---- Q tile via cp.async: 128 rows x 16 chunks ----
  {
    #pragma unroll
    for (int it = 0; it < 8; ++it) {
      const int c   = tid + it * 256;     // 0..2047
      const int row = c >> 4, col = (c & 15) << 3;
      const __half* src = Qf + (size_t)(q0 + row) * ON + h * HD + col;
      const uint32_t dst = sbase + (uint32_t)((row * QP + col) << 1);
      CP_ASYNC16(dst, src);
    }
  }

  auto LOADKV = [&](int kt) {
    const int s  = kt & 1;
    const int k0 = kt * ABN;
    const uint32_t stb = sbase + (uint32_t)((SST + s * STG) << 1);
    #pragma unroll
    for (int it = 0; it < 8; ++it) {
      const int c    = tid + it * 256;     // 0..2047
      const int tile = c >> 10;            // 0=K 1=V
      const int cc   = c & 1023;
      if (tile == 0) {                     // K: 64 rows x 16 chunks
        const int row = cc >> 4, col = (cc & 15) << 3;
        const __half* src = Kf + (size_t)(k0 + row) * KVW + kvh * HD + col;
        CP_ASYNC16(stb + (uint32_t)((row * QP + col) << 1), src);
      } else {                             // V: 128 rows x 8 chunks
        const int row = cc >> 3, col = (cc & 7) << 3;
        const __half* src = Vt + ((size_t)kvh * HD + row) * T_TOK + k0 + col;
        CP_ASYNC16(stb + (uint32_t)((FV + row * VTP + col) << 1), src);
      }
    }
    CP_COMMIT();
  };

  float oacc[16][4];
  #pragma unroll
  for (int nt = 0; nt < 16; ++nt)
    #pragma unroll
    for (int q = 0; q < 4; ++q) oacc[nt][q] = 0.f;
  float mA = -1e30f, mB = -1e30f, lA = 0.f, lB = 0.f;

  const int ktmax = q0 / ABN + 1;
  LOADKV(0);
  if (ktmax >= 1) LOADKV(1);

  for (int kt = 0; kt <= ktmax; ++kt) {
    const int k0 = kt * ABN;
    if (kt < ktmax) { CP_WAIT1(); } else { CP_WAIT0(); }
    __syncthreads();

    const uint32_t stb = sbase + (uint32_t)((SST + (kt & 1) * STG) << 1);

    // ---- S = Q @ K^T (fp16 1-term) ----
    float sacc[8][4];
    #pragma unroll
    for (int nt = 0; nt < 8; ++nt)
      #pragma unroll
      for (int q = 0; q < 4; ++q) sacc[nt][q] = 0.f;

    #pragma unroll
    for (int ks = 0; ks < 8; ++ks) {
      uint32_t qf[4], kf[4][4];
      const uint32_t qa = sbase + (uint32_t)(((w * 16 + a_r) * QP +
                                             ks * 16 + a_k) << 1);
      LDSM4(qf, qa);
      #pragma unroll
      for (int np = 0; np < 4; ++np) {
        const uint32_t ka = stb + (uint32_t)(((np * 16 + b_r) * QP +
                                              ks * 16 + b_k) << 1);
        LDSM4(kf[np], ka);
      }
      #pragma unroll
      for (int nt = 0; nt < 8; ++nt)
        MMA_F16(sacc[nt], qf, (&kf[nt >> 1][(nt & 1) * 2]));
    }

    const int qrA = q0 + w * 16 + (lane >> 2);
    const int qrB = qrA + 8;
    if (k0 + ABN - 1 > q0) {   // causal mask
      #pragma unroll
      for (int nt = 0; nt < 8; ++nt) {
        const int kc = k0 + nt * 8 + ((lane & 3) << 1);
        if (kc     > qrA) sacc[nt][0] = -1e30f;
        if (kc + 1 > qrA) sacc[nt][1] = -1e30f;
        if (kc     > qrB) sacc[nt][2] = -1e30f;
        if (kc + 1 > qrB) sacc[nt][3] = -1e30f;
      }
    }

    // ---- online softmax ----
    float mxA = -1e30f, mxB = -1e30f;
    #pragma unroll
    for (int nt = 0; nt < 8; ++nt) {
      mxA = fmaxf(mxA, fmaxf(sacc[nt][0], sacc[nt][1]));
      mxB = fmaxf(mxB, fmaxf(sacc[nt][2], sacc[nt][3]));
    }
    mxA = fmaxf(mxA, __shfl_xor_sync(0xffffffffu, mxA, 1));
    mxA = fmaxf(mxA, __shfl_xor_sync(0xffffffffu, mxA, 2));
    mxB = fmaxf(mxB, __shfl_xor_sync(0xffffffffu, mxB, 1));
    mxB = fmaxf(mxB, __shfl_xor_sync(0xffffffffu, mxB, 2));
    const float mnA = fmaxf(mA, mxA), mnB = fmaxf(mB, mxB);
    const float cA = __expf(mA - mnA), cB = __expf(mB - mnB);
    mA = mnA; mB = mnB;

    float rsA = 0.f, rsB = 0.f;
    #pragma unroll
    for (int nt = 0; nt < 8; ++nt) {
      sacc[nt][0] = __expf(sacc[nt][0] - mnA);
      sacc[nt][1] = __expf(sacc[nt][1] - mnA);
      sacc[nt][2] = __expf(sacc[nt][2] - mnB);
      sacc[nt][3] = __expf(sacc[nt][3] - mnB);
      rsA += sacc[nt][0] + sacc[nt][1];
      rsB += sacc[nt][2] + sacc[nt][3];
    }
    rsA += __shfl_xor_sync(0xffffffffu, rsA, 1);
    rsA += __shfl_xor_sync(0xffffffffu, rsA, 2);
    rsB += __shfl_xor_sync(0xffffffffu, rsB, 1);
    rsB += __shfl_xor_sync(0xffffffffu, rsB, 2);
    lA = lA * cA + rsA;
    lB = lB * cB + rsB;
    #pragma unroll
    for (int nt = 0; nt < 16; ++nt) {
      oacc[nt][0] *= cA; oacc[nt][1] *= cA;
      oacc[nt][2] *= cB; oacc[nt][3] *= cB;
    }

    // ---- O += P @ V (fp16 1-term) ----
    #pragma unroll
    for (int kk = 0; kk < 4; ++kk) {
      uint32_t ph[4];
      __half2 p0 = __floats2half2_rn(sacc[2*kk][0],   sacc[2*kk][1]);
      __half2 p1 = __floats2half2_rn(sacc[2*kk][2],   sacc[2*kk][3]);
      __half2 p2 = __floats2half2_rn(sacc[2*kk+1][0], sacc[2*kk+1][1]);
      __half2 p3 = __floats2half2_rn(sacc[2*kk+1][2], sacc[2*kk+1][3]);
      ph[0] = *reinterpret_cast<uint32_t*>(&p0);
      ph[1] = *reinterpret_cast<uint32_t*>(&p1);
      ph[2] = *reinterpret_cast<uint32_t*>(&p2);
      ph[3] = *reinterpret_cast<uint32_t*>(&p3);
      #pragma unroll
      for (int np = 0; np < 8; ++np) {
        uint32_t vf[4];
        const uint32_t va = stb + (uint32_t)((FV + (np * 16 + b_r) * VTP +
                                              kk * 16 + b_k) << 1);
        LDSM4(vf, va);
        MMA_F16(oacc[2*np],   ph, (&vf[0]));
        MMA_F16(oacc[2*np+1], ph, (&vf[2]));
      }
    }

    __syncthreads();
    if (kt + 2 <= ktmax) LOADKV(kt + 2);
  }

  // ---- epilogue: write fp16 (GEMM2 A operand) ----
  const float invA = 1.0f / lA, invB = 1.0f / lB;
  const int rowA = q0 + w * 16 + (lane >> 2);
  #pragma unroll
  for (int nt = 0; nt < 16; ++nt) {
    const int c0 = h * HD + nt * 8 + ((lane & 3) << 1);
    __half2 pa = __floats2half2_rn(oacc[nt][0] * invA, oacc[nt][1] * invA);
    __half2 pb = __floats2half2_rn(oacc[nt][2] * invB, oacc[nt][3] * invB);
    *(__half2*)&ob[(size_t)rowA * ON + c0]       = pa;
    *(__half2*)&ob[(size_t)(rowA + 8) * ON + c0] = pb;
  }
}

// ---------------------------------------------------------------------------
extern "C" void kernel_launch(void* const* d_in, const int* in_sizes, int n_in,
                              void* d_out, int out_size)
{
  (void)in_sizes; (void)n_in; (void)out_size;
  const int*   positions = (const int*)  d_in[0];
  const float* hidden    = (const float*)d_in[1];
  const float* w_qkv     = (const float*)d_in[2];
  const float* w_o       = (const float*)d_in[3];
  const float* qw        = (const float*)d_in[4];
  const float* kw        = (const float*)d_in[5];
  float* out = (float*)d_out;

  float* qkv;
  cudaGetSymbolAddress((void**)&qkv, g_qkv);
  __half *hid_h, *wqkv_h, *wo_h, *ob, *vt, *qf, *kf;
  cudaGetSymbolAddress((void**)&hid_h,  g_hid_h);
  cudaGetSymbolAddress((void**)&wqkv_h, g_wqkv_h);
  cudaGetSymbolAddress((void**)&wo_h,   g_wo_h);
  cudaGetSymbolAddress((void**)&ob,     g_ob);
  cudaGetSymbolAddress((void**)&vt,     g_vt);
  cudaGetSymbolAddress((void**)&qf,     g_q);
  cudaGetSymbolAddress((void**)&kf,     g_k);

  cudaFuncSetAttribute(gemm_mma, cudaFuncAttributeMaxDynamicSharedMemorySize,
                       GEMM_SMEM);
  cudaFuncSetAttribute(flash_mma, cudaFuncAttributeMaxDynamicSharedMemorySize,
                       FLASH_SMEM);

  // 0) fp32 -> fp16 operand converts for GEMM1
  {
    int n4 = T_TOK * HIDN / 4;
    cvt_f16<<<(n4 + 255) / 256, 256>>>(hidden, hid_h, n4);
    n4 = QKV_N * HIDN / 4;
    cvt_f16<<<(n4 + 255) / 256, 256>>>(w_qkv, wqkv_h, n4);
  }

  // 1) QKV projection (fp16 single-term HMMA)
  gemm_mma<<<dim3(QKV_N/128, T_TOK/128), 512, GEMM_SMEM>>>(
      hid_h, wqkv_h, qkv, T_TOK, QKV_N, HIDN);

  // 2) RMSNorm + RoPE -> Q/K fp16 ; V transpose (fp16)
  norm_rope<<<dim3(T_TOK, NH + NKV), 128>>>(qkv, positions, qw, kw, qf, kf);
  vtrans<<<dim3(T_TOK/64, NKV), 256>>>(qkv, vt);

  // 3) Causal GQA flash attention (fp16 1-term S and PV, LPT)
  flash_mma<<<dim3(T_TOK/ABM, NH), 256, FLASH_SMEM>>>(qf, kf, vt, ob);

  // 4) fp32 -> fp16 convert for w_o
  {
    int n4 = HIDN * ON / 4;
    cvt_f16<<<(n4 + 255) / 256, 256>>>(w_o, wo_h, n4);
  }

  // 5) Output projection (fp16 single-term HMMA)
  gemm_mma<<<dim3(HIDN/128, T_TOK/128), 512, GEMM_SMEM>>>(
      ob, wo_h, out, T_TOK, HIDN, ON);
}